// round 9
// baseline (speedup 1.0000x reference)
#include <cuda_runtime.h>
#include <cuda_bf16.h>
#include <math.h>
#include <stdint.h>

#define BB 8
#define TT 769
#define CC 1024
#define HH 16
#define HD 64
#define LL 32
#define COND 256
#define MROWS (BB*TT)   // 6152

// ---------------------------------------------------------------------------
// Device scratch (allocation-free requirement -> globals)
// ---------------------------------------------------------------------------
__device__ __nv_bfloat16 g_xqh[(size_t)MROWS * CC], g_xql[(size_t)MROWS * CC];
__device__ __nv_bfloat16 g_xkh[(size_t)MROWS * CC], g_xkl[(size_t)MROWS * CC];
__device__ __nv_bfloat16 g_Wh[(size_t)4 * CC * CC], g_Wl[(size_t)4 * CC * CC];
__device__ __nv_bfloat16 g_qh[(size_t)MROWS * CC], g_ql[(size_t)MROWS * CC];
__device__ __nv_bfloat16 g_kh[(size_t)MROWS * CC], g_kl[(size_t)MROWS * CC];
__device__ __nv_bfloat16 g_vh[(size_t)MROWS * CC], g_vl[(size_t)MROWS * CC];
__device__ __nv_bfloat16 g_ah[(size_t)MROWS * CC], g_al[(size_t)MROWS * CC];

// ---------------------------------------------------------------------------
// Helpers
// ---------------------------------------------------------------------------
__device__ __forceinline__ uint32_t smem_to_u32(const void* p) {
    uint32_t a;
    asm("{ .reg .u64 t; cvta.to.shared.u64 t, %1; cvt.u32.u64 %0, t; }"
        : "=r"(a) : "l"(p));
    return a;
}
__device__ __forceinline__ void ldm_x4(uint32_t* r, uint32_t addr) {
    asm volatile("ldmatrix.sync.aligned.m8n8.x4.shared.b16 {%0,%1,%2,%3}, [%4];"
        : "=r"(r[0]), "=r"(r[1]), "=r"(r[2]), "=r"(r[3]) : "r"(addr));
}
__device__ __forceinline__ void ldm_x4_t(uint32_t* r, uint32_t addr) {
    asm volatile("ldmatrix.sync.aligned.m8n8.x4.trans.shared.b16 {%0,%1,%2,%3}, [%4];"
        : "=r"(r[0]), "=r"(r[1]), "=r"(r[2]), "=r"(r[3]) : "r"(addr));
}
// NOTE: non-volatile on purpose — pure register dataflow, lets the compiler
// schedule/interleave MMAs freely.
__device__ __forceinline__ void mma16816(float* d, const uint32_t* a,
                                         uint32_t b0, uint32_t b1) {
    asm("mma.sync.aligned.m16n8k16.row.col.f32.bf16.bf16.f32 "
        "{%0,%1,%2,%3}, {%4,%5,%6,%7}, {%8,%9}, {%0,%1,%2,%3};"
        : "+f"(d[0]), "+f"(d[1]), "+f"(d[2]), "+f"(d[3])
        : "r"(a[0]), "r"(a[1]), "r"(a[2]), "r"(a[3]), "r"(b0), "r"(b1));
}
__device__ __forceinline__ void cp16(uint32_t dst, const void* src, bool pred) {
    int n = pred ? 16 : 0;
    asm volatile("cp.async.cg.shared.global [%0], [%1], 16, %2;"
        :: "r"(dst), "l"(src), "r"(n) : "memory");
}
#define CP_COMMIT() asm volatile("cp.async.commit_group;" ::: "memory")
#define CP_WAIT0()  asm volatile("cp.async.wait_group 0;" ::: "memory")

// pack 2 floats -> bf16x2 hi + bf16x2 residual-lo
__device__ __forceinline__ void pack_split(float x, float y,
                                           uint32_t& hi, uint32_t& lo) {
    __nv_bfloat162 h = __floats2bfloat162_rn(x, y);
    float hx = __low2float(h), hy = __high2float(h);
    __nv_bfloat162 l2 = __floats2bfloat162_rn(x - hx, y - hy);
    hi = *reinterpret_cast<uint32_t*>(&h);
    lo = *reinterpret_cast<uint32_t*>(&l2);
}

// ---------------------------------------------------------------------------
// One launch for all 6 one-time splits (blockIdx.y selects the tensor).
// ---------------------------------------------------------------------------
__global__ void split6_kernel(
    const float* __restrict__ s0, __nv_bfloat16* __restrict__ h0,
    __nv_bfloat16* __restrict__ l0, int n0,
    const float* __restrict__ s1, __nv_bfloat16* __restrict__ h1,
    __nv_bfloat16* __restrict__ l1, int n1,
    const float* __restrict__ s2, __nv_bfloat16* __restrict__ h2,
    __nv_bfloat16* __restrict__ l2, int n2,
    const float* __restrict__ s3, __nv_bfloat16* __restrict__ h3,
    __nv_bfloat16* __restrict__ l3, int n3,
    const float* __restrict__ s4, __nv_bfloat16* __restrict__ h4,
    __nv_bfloat16* __restrict__ l4, int n4,
    const float* __restrict__ s5, __nv_bfloat16* __restrict__ h5,
    __nv_bfloat16* __restrict__ l5, int n5)
{
    const float* src; __nv_bfloat16 *hi, *lo; int n;
    switch (blockIdx.y) {
        case 0: src = s0; hi = h0; lo = l0; n = n0; break;
        case 1: src = s1; hi = h1; lo = l1; n = n1; break;
        case 2: src = s2; hi = h2; lo = l2; n = n2; break;
        case 3: src = s3; hi = h3; lo = l3; n = n3; break;
        case 4: src = s4; hi = h4; lo = l4; n = n4; break;
        default: src = s5; hi = h5; lo = l5; n = n5; break;
    }
    int idx = blockIdx.x * blockDim.x + threadIdx.x;
    if (idx >= n) return;
    float4 v = reinterpret_cast<const float4*>(src)[idx];
    uint2 h, l;
    pack_split(v.x, v.y, h.x, l.x);
    pack_split(v.z, v.w, h.y, l.y);
    reinterpret_cast<uint2*>(hi)[idx] = h;
    reinterpret_cast<uint2*>(lo)[idx] = l;
}

// ===========================================================================
// GEMM: 128x128 tile, k-chunk 32, 2 CTAs/SM, cp.async double-buffered,
// one __syncthreads per chunk. 3-term bf16 split with PASS-SEPARATED MMAs
// (no back-to-back same-accumulator HMMAs). Fused epilogues.
// ===========================================================================
#define RSB 80
#define GARR 10240
#define GBUF (4 * GARR)

__global__ void __launch_bounds__(256, 2) gemm_tc_kernel(
    const __nv_bfloat16* __restrict__ A0h, const __nv_bfloat16* __restrict__ A0l,
    const __nv_bfloat16* __restrict__ B0h, const __nv_bfloat16* __restrict__ B0l,
    const float* __restrict__ b0,
    __nv_bfloat16* __restrict__ O0h, __nv_bfloat16* __restrict__ O0l,
    float* __restrict__ F0,
    const __nv_bfloat16* __restrict__ A1h, const __nv_bfloat16* __restrict__ A1l,
    const __nv_bfloat16* __restrict__ B1h, const __nv_bfloat16* __restrict__ B1l,
    const float* __restrict__ b1,
    __nv_bfloat16* __restrict__ O1h, __nv_bfloat16* __restrict__ O1l,
    const __nv_bfloat16* __restrict__ A2h, const __nv_bfloat16* __restrict__ A2l,
    const __nv_bfloat16* __restrict__ B2h, const __nv_bfloat16* __restrict__ B2l,
    const float* __restrict__ b2,
    __nv_bfloat16* __restrict__ O2h, __nv_bfloat16* __restrict__ O2l,
    const float* __restrict__ rope, int fused, int M)
{
    extern __shared__ char sm[];
    const uint32_t smb = smem_to_u32(sm);
    const int tid = threadIdx.x;
    const int lid = tid & 31;
    const int wid = tid >> 5;
    const int wm = wid >> 2, wn = wid & 3;

    const __nv_bfloat16 *Ah, *Al, *Bh, *Bl;
    const float* Bi;
    __nv_bfloat16 *Oh, *Ol;
    if (blockIdx.z == 0)      { Ah=A0h; Al=A0l; Bh=B0h; Bl=B0l; Bi=b0; Oh=O0h; Ol=O0l; }
    else if (blockIdx.z == 1) { Ah=A1h; Al=A1l; Bh=B1h; Bl=B1l; Bi=b1; Oh=O1h; Ol=O1l; }
    else                      { Ah=A2h; Al=A2l; Bh=B2h; Bl=B2l; Bi=b2; Oh=O2h; Ol=O2l; }
    const int mode = fused ? (int)blockIdx.z : 3;

    const int bm = blockIdx.y * 128, bn = blockIdx.x * 128;
    const uint32_t lmoff = (uint32_t)((lid & 15) * RSB + ((lid >> 4) << 4));

    const int r0 = tid >> 2, s0 = (tid & 3);
    const int r1 = (tid + 256) >> 2, s1 = ((tid + 256) & 3);

    float acc[4][4][4];
#pragma unroll
    for (int a = 0; a < 4; a++)
#pragma unroll
        for (int b = 0; b < 4; b++)
#pragma unroll
            for (int c = 0; c < 4; c++) acc[a][b][c] = 0.f;

    auto issue = [&](int ch, int buf) {
        uint32_t base = smb + buf * GBUF;
#pragma unroll
        for (int j = 0; j < 2; j++) {
            int row = j ? r1 : r0;
            int seg = j ? s1 : s0;
            uint32_t doff = (uint32_t)(row * RSB + seg * 16);
            bool ap = (bm + row) < M;
            size_t abyte = ((size_t)(bm + row) * CC + ch * 32) * 2 + seg * 16;
            size_t bbyte = ((size_t)(bn + row) * CC + ch * 32) * 2 + seg * 16;
            cp16(base + doff,             (const char*)Ah + abyte, ap);
            cp16(base + GARR + doff,      (const char*)Al + abyte, ap);
            cp16(base + 2 * GARR + doff,  (const char*)Bh + bbyte, true);
            cp16(base + 3 * GARR + doff,  (const char*)Bl + bbyte, true);
        }
    };

    issue(0, 0);
    CP_COMMIT();

    for (int ch = 0; ch < 32; ch++) {
        CP_WAIT0();
        __syncthreads();
        if (ch < 31) { issue(ch + 1, (ch + 1) & 1); CP_COMMIT(); }

        const uint32_t base = smb + (ch & 1) * GBUF;
#pragma unroll
        for (int ks = 0; ks < 2; ks++) {
            const uint32_t kofs = (uint32_t)(ks * 32);
            uint32_t Af[4][4], Al4[4][4], Bf[2][4];
#pragma unroll
            for (int mt = 0; mt < 4; mt++) {
                uint32_t rb = (uint32_t)((wm * 64 + mt * 16) * RSB) + kofs + lmoff;
                ldm_x4(Af[mt],  base + rb);
                ldm_x4(Al4[mt], base + GARR + rb);
            }
#pragma unroll
            for (int np = 0; np < 2; np++) {
                uint32_t rb = (uint32_t)((wn * 32 + np * 16) * RSB) + kofs + lmoff;
                ldm_x4(Bf[np], base + 2 * GARR + rb);
            }
            // pass 1: Ah x Bh (16 independent accumulators)
#pragma unroll
            for (int mt = 0; mt < 4; mt++)
#pragma unroll
                for (int nt = 0; nt < 4; nt++) {
                    uint32_t bb0 = Bf[nt >> 1][nt & 1];
                    uint32_t bb1 = Bf[nt >> 1][2 + (nt & 1)];
                    mma16816(acc[mt][nt], Af[mt], bb0, bb1);
                }
            // pass 2: Al x Bh
#pragma unroll
            for (int mt = 0; mt < 4; mt++)
#pragma unroll
                for (int nt = 0; nt < 4; nt++) {
                    uint32_t bb0 = Bf[nt >> 1][nt & 1];
                    uint32_t bb1 = Bf[nt >> 1][2 + (nt & 1)];
                    mma16816(acc[mt][nt], Al4[mt], bb0, bb1);
                }
            // reload B lo, pass 3: Ah x Bl
#pragma unroll
            for (int np = 0; np < 2; np++) {
                uint32_t rb = (uint32_t)((wn * 32 + np * 16) * RSB) + kofs + lmoff;
                ldm_x4(Bf[np], base + 3 * GARR + rb);
            }
#pragma unroll
            for (int mt = 0; mt < 4; mt++)
#pragma unroll
                for (int nt = 0; nt < 4; nt++) {
                    uint32_t bb0 = Bf[nt >> 1][nt & 1];
                    uint32_t bb1 = Bf[nt >> 1][2 + (nt & 1)];
                    mma16816(acc[mt][nt], Af[mt], bb0, bb1);
                }
        }
    }

    const int rbase = bm + wm * 64 + (lid >> 2);
    const int cbase = bn + wn * 32 + (lid & 3) * 2;
#pragma unroll
    for (int mt = 0; mt < 4; mt++) {
#pragma unroll
        for (int nt = 0; nt < 4; nt++) {
            int c = cbase + nt * 8;
            float2 bv = *(const float2*)(Bi + c);
#pragma unroll
            for (int half = 0; half < 2; half++) {
                int rr = rbase + mt * 16 + half * 8;
                if (rr >= M) continue;
                float v0 = acc[mt][nt][half * 2 + 0] + bv.x;
                float v1 = acc[mt][nt][half * 2 + 1] + bv.y;
                if (mode == 3) {
                    *(float2*)(F0 + (size_t)rr * CC + c) = make_float2(v0, v1);
                    continue;
                }
                if (mode <= 1) {
                    int d = c & 63;
                    if (d < LL) {
                        int t = rr % TT;
                        float f0 = rope[t * LL + d], f1 = rope[t * LL + d + 1];
                        float c0 = cosf(f0), s0f = sinf(f0);
                        float c1 = cosf(f1), s1f = sinf(f1);
                        float a = v0, bq2 = v1;
                        v0 = a * c0 - bq2 * s0f;
                        v1 = bq2 * c1 + a * s1f;
                    }
                    if (mode == 0) { v0 *= 0.125f; v1 *= 0.125f; }
                }
                uint32_t h, l;
                pack_split(v0, v1, h, l);
                size_t off = (size_t)rr * CC + c;
                *reinterpret_cast<uint32_t*>(Oh + off) = h;
                *reinterpret_cast<uint32_t*>(Ol + off) = l;
            }
        }
    }
}

// ===========================================================================
// Tensor-core flash attention. CTA = (64 q, h, b); 4 warps x 16 q-rows,
// 128 threads, single sync per kv tile, pass-separated MMAs.
// ===========================================================================
#define AST 144
#define SQH 0
#define SQL 9216
#define SKH(b) (18432 + (b) * 18432)
#define SKL(b) (SKH(b) + 9216)
#define SVH(b) (55296 + (b) * 18432)
#define SVL(b) (SVH(b) + 9216)
#define SMEM_ATTN 92160

__global__ void __launch_bounds__(128) attn_tc_kernel(
    const __nv_bfloat16* __restrict__ qh, const __nv_bfloat16* __restrict__ ql,
    const __nv_bfloat16* __restrict__ kh, const __nv_bfloat16* __restrict__ kl,
    const __nv_bfloat16* __restrict__ vh, const __nv_bfloat16* __restrict__ vl,
    __nv_bfloat16* __restrict__ oh, __nv_bfloat16* __restrict__ ol)
{
    extern __shared__ char sm[];
    const uint32_t smb = smem_to_u32(sm);
    const int tid = threadIdx.x;
    const int l = tid & 31, w = tid >> 5;
    const int q0 = blockIdx.x * 64;
    const int h = blockIdx.y, b = blockIdx.z;
    const size_t rb = (size_t)b * TT * CC + (size_t)h * HD;

#pragma unroll
    for (int j = 0; j < 4; j++) {
        int slot = tid + j * 128;
        int row = slot >> 3, seg = slot & 7;
        bool p = (q0 + row) < TT;
        size_t byte = (rb + (size_t)(q0 + row) * CC) * 2 + seg * 16;
        uint32_t doff = (uint32_t)(row * AST + seg * 16);
        cp16(smb + SQH + doff, (const char*)qh + byte, p);
        cp16(smb + SQL + doff, (const char*)ql + byte, p);
    }

    auto issue_kv = [&](int t, int buf) {
        int kv0 = t * 64;
#pragma unroll
        for (int j = 0; j < 4; j++) {
            int slot = tid + j * 128;
            int row = slot >> 3, seg = slot & 7;
            bool p = (kv0 + row) < TT;
            size_t byte = (rb + (size_t)(kv0 + row) * CC) * 2 + seg * 16;
            uint32_t doff = (uint32_t)(row * AST + seg * 16);
            cp16(smb + SKH(buf) + doff, (const char*)kh + byte, p);
            cp16(smb + SKL(buf) + doff, (const char*)kl + byte, p);
            cp16(smb + SVH(buf) + doff, (const char*)vh + byte, p);
            cp16(smb + SVL(buf) + doff, (const char*)vl + byte, p);
        }
    };

    issue_kv(0, 0);
    CP_COMMIT();

    int kv_end = q0 + COND + 63;
    if (kv_end > TT) kv_end = TT;
    const int nkv = (kv_end + 63) >> 6;

    const uint32_t lmoff = (uint32_t)((l & 15) * AST + ((l >> 4) << 4));
    const int qg0 = q0 + w * 16 + (l >> 2);
    const int qg1 = qg0 + 8;

    uint32_t Qf[4][4], Ql4[4][4];
    float Oacc[8][4];
#pragma unroll
    for (int i = 0; i < 8; i++)
#pragma unroll
        for (int j = 0; j < 4; j++) Oacc[i][j] = 0.f;
    float m0 = -1e30f, m1 = -1e30f, l0 = 0.f, l1 = 0.f;

    for (int t = 0; t < nkv; t++) {
        const int buf = t & 1;
        CP_WAIT0();
        __syncthreads();
        if (t + 1 < nkv) { issue_kv(t + 1, buf ^ 1); CP_COMMIT(); }

        if (t == 0) {
#pragma unroll
            for (int ks = 0; ks < 4; ks++) {
                uint32_t rbq = (uint32_t)((w * 16) * AST) + ks * 32 + lmoff;
                ldm_x4(Qf[ks],  smb + SQH + rbq);
                ldm_x4(Ql4[ks], smb + SQL + rbq);
            }
        }

        const int kv0 = t * 64;
        float S[8][4];
#pragma unroll
        for (int i = 0; i < 8; i++)
#pragma unroll
            for (int j = 0; j < 4; j++) S[i][j] = 0.f;

#pragma unroll
        for (int ks = 0; ks < 4; ks++) {
            uint32_t Kf[4][4], Kl4[4][4];
#pragma unroll
            for (int np = 0; np < 4; np++) {
                uint32_t rbk = (uint32_t)((np * 16) * AST) + ks * 32 + lmoff;
                ldm_x4(Kf[np],  smb + SKH(buf) + rbk);
                ldm_x4(Kl4[np], smb + SKL(buf) + rbk);
            }
            // pass 1: Qh x Kh over all 8 S tiles
#pragma unroll
            for (int nt = 0; nt < 8; nt++) {
                uint32_t bh0 = Kf[nt >> 1][nt & 1];
                uint32_t bh1 = Kf[nt >> 1][2 + (nt & 1)];
                mma16816(S[nt], Qf[ks], bh0, bh1);
            }
            // pass 2: Ql x Kh
#pragma unroll
            for (int nt = 0; nt < 8; nt++) {
                uint32_t bh0 = Kf[nt >> 1][nt & 1];
                uint32_t bh1 = Kf[nt >> 1][2 + (nt & 1)];
                mma16816(S[nt], Ql4[ks], bh0, bh1);
            }
            // pass 3: Qh x Kl
#pragma unroll
            for (int nt = 0; nt < 8; nt++) {
                uint32_t bl0 = Kl4[nt >> 1][nt & 1];
                uint32_t bl1 = Kl4[nt >> 1][2 + (nt & 1)];
                mma16816(S[nt], Qf[ks], bl0, bl1);
            }
        }

        float mx0 = -1e30f, mx1 = -1e30f;
#pragma unroll
        for (int nt = 0; nt < 8; nt++) {
#pragma unroll
            for (int e = 0; e < 2; e++) {
                int kvc = kv0 + nt * 8 + (l & 3) * 2 + e;
                bool inb = kvc < TT;
                if (!(inb && kvc < COND + qg0)) S[nt][e] = -1e30f;
                if (!(inb && kvc < COND + qg1)) S[nt][2 + e] = -1e30f;
                mx0 = fmaxf(mx0, S[nt][e]);
                mx1 = fmaxf(mx1, S[nt][2 + e]);
            }
        }
        mx0 = fmaxf(mx0, __shfl_xor_sync(0xffffffffu, mx0, 1));
        mx0 = fmaxf(mx0, __shfl_xor_sync(0xffffffffu, mx0, 2));
        mx1 = fmaxf(mx1, __shfl_xor_sync(0xffffffffu, mx1, 1));
        mx1 = fmaxf(mx1, __shfl_xor_sync(0xffffffffu, mx1, 2));

        float mn0 = fmaxf(m0, mx0), mn1 = fmaxf(m1, mx1);
        float al0 = __expf(m0 - mn0), al1 = __expf(m1 - mn1);
        m0 = mn0; m1 = mn1;

        float s0 = 0.f, s1 = 0.f;
#pragma unroll
        for (int nt = 0; nt < 8; nt++) {
#pragma unroll
            for (int e = 0; e < 2; e++) {
                S[nt][e] = __expf(S[nt][e] - mn0);         s0 += S[nt][e];
                S[nt][2 + e] = __expf(S[nt][2 + e] - mn1); s1 += S[nt][2 + e];
            }
        }
        s0 += __shfl_xor_sync(0xffffffffu, s0, 1);
        s0 += __shfl_xor_sync(0xffffffffu, s0, 2);
        s1 += __shfl_xor_sync(0xffffffffu, s1, 1);
        s1 += __shfl_xor_sync(0xffffffffu, s1, 2);
        l0 = l0 * al0 + s0;
        l1 = l1 * al1 + s1;

#pragma unroll
        for (int nt = 0; nt < 8; nt++) {
            Oacc[nt][0] *= al0; Oacc[nt][1] *= al0;
            Oacc[nt][2] *= al1; Oacc[nt][3] *= al1;
        }

#pragma unroll
        for (int ks = 0; ks < 4; ks++) {
            uint32_t Ph[4], Pl[4];
            pack_split(S[2 * ks][0],     S[2 * ks][1],     Ph[0], Pl[0]);
            pack_split(S[2 * ks][2],     S[2 * ks][3],     Ph[1], Pl[1]);
            pack_split(S[2 * ks + 1][0], S[2 * ks + 1][1], Ph[2], Pl[2]);
            pack_split(S[2 * ks + 1][2], S[2 * ks + 1][3], Ph[3], Pl[3]);

            uint32_t Vf[4][4], Vl4[4][4];
#pragma unroll
            for (int np = 0; np < 4; np++) {
                uint32_t rbv = (uint32_t)((ks * 16) * AST) + np * 32 + lmoff;
                ldm_x4_t(Vf[np],  smb + SVH(buf) + rbv);
                ldm_x4_t(Vl4[np], smb + SVL(buf) + rbv);
            }
            // pass 1: Ph x Vh
#pragma unroll
            for (int nt = 0; nt < 8; nt++) {
                uint32_t bh0 = Vf[nt >> 1][(nt & 1) * 2];
                uint32_t bh1 = Vf[nt >> 1][(nt & 1) * 2 + 1];
                mma16816(Oacc[nt], Ph, bh0, bh1);
            }
            // pass 2: Pl x Vh
#pragma unroll
            for (int nt = 0; nt < 8; nt++) {
                uint32_t bh0 = Vf[nt >> 1][(nt & 1) * 2];
                uint32_t bh1 = Vf[nt >> 1][(nt & 1) * 2 + 1];
                mma16816(Oacc[nt], Pl, bh0, bh1);
            }
            // pass 3: Ph x Vl
#pragma unroll
            for (int nt = 0; nt < 8; nt++) {
                uint32_t bl0 = Vl4[nt >> 1][(nt & 1) * 2];
                uint32_t bl1 = Vl4[nt >> 1][(nt & 1) * 2 + 1];
                mma16816(Oacc[nt], Ph, bl0, bl1);
            }
        }
    }

    float inv0 = 1.f / l0, inv1 = 1.f / l1;
#pragma unroll
    for (int nt = 0; nt < 8; nt++) {
        int c = nt * 8 + (l & 3) * 2;
        uint32_t hi, lo;
        if (qg0 < TT) {
            pack_split(Oacc[nt][0] * inv0, Oacc[nt][1] * inv0, hi, lo);
            size_t off = rb + (size_t)qg0 * CC + c;
            *reinterpret_cast<uint32_t*>(oh + off) = hi;
            *reinterpret_cast<uint32_t*>(ol + off) = lo;
        }
        if (qg1 < TT) {
            pack_split(Oacc[nt][2] * inv1, Oacc[nt][3] * inv1, hi, lo);
            size_t off = rb + (size_t)qg1 * CC + c;
            *reinterpret_cast<uint32_t*>(oh + off) = hi;
            *reinterpret_cast<uint32_t*>(ol + off) = lo;
        }
    }
}

// ---------------------------------------------------------------------------
// Launch
// ---------------------------------------------------------------------------
extern "C" void kernel_launch(void* const* d_in, const int* in_sizes, int n_in,
                              void* d_out, int out_size)
{
    const float* x_q  = (const float*)d_in[0];
    const float* x_kv = (const float*)d_in[1];
    const float* rope = (const float*)d_in[2];
    const float* Wq   = (const float*)d_in[3];
    const float* bq   = (const float*)d_in[4];
    const float* Wk   = (const float*)d_in[5];
    const float* bk   = (const float*)d_in[6];
    const float* Wv   = (const float*)d_in[7];
    const float* bv   = (const float*)d_in[8];
    const float* Wp   = (const float*)d_in[9];
    const float* bp   = (const float*)d_in[10];
    float* out = (float*)d_out;

    __nv_bfloat16 *xqh, *xql, *xkh, *xkl, *Wh, *Wl;
    __nv_bfloat16 *qh, *ql, *kh, *kl, *vh, *vl, *ah, *al;
    cudaGetSymbolAddress((void**)&xqh, g_xqh);
    cudaGetSymbolAddress((void**)&xql, g_xql);
    cudaGetSymbolAddress((void**)&xkh, g_xkh);
    cudaGetSymbolAddress((void**)&xkl, g_xkl);
    cudaGetSymbolAddress((void**)&Wh,  g_Wh);
    cudaGetSymbolAddress((void**)&Wl,  g_Wl);
    cudaGetSymbolAddress((void**)&qh,  g_qh);
    cudaGetSymbolAddress((void**)&ql,  g_ql);
    cudaGetSymbolAddress((void**)&kh,  g_kh);
    cudaGetSymbolAddress((void**)&kl,  g_kl);
    cudaGetSymbolAddress((void**)&vh,  g_vh);
    cudaGetSymbolAddress((void**)&vl,  g_vl);
    cudaGetSymbolAddress((void**)&ah,  g_ah);
    cudaGetSymbolAddress((void**)&al,  g_al);

    cudaFuncSetAttribute(gemm_tc_kernel,
        cudaFuncAttributeMaxDynamicSharedMemorySize, 2 * GBUF);
    cudaFuncSetAttribute(attn_tc_kernel,
        cudaFuncAttributeMaxDynamicSharedMemorySize, SMEM_ATTN);

    // 1) all six one-time splits in ONE launch
    const int NX4 = MROWS * CC / 4;
    const int NW4 = CC * CC / 4;
    dim3 split_grid((NX4 + 255) / 256, 6);
    split6_kernel<<<split_grid, 256>>>(
        x_q,  xqh, xql, NX4,
        x_kv, xkh, xkl, NX4,
        Wq, Wh,              Wl,              NW4,
        Wk, Wh + CC * CC,     Wl + CC * CC,     NW4,
        Wv, Wh + 2 * CC * CC, Wl + 2 * CC * CC, NW4,
        Wp, Wh + 3 * CC * CC, Wl + 3 * CC * CC, NW4);

    // 2) fused Q/K/V projections with rotary/scale/split epilogues
    dim3 g_qkv(CC / 128, (MROWS + 127) / 128, 3);   // (8, 49, 3)
    gemm_tc_kernel<<<g_qkv, 256, 2 * GBUF>>>(
        xqh, xql, Wh,              Wl,              bq, qh, ql, nullptr,
        xkh, xkl, Wh + CC * CC,     Wl + CC * CC,     bk, kh, kl,
        xkh, xkl, Wh + 2 * CC * CC, Wl + 2 * CC * CC, bv, vh, vl,
        rope, 1, MROWS);

    // 3) tensor-core attention (64-q tiles) -> split output
    dim3 attn_grid((TT + 63) / 64, HH, BB);         // (13, 16, 8)
    attn_tc_kernel<<<attn_grid, 128, SMEM_ATTN>>>(qh, ql, kh, kl, vh, vl, ah, al);

    // 4) output projection, f32 epilogue
    dim3 g_out(CC / 128, (MROWS + 127) / 128, 1);
    gemm_tc_kernel<<<g_out, 256, 2 * GBUF>>>(
        ah, al, Wh + 3 * CC * CC, Wl + 3 * CC * CC, bp, nullptr, nullptr, out,
        ah, al, Wh + 3 * CC * CC, Wl + 3 * CC * CC, bp, nullptr, nullptr,
        ah, al, Wh + 3 * CC * CC, Wl + 3 * CC * CC, bp, nullptr, nullptr,
        rope, 0, MROWS);
}

// round 10
// speedup vs baseline: 1.0631x; 1.0631x over previous
#include <cuda_runtime.h>
#include <cuda_bf16.h>
#include <math.h>
#include <stdint.h>

#define BB 8
#define TT 769
#define CC 1024
#define HH 16
#define HD 64
#define LL 32
#define COND 256
#define MROWS (BB*TT)   // 6152

// ---------------------------------------------------------------------------
// Device scratch (allocation-free requirement -> globals)
// ---------------------------------------------------------------------------
__device__ __nv_bfloat16 g_xqh[(size_t)MROWS * CC], g_xql[(size_t)MROWS * CC];
__device__ __nv_bfloat16 g_xkh[(size_t)MROWS * CC], g_xkl[(size_t)MROWS * CC];
__device__ __nv_bfloat16 g_Wh[(size_t)4 * CC * CC], g_Wl[(size_t)4 * CC * CC];
__device__ __nv_bfloat16 g_qh[(size_t)MROWS * CC], g_ql[(size_t)MROWS * CC];
__device__ __nv_bfloat16 g_kh[(size_t)MROWS * CC], g_kl[(size_t)MROWS * CC];
__device__ __nv_bfloat16 g_vh[(size_t)MROWS * CC], g_vl[(size_t)MROWS * CC];
__device__ __nv_bfloat16 g_ah[(size_t)MROWS * CC], g_al[(size_t)MROWS * CC];

// ---------------------------------------------------------------------------
// Helpers
// ---------------------------------------------------------------------------
__device__ __forceinline__ uint32_t smem_to_u32(const void* p) {
    uint32_t a;
    asm("{ .reg .u64 t; cvta.to.shared.u64 t, %1; cvt.u32.u64 %0, t; }"
        : "=r"(a) : "l"(p));
    return a;
}
__device__ __forceinline__ void ldm_x4(uint32_t* r, uint32_t addr) {
    asm volatile("ldmatrix.sync.aligned.m8n8.x4.shared.b16 {%0,%1,%2,%3}, [%4];"
        : "=r"(r[0]), "=r"(r[1]), "=r"(r[2]), "=r"(r[3]) : "r"(addr));
}
__device__ __forceinline__ void ldm_x4_t(uint32_t* r, uint32_t addr) {
    asm volatile("ldmatrix.sync.aligned.m8n8.x4.trans.shared.b16 {%0,%1,%2,%3}, [%4];"
        : "=r"(r[0]), "=r"(r[1]), "=r"(r[2]), "=r"(r[3]) : "r"(addr));
}
__device__ __forceinline__ void mma16816(float* d, const uint32_t* a,
                                         uint32_t b0, uint32_t b1) {
    asm("mma.sync.aligned.m16n8k16.row.col.f32.bf16.bf16.f32 "
        "{%0,%1,%2,%3}, {%4,%5,%6,%7}, {%8,%9}, {%0,%1,%2,%3};"
        : "+f"(d[0]), "+f"(d[1]), "+f"(d[2]), "+f"(d[3])
        : "r"(a[0]), "r"(a[1]), "r"(a[2]), "r"(a[3]), "r"(b0), "r"(b1));
}
__device__ __forceinline__ void cp16(uint32_t dst, const void* src, bool pred) {
    int n = pred ? 16 : 0;
    asm volatile("cp.async.cg.shared.global [%0], [%1], 16, %2;"
        :: "r"(dst), "l"(src), "r"(n) : "memory");
}
#define CP_COMMIT() asm volatile("cp.async.commit_group;" ::: "memory")
#define CP_WAIT0()  asm volatile("cp.async.wait_group 0;" ::: "memory")

// pack 2 floats -> bf16x2 hi + bf16x2 residual-lo
__device__ __forceinline__ void pack_split(float x, float y,
                                           uint32_t& hi, uint32_t& lo) {
    __nv_bfloat162 h = __floats2bfloat162_rn(x, y);
    float hx = __low2float(h), hy = __high2float(h);
    __nv_bfloat162 l2 = __floats2bfloat162_rn(x - hx, y - hy);
    hi = *reinterpret_cast<uint32_t*>(&h);
    lo = *reinterpret_cast<uint32_t*>(&l2);
}

// ---------------------------------------------------------------------------
// One launch for all 6 one-time splits (blockIdx.y selects the tensor).
// ---------------------------------------------------------------------------
__global__ void split6_kernel(
    const float* __restrict__ s0, __nv_bfloat16* __restrict__ h0,
    __nv_bfloat16* __restrict__ l0, int n0,
    const float* __restrict__ s1, __nv_bfloat16* __restrict__ h1,
    __nv_bfloat16* __restrict__ l1, int n1,
    const float* __restrict__ s2, __nv_bfloat16* __restrict__ h2,
    __nv_bfloat16* __restrict__ l2, int n2,
    const float* __restrict__ s3, __nv_bfloat16* __restrict__ h3,
    __nv_bfloat16* __restrict__ l3, int n3,
    const float* __restrict__ s4, __nv_bfloat16* __restrict__ h4,
    __nv_bfloat16* __restrict__ l4, int n4,
    const float* __restrict__ s5, __nv_bfloat16* __restrict__ h5,
    __nv_bfloat16* __restrict__ l5, int n5)
{
    const float* src; __nv_bfloat16 *hi, *lo; int n;
    switch (blockIdx.y) {
        case 0: src = s0; hi = h0; lo = l0; n = n0; break;
        case 1: src = s1; hi = h1; lo = l1; n = n1; break;
        case 2: src = s2; hi = h2; lo = l2; n = n2; break;
        case 3: src = s3; hi = h3; lo = l3; n = n3; break;
        case 4: src = s4; hi = h4; lo = l4; n = n4; break;
        default: src = s5; hi = h5; lo = l5; n = n5; break;
    }
    int idx = blockIdx.x * blockDim.x + threadIdx.x;
    if (idx >= n) return;
    float4 v = reinterpret_cast<const float4*>(src)[idx];
    uint2 h, l;
    pack_split(v.x, v.y, h.x, l.x);
    pack_split(v.z, v.w, h.y, l.y);
    reinterpret_cast<uint2*>(hi)[idx] = h;
    reinterpret_cast<uint2*>(lo)[idx] = l;
}

// ===========================================================================
// GEMM (unchanged, proven config): 128x128 tile, k-chunk 32, 2 CTAs/SM,
// cp.async double-buffered, one sync per chunk, 3-term bf16 split,
// fused epilogues.
// ===========================================================================
#define RSB 80
#define GARR 10240
#define GBUF (4 * GARR)

__global__ void __launch_bounds__(256, 2) gemm_tc_kernel(
    const __nv_bfloat16* __restrict__ A0h, const __nv_bfloat16* __restrict__ A0l,
    const __nv_bfloat16* __restrict__ B0h, const __nv_bfloat16* __restrict__ B0l,
    const float* __restrict__ b0,
    __nv_bfloat16* __restrict__ O0h, __nv_bfloat16* __restrict__ O0l,
    float* __restrict__ F0,
    const __nv_bfloat16* __restrict__ A1h, const __nv_bfloat16* __restrict__ A1l,
    const __nv_bfloat16* __restrict__ B1h, const __nv_bfloat16* __restrict__ B1l,
    const float* __restrict__ b1,
    __nv_bfloat16* __restrict__ O1h, __nv_bfloat16* __restrict__ O1l,
    const __nv_bfloat16* __restrict__ A2h, const __nv_bfloat16* __restrict__ A2l,
    const __nv_bfloat16* __restrict__ B2h, const __nv_bfloat16* __restrict__ B2l,
    const float* __restrict__ b2,
    __nv_bfloat16* __restrict__ O2h, __nv_bfloat16* __restrict__ O2l,
    const float* __restrict__ rope, int fused, int M)
{
    extern __shared__ char sm[];
    const uint32_t smb = smem_to_u32(sm);
    const int tid = threadIdx.x;
    const int lid = tid & 31;
    const int wid = tid >> 5;
    const int wm = wid >> 2, wn = wid & 3;

    const __nv_bfloat16 *Ah, *Al, *Bh, *Bl;
    const float* Bi;
    __nv_bfloat16 *Oh, *Ol;
    if (blockIdx.z == 0)      { Ah=A0h; Al=A0l; Bh=B0h; Bl=B0l; Bi=b0; Oh=O0h; Ol=O0l; }
    else if (blockIdx.z == 1) { Ah=A1h; Al=A1l; Bh=B1h; Bl=B1l; Bi=b1; Oh=O1h; Ol=O1l; }
    else                      { Ah=A2h; Al=A2l; Bh=B2h; Bl=B2l; Bi=b2; Oh=O2h; Ol=O2l; }
    const int mode = fused ? (int)blockIdx.z : 3;

    const int bm = blockIdx.y * 128, bn = blockIdx.x * 128;
    const uint32_t lmoff = (uint32_t)((lid & 15) * RSB + ((lid >> 4) << 4));

    const int r0 = tid >> 2, s0 = (tid & 3);
    const int r1 = (tid + 256) >> 2, s1 = ((tid + 256) & 3);

    float acc[4][4][4];
#pragma unroll
    for (int a = 0; a < 4; a++)
#pragma unroll
        for (int b = 0; b < 4; b++)
#pragma unroll
            for (int c = 0; c < 4; c++) acc[a][b][c] = 0.f;

    auto issue = [&](int ch, int buf) {
        uint32_t base = smb + buf * GBUF;
#pragma unroll
        for (int j = 0; j < 2; j++) {
            int row = j ? r1 : r0;
            int seg = j ? s1 : s0;
            uint32_t doff = (uint32_t)(row * RSB + seg * 16);
            bool ap = (bm + row) < M;
            size_t abyte = ((size_t)(bm + row) * CC + ch * 32) * 2 + seg * 16;
            size_t bbyte = ((size_t)(bn + row) * CC + ch * 32) * 2 + seg * 16;
            cp16(base + doff,             (const char*)Ah + abyte, ap);
            cp16(base + GARR + doff,      (const char*)Al + abyte, ap);
            cp16(base + 2 * GARR + doff,  (const char*)Bh + bbyte, true);
            cp16(base + 3 * GARR + doff,  (const char*)Bl + bbyte, true);
        }
    };

    issue(0, 0);
    CP_COMMIT();

    for (int ch = 0; ch < 32; ch++) {
        CP_WAIT0();
        __syncthreads();
        if (ch < 31) { issue(ch + 1, (ch + 1) & 1); CP_COMMIT(); }

        const uint32_t base = smb + (ch & 1) * GBUF;
#pragma unroll
        for (int ks = 0; ks < 2; ks++) {
            const uint32_t kofs = (uint32_t)(ks * 32);
            uint32_t Af[4][4], Al4[4][4], Bf[2][4];
#pragma unroll
            for (int mt = 0; mt < 4; mt++) {
                uint32_t rb = (uint32_t)((wm * 64 + mt * 16) * RSB) + kofs + lmoff;
                ldm_x4(Af[mt],  base + rb);
                ldm_x4(Al4[mt], base + GARR + rb);
            }
#pragma unroll
            for (int np = 0; np < 2; np++) {
                uint32_t rb = (uint32_t)((wn * 32 + np * 16) * RSB) + kofs + lmoff;
                ldm_x4(Bf[np], base + 2 * GARR + rb);
            }
#pragma unroll
            for (int mt = 0; mt < 4; mt++)
#pragma unroll
                for (int nt = 0; nt < 4; nt++) {
                    uint32_t bb0 = Bf[nt >> 1][nt & 1];
                    uint32_t bb1 = Bf[nt >> 1][2 + (nt & 1)];
                    mma16816(acc[mt][nt], Af[mt], bb0, bb1);
                    mma16816(acc[mt][nt], Al4[mt], bb0, bb1);
                }
#pragma unroll
            for (int np = 0; np < 2; np++) {
                uint32_t rb = (uint32_t)((wn * 32 + np * 16) * RSB) + kofs + lmoff;
                ldm_x4(Bf[np], base + 3 * GARR + rb);
            }
#pragma unroll
            for (int mt = 0; mt < 4; mt++)
#pragma unroll
                for (int nt = 0; nt < 4; nt++) {
                    uint32_t bb0 = Bf[nt >> 1][nt & 1];
                    uint32_t bb1 = Bf[nt >> 1][2 + (nt & 1)];
                    mma16816(acc[mt][nt], Af[mt], bb0, bb1);
                }
        }
    }

    const int rbase = bm + wm * 64 + (lid >> 2);
    const int cbase = bn + wn * 32 + (lid & 3) * 2;
#pragma unroll
    for (int mt = 0; mt < 4; mt++) {
#pragma unroll
        for (int nt = 0; nt < 4; nt++) {
            int c = cbase + nt * 8;
            float2 bv = *(const float2*)(Bi + c);
#pragma unroll
            for (int half = 0; half < 2; half++) {
                int rr = rbase + mt * 16 + half * 8;
                if (rr >= M) continue;
                float v0 = acc[mt][nt][half * 2 + 0] + bv.x;
                float v1 = acc[mt][nt][half * 2 + 1] + bv.y;
                if (mode == 3) {
                    *(float2*)(F0 + (size_t)rr * CC + c) = make_float2(v0, v1);
                    continue;
                }
                if (mode <= 1) {
                    int d = c & 63;
                    if (d < LL) {
                        int t = rr % TT;
                        float f0 = rope[t * LL + d], f1 = rope[t * LL + d + 1];
                        float c0 = cosf(f0), s0f = sinf(f0);
                        float c1 = cosf(f1), s1f = sinf(f1);
                        float a = v0, bq2 = v1;
                        v0 = a * c0 - bq2 * s0f;
                        v1 = bq2 * c1 + a * s1f;
                    }
                    if (mode == 0) { v0 *= 0.125f; v1 *= 0.125f; }
                }
                uint32_t h, l;
                pack_split(v0, v1, h, l);
                size_t off = (size_t)rr * CC + c;
                *reinterpret_cast<uint32_t*>(Oh + off) = h;
                *reinterpret_cast<uint32_t*>(Ol + off) = l;
            }
        }
    }
}

// ===========================================================================
// Tensor-core flash attention v3. CTA = (64 q, h, b); 4 warps, 128 threads.
// XOR-swizzled smem (no padding): 64 KB/CTA -> 3 CTAs/SM = 12 warps.
// Q is staged in buffer 1 and overwritten by kv tile 1 after fragments load.
// ===========================================================================
// per-buffer layout (32768 B): Kh 0 | Kl 8192 | Vh 16384 | Vl 24576
#define ABUF(b)  ((b) * 32768)
#define AKH(b)   (ABUF(b) + 0)
#define AKL(b)   (ABUF(b) + 8192)
#define AVH(b)   (ABUF(b) + 16384)
#define AVL(b)   (ABUF(b) + 24576)
#define AQH      (ABUF(1) + 0)       // aliases buf1 Kh
#define AQL      (ABUF(1) + 8192)    // aliases buf1 Kl
#define SMEM_ATTN 65536

// swizzled byte offset within a 64x128B tile: row*128 ^ ((row&7)<<4) applied
// to the 16B segment index.
#define SWOFF(row, seg) ((uint32_t)((row) * 128 + ((((seg) ^ ((row) & 7))) << 4)))

__global__ void __launch_bounds__(128, 3) attn_tc_kernel(
    const __nv_bfloat16* __restrict__ qh, const __nv_bfloat16* __restrict__ ql,
    const __nv_bfloat16* __restrict__ kh, const __nv_bfloat16* __restrict__ kl,
    const __nv_bfloat16* __restrict__ vh, const __nv_bfloat16* __restrict__ vl,
    __nv_bfloat16* __restrict__ oh, __nv_bfloat16* __restrict__ ol)
{
    extern __shared__ char sm[];
    const uint32_t smb = smem_to_u32(sm);
    const int tid = threadIdx.x;
    const int l = tid & 31, w = tid >> 5;
    const int q0 = blockIdx.x * 64;
    const int h = blockIdx.y, b = blockIdx.z;
    const size_t rb = (size_t)b * TT * CC + (size_t)h * HD;

    // lane constants for swizzled ldmatrix addressing:
    // addr = base + (R + (l&15))*128 + (((cseg | (l>>4)) ^ (l&7)) << 4)
    const uint32_t lrow = (uint32_t)(l & 15) * 128;
    const uint32_t lhb = (uint32_t)(l >> 4);
    const uint32_t lx7 = (uint32_t)(l & 7);
    auto swa = [&](uint32_t base, uint32_t R, uint32_t cseg) {
        return base + R * 128 + lrow + ((((cseg | lhb)) ^ lx7) << 4);
    };

    // ---- stage Q in buf1 (swizzled), read frags, then free the region ----
#pragma unroll
    for (int j = 0; j < 4; j++) {
        int slot = tid + j * 128;          // 0..511 = 64 rows x 8 segs
        int row = slot >> 3, seg = slot & 7;
        bool p = (q0 + row) < TT;
        size_t byte = (rb + (size_t)(q0 + row) * CC) * 2 + seg * 16;
        uint32_t doff = SWOFF(row, seg);
        cp16(smb + AQH + doff, (const char*)qh + byte, p);
        cp16(smb + AQL + doff, (const char*)ql + byte, p);
    }
    CP_COMMIT();
    CP_WAIT0();
    __syncthreads();

    uint32_t Qf[4][4], Ql4[4][4];
#pragma unroll
    for (int ks = 0; ks < 4; ks++) {
        ldm_x4(Qf[ks],  swa(smb + AQH, (uint32_t)(w * 16), (uint32_t)(ks * 2)));
        ldm_x4(Ql4[ks], swa(smb + AQL, (uint32_t)(w * 16), (uint32_t)(ks * 2)));
    }
    __syncthreads();                       // all warps done with Q region

    auto issue_kv = [&](int t, int buf) {
        int kv0 = t * 64;
#pragma unroll
        for (int j = 0; j < 4; j++) {
            int slot = tid + j * 128;
            int row = slot >> 3, seg = slot & 7;
            bool p = (kv0 + row) < TT;
            size_t byte = (rb + (size_t)(kv0 + row) * CC) * 2 + seg * 16;
            uint32_t doff = SWOFF(row, seg);
            cp16(smb + AKH(buf) + doff, (const char*)kh + byte, p);
            cp16(smb + AKL(buf) + doff, (const char*)kl + byte, p);
            cp16(smb + AVH(buf) + doff, (const char*)vh + byte, p);
            cp16(smb + AVL(buf) + doff, (const char*)vl + byte, p);
        }
    };

    issue_kv(0, 0);
    CP_COMMIT();

    int kv_end = q0 + COND + 63;
    if (kv_end > TT) kv_end = TT;
    const int nkv = (kv_end + 63) >> 6;    // >= 4 always (COND=256)

    const int qg0 = q0 + w * 16 + (l >> 2);
    const int qg1 = qg0 + 8;

    float Oacc[8][4];
#pragma unroll
    for (int i = 0; i < 8; i++)
#pragma unroll
        for (int j = 0; j < 4; j++) Oacc[i][j] = 0.f;
    float m0 = -1e30f, m1 = -1e30f, l0 = 0.f, l1 = 0.f;

    for (int t = 0; t < nkv; t++) {
        const int buf = t & 1;
        CP_WAIT0();                        // kv tile t resident
        __syncthreads();                   // prev iteration's reads complete
        if (t + 1 < nkv) { issue_kv(t + 1, buf ^ 1); CP_COMMIT(); }

        const int kv0 = t * 64;
        float S[8][4];
#pragma unroll
        for (int i = 0; i < 8; i++)
#pragma unroll
            for (int j = 0; j < 4; j++) S[i][j] = 0.f;

#pragma unroll
        for (int ks = 0; ks < 4; ks++) {
            uint32_t Kf[4][4], Kl4[4][4];
#pragma unroll
            for (int np = 0; np < 4; np++) {
                ldm_x4(Kf[np],  swa(smb + AKH(buf), (uint32_t)(np * 16), (uint32_t)(ks * 2)));
                ldm_x4(Kl4[np], swa(smb + AKL(buf), (uint32_t)(np * 16), (uint32_t)(ks * 2)));
            }
#pragma unroll
            for (int nt = 0; nt < 8; nt++) {
                uint32_t bh0 = Kf[nt >> 1][nt & 1];
                uint32_t bh1 = Kf[nt >> 1][2 + (nt & 1)];
                mma16816(S[nt], Qf[ks], bh0, bh1);
                mma16816(S[nt], Ql4[ks], bh0, bh1);
                uint32_t bl0 = Kl4[nt >> 1][nt & 1];
                uint32_t bl1 = Kl4[nt >> 1][2 + (nt & 1)];
                mma16816(S[nt], Qf[ks], bl0, bl1);
            }
        }

        float mx0 = -1e30f, mx1 = -1e30f;
#pragma unroll
        for (int nt = 0; nt < 8; nt++) {
#pragma unroll
            for (int e = 0; e < 2; e++) {
                int kvc = kv0 + nt * 8 + (l & 3) * 2 + e;
                bool inb = kvc < TT;
                if (!(inb && kvc < COND + qg0)) S[nt][e] = -1e30f;
                if (!(inb && kvc < COND + qg1)) S[nt][2 + e] = -1e30f;
                mx0 = fmaxf(mx0, S[nt][e]);
                mx1 = fmaxf(mx1, S[nt][2 + e]);
            }
        }
        mx0 = fmaxf(mx0, __shfl_xor_sync(0xffffffffu, mx0, 1));
        mx0 = fmaxf(mx0, __shfl_xor_sync(0xffffffffu, mx0, 2));
        mx1 = fmaxf(mx1, __shfl_xor_sync(0xffffffffu, mx1, 1));
        mx1 = fmaxf(mx1, __shfl_xor_sync(0xffffffffu, mx1, 2));

        float mn0 = fmaxf(m0, mx0), mn1 = fmaxf(m1, mx1);
        float al0 = __expf(m0 - mn0), al1 = __expf(m1 - mn1);
        m0 = mn0; m1 = mn1;

        float s0 = 0.f, s1 = 0.f;
#pragma unroll
        for (int nt = 0; nt < 8; nt++) {
#pragma unroll
            for (int e = 0; e < 2; e++) {
                S[nt][e] = __expf(S[nt][e] - mn0);         s0 += S[nt][e];
                S[nt][2 + e] = __expf(S[nt][2 + e] - mn1); s1 += S[nt][2 + e];
            }
        }
        s0 += __shfl_xor_sync(0xffffffffu, s0, 1);
        s0 += __shfl_xor_sync(0xffffffffu, s0, 2);
        s1 += __shfl_xor_sync(0xffffffffu, s1, 1);
        s1 += __shfl_xor_sync(0xffffffffu, s1, 2);
        l0 = l0 * al0 + s0;
        l1 = l1 * al1 + s1;

#pragma unroll
        for (int nt = 0; nt < 8; nt++) {
            Oacc[nt][0] *= al0; Oacc[nt][1] *= al0;
            Oacc[nt][2] *= al1; Oacc[nt][3] *= al1;
        }

#pragma unroll
        for (int ks = 0; ks < 4; ks++) {
            uint32_t Ph[4], Pl[4];
            pack_split(S[2 * ks][0],     S[2 * ks][1],     Ph[0], Pl[0]);
            pack_split(S[2 * ks][2],     S[2 * ks][3],     Ph[1], Pl[1]);
            pack_split(S[2 * ks + 1][0], S[2 * ks + 1][1], Ph[2], Pl[2]);
            pack_split(S[2 * ks + 1][2], S[2 * ks + 1][3], Ph[3], Pl[3]);

            uint32_t Vf[4][4], Vl4[4][4];
#pragma unroll
            for (int np = 0; np < 4; np++) {
                ldm_x4_t(Vf[np],  swa(smb + AVH(buf), (uint32_t)(ks * 16), (uint32_t)(np * 2)));
                ldm_x4_t(Vl4[np], swa(smb + AVL(buf), (uint32_t)(ks * 16), (uint32_t)(np * 2)));
            }
#pragma unroll
            for (int nt = 0; nt < 8; nt++) {
                uint32_t bh0 = Vf[nt >> 1][(nt & 1) * 2];
                uint32_t bh1 = Vf[nt >> 1][(nt & 1) * 2 + 1];
                mma16816(Oacc[nt], Ph, bh0, bh1);
                mma16816(Oacc[nt], Pl, bh0, bh1);
                uint32_t bl0 = Vl4[nt >> 1][(nt & 1) * 2];
                uint32_t bl1 = Vl4[nt >> 1][(nt & 1) * 2 + 1];
                mma16816(Oacc[nt], Ph, bl0, bl1);
            }
        }
    }

    float inv0 = 1.f / l0, inv1 = 1.f / l1;
#pragma unroll
    for (int nt = 0; nt < 8; nt++) {
        int c = nt * 8 + (l & 3) * 2;
        uint32_t hi, lo;
        if (qg0 < TT) {
            pack_split(Oacc[nt][0] * inv0, Oacc[nt][1] * inv0, hi, lo);
            size_t off = rb + (size_t)qg0 * CC + c;
            *reinterpret_cast<uint32_t*>(oh + off) = hi;
            *reinterpret_cast<uint32_t*>(ol + off) = lo;
        }
        if (qg1 < TT) {
            pack_split(Oacc[nt][2] * inv1, Oacc[nt][3] * inv1, hi, lo);
            size_t off = rb + (size_t)qg1 * CC + c;
            *reinterpret_cast<uint32_t*>(oh + off) = hi;
            *reinterpret_cast<uint32_t*>(ol + off) = lo;
        }
    }
}

// ---------------------------------------------------------------------------
// Launch
// ---------------------------------------------------------------------------
extern "C" void kernel_launch(void* const* d_in, const int* in_sizes, int n_in,
                              void* d_out, int out_size)
{
    const float* x_q  = (const float*)d_in[0];
    const float* x_kv = (const float*)d_in[1];
    const float* rope = (const float*)d_in[2];
    const float* Wq   = (const float*)d_in[3];
    const float* bq   = (const float*)d_in[4];
    const float* Wk   = (const float*)d_in[5];
    const float* bk   = (const float*)d_in[6];
    const float* Wv   = (const float*)d_in[7];
    const float* bv   = (const float*)d_in[8];
    const float* Wp   = (const float*)d_in[9];
    const float* bp   = (const float*)d_in[10];
    float* out = (float*)d_out;

    __nv_bfloat16 *xqh, *xql, *xkh, *xkl, *Wh, *Wl;
    __nv_bfloat16 *qh, *ql, *kh, *kl, *vh, *vl, *ah, *al;
    cudaGetSymbolAddress((void**)&xqh, g_xqh);
    cudaGetSymbolAddress((void**)&xql, g_xql);
    cudaGetSymbolAddress((void**)&xkh, g_xkh);
    cudaGetSymbolAddress((void**)&xkl, g_xkl);
    cudaGetSymbolAddress((void**)&Wh,  g_Wh);
    cudaGetSymbolAddress((void**)&Wl,  g_Wl);
    cudaGetSymbolAddress((void**)&qh,  g_qh);
    cudaGetSymbolAddress((void**)&ql,  g_ql);
    cudaGetSymbolAddress((void**)&kh,  g_kh);
    cudaGetSymbolAddress((void**)&kl,  g_kl);
    cudaGetSymbolAddress((void**)&vh,  g_vh);
    cudaGetSymbolAddress((void**)&vl,  g_vl);
    cudaGetSymbolAddress((void**)&ah,  g_ah);
    cudaGetSymbolAddress((void**)&al,  g_al);

    cudaFuncSetAttribute(gemm_tc_kernel,
        cudaFuncAttributeMaxDynamicSharedMemorySize, 2 * GBUF);
    cudaFuncSetAttribute(attn_tc_kernel,
        cudaFuncAttributeMaxDynamicSharedMemorySize, SMEM_ATTN);

    // 1) all six one-time splits in ONE launch
    const int NX4 = MROWS * CC / 4;
    const int NW4 = CC * CC / 4;
    dim3 split_grid((NX4 + 255) / 256, 6);
    split6_kernel<<<split_grid, 256>>>(
        x_q,  xqh, xql, NX4,
        x_kv, xkh, xkl, NX4,
        Wq, Wh,              Wl,              NW4,
        Wk, Wh + CC * CC,     Wl + CC * CC,     NW4,
        Wv, Wh + 2 * CC * CC, Wl + 2 * CC * CC, NW4,
        Wp, Wh + 3 * CC * CC, Wl + 3 * CC * CC, NW4);

    // 2) fused Q/K/V projections with rotary/scale/split epilogues
    dim3 g_qkv(CC / 128, (MROWS + 127) / 128, 3);   // (8, 49, 3)
    gemm_tc_kernel<<<g_qkv, 256, 2 * GBUF>>>(
        xqh, xql, Wh,              Wl,              bq, qh, ql, nullptr,
        xkh, xkl, Wh + CC * CC,     Wl + CC * CC,     bk, kh, kl,
        xkh, xkl, Wh + 2 * CC * CC, Wl + 2 * CC * CC, bv, vh, vl,
        rope, 1, MROWS);

    // 3) tensor-core attention (64-q tiles, 3 CTAs/SM) -> split output
    dim3 attn_grid((TT + 63) / 64, HH, BB);         // (13, 16, 8)
    attn_tc_kernel<<<attn_grid, 128, SMEM_ATTN>>>(qh, ql, kh, kl, vh, vl, ah, al);

    // 4) output projection, f32 epilogue
    dim3 g_out(CC / 128, (MROWS + 127) / 128, 1);
    gemm_tc_kernel<<<g_out, 256, 2 * GBUF>>>(
        ah, al, Wh + 3 * CC * CC, Wl + 3 * CC * CC, bp, nullptr, nullptr, out,
        ah, al, Wh + 3 * CC * CC, Wl + 3 * CC * CC, bp, nullptr, nullptr,
        ah, al, Wh + 3 * CC * CC, Wl + 3 * CC * CC, bp, nullptr, nullptr,
        rope, 0, MROWS);
}

// round 11
// speedup vs baseline: 1.2930x; 1.2163x over previous
#include <cuda_runtime.h>
#include <cuda_fp16.h>
#include <math.h>
#include <stdint.h>

#define BB 8
#define TT 769
#define CC 1024
#define HH 16
#define HD 64
#define LL 32
#define COND 256
#define MROWS (BB*TT)   // 6152

// ---------------------------------------------------------------------------
// Device scratch (allocation-free requirement -> globals)  [all fp16 now]
// ---------------------------------------------------------------------------
__device__ __half g_xqh[(size_t)MROWS * CC], g_xql[(size_t)MROWS * CC];
__device__ __half g_xkh[(size_t)MROWS * CC], g_xkl[(size_t)MROWS * CC];
__device__ __half g_Wh[(size_t)4 * CC * CC];          // W: hi only (2-term)
__device__ __half g_qh[(size_t)MROWS * CC], g_ql[(size_t)MROWS * CC];
__device__ __half g_kh[(size_t)MROWS * CC], g_kl[(size_t)MROWS * CC];
__device__ __half g_vh[(size_t)MROWS * CC], g_vl[(size_t)MROWS * CC];
__device__ __half g_ah[(size_t)MROWS * CC], g_al[(size_t)MROWS * CC];

// ---------------------------------------------------------------------------
// Helpers
// ---------------------------------------------------------------------------
__device__ __forceinline__ uint32_t smem_to_u32(const void* p) {
    uint32_t a;
    asm("{ .reg .u64 t; cvta.to.shared.u64 t, %1; cvt.u32.u64 %0, t; }"
        : "=r"(a) : "l"(p));
    return a;
}
__device__ __forceinline__ void ldm_x4(uint32_t* r, uint32_t addr) {
    asm volatile("ldmatrix.sync.aligned.m8n8.x4.shared.b16 {%0,%1,%2,%3}, [%4];"
        : "=r"(r[0]), "=r"(r[1]), "=r"(r[2]), "=r"(r[3]) : "r"(addr));
}
__device__ __forceinline__ void ldm_x4_t(uint32_t* r, uint32_t addr) {
    asm volatile("ldmatrix.sync.aligned.m8n8.x4.trans.shared.b16 {%0,%1,%2,%3}, [%4];"
        : "=r"(r[0]), "=r"(r[1]), "=r"(r[2]), "=r"(r[3]) : "r"(addr));
}
__device__ __forceinline__ void mma16816(float* d, const uint32_t* a,
                                         uint32_t b0, uint32_t b1) {
    asm("mma.sync.aligned.m16n8k16.row.col.f32.f16.f16.f32 "
        "{%0,%1,%2,%3}, {%4,%5,%6,%7}, {%8,%9}, {%0,%1,%2,%3};"
        : "+f"(d[0]), "+f"(d[1]), "+f"(d[2]), "+f"(d[3])
        : "r"(a[0]), "r"(a[1]), "r"(a[2]), "r"(a[3]), "r"(b0), "r"(b1));
}
__device__ __forceinline__ void cp16(uint32_t dst, const void* src, bool pred) {
    int n = pred ? 16 : 0;
    asm volatile("cp.async.cg.shared.global [%0], [%1], 16, %2;"
        :: "r"(dst), "l"(src), "r"(n) : "memory");
}
#define CP_COMMIT() asm volatile("cp.async.commit_group;" ::: "memory")
#define CP_WAIT0()  asm volatile("cp.async.wait_group 0;" ::: "memory")

// pack 2 floats -> half2 hi + half2 residual-lo
__device__ __forceinline__ void pack_split(float x, float y,
                                           uint32_t& hi, uint32_t& lo) {
    __half2 h = __floats2half2_rn(x, y);
    float hx = __low2float(h), hy = __high2float(h);
    __half2 l2 = __floats2half2_rn(x - hx, y - hy);
    hi = *reinterpret_cast<uint32_t*>(&h);
    lo = *reinterpret_cast<uint32_t*>(&l2);
}
__device__ __forceinline__ uint32_t pack_hi(float x, float y) {
    __half2 h = __floats2half2_rn(x, y);
    return *reinterpret_cast<uint32_t*>(&h);
}

// ---------------------------------------------------------------------------
// One launch for all 6 one-time splits. lo==nullptr -> hi-only (weights).
// ---------------------------------------------------------------------------
__global__ void split6_kernel(
    const float* __restrict__ s0, __half* __restrict__ h0, __half* __restrict__ l0, int n0,
    const float* __restrict__ s1, __half* __restrict__ h1, __half* __restrict__ l1, int n1,
    const float* __restrict__ s2, __half* __restrict__ h2, __half* __restrict__ l2, int n2,
    const float* __restrict__ s3, __half* __restrict__ h3, __half* __restrict__ l3, int n3,
    const float* __restrict__ s4, __half* __restrict__ h4, __half* __restrict__ l4, int n4,
    const float* __restrict__ s5, __half* __restrict__ h5, __half* __restrict__ l5, int n5)
{
    const float* src; __half *hi, *lo; int n;
    switch (blockIdx.y) {
        case 0: src = s0; hi = h0; lo = l0; n = n0; break;
        case 1: src = s1; hi = h1; lo = l1; n = n1; break;
        case 2: src = s2; hi = h2; lo = l2; n = n2; break;
        case 3: src = s3; hi = h3; lo = l3; n = n3; break;
        case 4: src = s4; hi = h4; lo = l4; n = n4; break;
        default: src = s5; hi = h5; lo = l5; n = n5; break;
    }
    int idx = blockIdx.x * blockDim.x + threadIdx.x;
    if (idx >= n) return;
    float4 v = reinterpret_cast<const float4*>(src)[idx];
    if (lo) {
        uint2 h, l;
        pack_split(v.x, v.y, h.x, l.x);
        pack_split(v.z, v.w, h.y, l.y);
        reinterpret_cast<uint2*>(hi)[idx] = h;
        reinterpret_cast<uint2*>(lo)[idx] = l;
    } else {
        uint2 h;
        h.x = pack_hi(v.x, v.y);
        h.y = pack_hi(v.z, v.w);
        reinterpret_cast<uint2*>(hi)[idx] = h;
    }
}

// ===========================================================================
// GEMM (fp16 2-term): Y = (Ah+Al) x Bh^T + bias. 128x128 tile, k-chunk 32,
// 2 CTAs/SM, cp.async double-buffered, one sync per chunk. Fused epilogues:
// mode 0 q (rotary+scale+split), 1 k (rotary+split), 2 v (split), 3 f32.
// ===========================================================================
#define RSB 80
#define GARR 10240
#define GBUF (3 * GARR)     // Ah | Al | Bh

__global__ void __launch_bounds__(256, 2) gemm_tc_kernel(
    const __half* __restrict__ A0h, const __half* __restrict__ A0l,
    const __half* __restrict__ B0, const float* __restrict__ b0,
    __half* __restrict__ O0h, __half* __restrict__ O0l, float* __restrict__ F0,
    const __half* __restrict__ A1h, const __half* __restrict__ A1l,
    const __half* __restrict__ B1, const float* __restrict__ b1,
    __half* __restrict__ O1h, __half* __restrict__ O1l,
    const __half* __restrict__ A2h, const __half* __restrict__ A2l,
    const __half* __restrict__ B2, const float* __restrict__ b2,
    __half* __restrict__ O2h, __half* __restrict__ O2l,
    const float* __restrict__ rope, int fused, int M)
{
    extern __shared__ char sm[];
    const uint32_t smb = smem_to_u32(sm);
    const int tid = threadIdx.x;
    const int lid = tid & 31;
    const int wid = tid >> 5;
    const int wm = wid >> 2, wn = wid & 3;

    const __half *Ah, *Al, *Bh;
    const float* Bi;
    __half *Oh, *Ol;
    if (blockIdx.z == 0)      { Ah=A0h; Al=A0l; Bh=B0; Bi=b0; Oh=O0h; Ol=O0l; }
    else if (blockIdx.z == 1) { Ah=A1h; Al=A1l; Bh=B1; Bi=b1; Oh=O1h; Ol=O1l; }
    else                      { Ah=A2h; Al=A2l; Bh=B2; Bi=b2; Oh=O2h; Ol=O2l; }
    const int mode = fused ? (int)blockIdx.z : 3;

    const int bm = blockIdx.y * 128, bn = blockIdx.x * 128;
    const uint32_t lmoff = (uint32_t)((lid & 15) * RSB + ((lid >> 4) << 4));

    const int r0 = tid >> 2, s0 = (tid & 3);
    const int r1 = (tid + 256) >> 2, s1 = ((tid + 256) & 3);

    float acc[4][4][4];
#pragma unroll
    for (int a = 0; a < 4; a++)
#pragma unroll
        for (int b = 0; b < 4; b++)
#pragma unroll
            for (int c = 0; c < 4; c++) acc[a][b][c] = 0.f;

    auto issue = [&](int ch, int buf) {
        uint32_t base = smb + buf * GBUF;
#pragma unroll
        for (int j = 0; j < 2; j++) {
            int row = j ? r1 : r0;
            int seg = j ? s1 : s0;
            uint32_t doff = (uint32_t)(row * RSB + seg * 16);
            bool ap = (bm + row) < M;
            size_t abyte = ((size_t)(bm + row) * CC + ch * 32) * 2 + seg * 16;
            size_t bbyte = ((size_t)(bn + row) * CC + ch * 32) * 2 + seg * 16;
            cp16(base + doff,            (const char*)Ah + abyte, ap);
            cp16(base + GARR + doff,     (const char*)Al + abyte, ap);
            cp16(base + 2 * GARR + doff, (const char*)Bh + bbyte, true);
        }
    };

    issue(0, 0);
    CP_COMMIT();

    for (int ch = 0; ch < 32; ch++) {
        CP_WAIT0();
        __syncthreads();
        if (ch < 31) { issue(ch + 1, (ch + 1) & 1); CP_COMMIT(); }

        const uint32_t base = smb + (ch & 1) * GBUF;
#pragma unroll
        for (int ks = 0; ks < 2; ks++) {
            const uint32_t kofs = (uint32_t)(ks * 32);
            uint32_t Af[4][4], Al4[4][4], Bf[2][4];
#pragma unroll
            for (int mt = 0; mt < 4; mt++) {
                uint32_t rb = (uint32_t)((wm * 64 + mt * 16) * RSB) + kofs + lmoff;
                ldm_x4(Af[mt],  base + rb);
                ldm_x4(Al4[mt], base + GARR + rb);
            }
#pragma unroll
            for (int np = 0; np < 2; np++) {
                uint32_t rb = (uint32_t)((wn * 32 + np * 16) * RSB) + kofs + lmoff;
                ldm_x4(Bf[np], base + 2 * GARR + rb);
            }
            // pass 1: Ah x Bh
#pragma unroll
            for (int mt = 0; mt < 4; mt++)
#pragma unroll
                for (int nt = 0; nt < 4; nt++) {
                    uint32_t bb0 = Bf[nt >> 1][nt & 1];
                    uint32_t bb1 = Bf[nt >> 1][2 + (nt & 1)];
                    mma16816(acc[mt][nt], Af[mt], bb0, bb1);
                }
            // pass 2: Al x Bh
#pragma unroll
            for (int mt = 0; mt < 4; mt++)
#pragma unroll
                for (int nt = 0; nt < 4; nt++) {
                    uint32_t bb0 = Bf[nt >> 1][nt & 1];
                    uint32_t bb1 = Bf[nt >> 1][2 + (nt & 1)];
                    mma16816(acc[mt][nt], Al4[mt], bb0, bb1);
                }
        }
    }

    const int rbase = bm + wm * 64 + (lid >> 2);
    const int cbase = bn + wn * 32 + (lid & 3) * 2;
#pragma unroll
    for (int mt = 0; mt < 4; mt++) {
#pragma unroll
        for (int nt = 0; nt < 4; nt++) {
            int c = cbase + nt * 8;
            float2 bv = *(const float2*)(Bi + c);
#pragma unroll
            for (int half = 0; half < 2; half++) {
                int rr = rbase + mt * 16 + half * 8;
                if (rr >= M) continue;
                float v0 = acc[mt][nt][half * 2 + 0] + bv.x;
                float v1 = acc[mt][nt][half * 2 + 1] + bv.y;
                if (mode == 3) {
                    *(float2*)(F0 + (size_t)rr * CC + c) = make_float2(v0, v1);
                    continue;
                }
                if (mode <= 1) {
                    int d = c & 63;
                    if (d < LL) {
                        int t = rr % TT;
                        float f0 = rope[t * LL + d], f1 = rope[t * LL + d + 1];
                        float c0 = cosf(f0), s0f = sinf(f0);
                        float c1 = cosf(f1), s1f = sinf(f1);
                        float a = v0, bq2 = v1;
                        v0 = a * c0 - bq2 * s0f;
                        v1 = bq2 * c1 + a * s1f;
                    }
                    if (mode == 0) { v0 *= 0.125f; v1 *= 0.125f; }
                }
                uint32_t h, l;
                pack_split(v0, v1, h, l);
                size_t off = (size_t)rr * CC + c;
                *reinterpret_cast<uint32_t*>(Oh + off) = h;
                *reinterpret_cast<uint32_t*>(Ol + off) = l;
            }
        }
    }
}

// ===========================================================================
// Tensor-core flash attention (fp16, 3-term). CTA = (64 q, h, b); 4 warps,
// XOR-swizzled smem 64 KB, 3 CTAs/SM. Q staged in buf1, then overwritten.
// ===========================================================================
#define ABUF(b)  ((b) * 32768)
#define AKH(b)   (ABUF(b) + 0)
#define AKL(b)   (ABUF(b) + 8192)
#define AVH(b)   (ABUF(b) + 16384)
#define AVL(b)   (ABUF(b) + 24576)
#define AQH      (ABUF(1) + 0)
#define AQL      (ABUF(1) + 8192)
#define SMEM_ATTN 65536

#define SWOFF(row, seg) ((uint32_t)((row) * 128 + ((((seg) ^ ((row) & 7))) << 4)))

__global__ void __launch_bounds__(128, 3) attn_tc_kernel(
    const __half* __restrict__ qh, const __half* __restrict__ ql,
    const __half* __restrict__ kh, const __half* __restrict__ kl,
    const __half* __restrict__ vh, const __half* __restrict__ vl,
    __half* __restrict__ oh, __half* __restrict__ ol)
{
    extern __shared__ char sm[];
    const uint32_t smb = smem_to_u32(sm);
    const int tid = threadIdx.x;
    const int l = tid & 31, w = tid >> 5;
    const int q0 = blockIdx.x * 64;
    const int h = blockIdx.y, b = blockIdx.z;
    const size_t rb = (size_t)b * TT * CC + (size_t)h * HD;

    const uint32_t lrow = (uint32_t)(l & 15) * 128;
    const uint32_t lhb = (uint32_t)(l >> 4);
    const uint32_t lx7 = (uint32_t)(l & 7);
    auto swa = [&](uint32_t base, uint32_t R, uint32_t cseg) {
        return base + R * 128 + lrow + ((((cseg | lhb)) ^ lx7) << 4);
    };

#pragma unroll
    for (int j = 0; j < 4; j++) {
        int slot = tid + j * 128;
        int row = slot >> 3, seg = slot & 7;
        bool p = (q0 + row) < TT;
        size_t byte = (rb + (size_t)(q0 + row) * CC) * 2 + seg * 16;
        uint32_t doff = SWOFF(row, seg);
        cp16(smb + AQH + doff, (const char*)qh + byte, p);
        cp16(smb + AQL + doff, (const char*)ql + byte, p);
    }
    CP_COMMIT();
    CP_WAIT0();
    __syncthreads();

    uint32_t Qf[4][4], Ql4[4][4];
#pragma unroll
    for (int ks = 0; ks < 4; ks++) {
        ldm_x4(Qf[ks],  swa(smb + AQH, (uint32_t)(w * 16), (uint32_t)(ks * 2)));
        ldm_x4(Ql4[ks], swa(smb + AQL, (uint32_t)(w * 16), (uint32_t)(ks * 2)));
    }
    __syncthreads();

    auto issue_kv = [&](int t, int buf) {
        int kv0 = t * 64;
#pragma unroll
        for (int j = 0; j < 4; j++) {
            int slot = tid + j * 128;
            int row = slot >> 3, seg = slot & 7;
            bool p = (kv0 + row) < TT;
            size_t byte = (rb + (size_t)(kv0 + row) * CC) * 2 + seg * 16;
            uint32_t doff = SWOFF(row, seg);
            cp16(smb + AKH(buf) + doff, (const char*)kh + byte, p);
            cp16(smb + AKL(buf) + doff, (const char*)kl + byte, p);
            cp16(smb + AVH(buf) + doff, (const char*)vh + byte, p);
            cp16(smb + AVL(buf) + doff, (const char*)vl + byte, p);
        }
    };

    issue_kv(0, 0);
    CP_COMMIT();

    int kv_end = q0 + COND + 63;
    if (kv_end > TT) kv_end = TT;
    const int nkv = (kv_end + 63) >> 6;

    const int qg0 = q0 + w * 16 + (l >> 2);
    const int qg1 = qg0 + 8;

    float Oacc[8][4];
#pragma unroll
    for (int i = 0; i < 8; i++)
#pragma unroll
        for (int j = 0; j < 4; j++) Oacc[i][j] = 0.f;
    float m0 = -1e30f, m1 = -1e30f, l0 = 0.f, l1 = 0.f;

    for (int t = 0; t < nkv; t++) {
        const int buf = t & 1;
        CP_WAIT0();
        __syncthreads();
        if (t + 1 < nkv) { issue_kv(t + 1, buf ^ 1); CP_COMMIT(); }

        const int kv0 = t * 64;
        float S[8][4];
#pragma unroll
        for (int i = 0; i < 8; i++)
#pragma unroll
            for (int j = 0; j < 4; j++) S[i][j] = 0.f;

#pragma unroll
        for (int ks = 0; ks < 4; ks++) {
            uint32_t Kf[4][4], Kl4[4][4];
#pragma unroll
            for (int np = 0; np < 4; np++) {
                ldm_x4(Kf[np],  swa(smb + AKH(buf), (uint32_t)(np * 16), (uint32_t)(ks * 2)));
                ldm_x4(Kl4[np], swa(smb + AKL(buf), (uint32_t)(np * 16), (uint32_t)(ks * 2)));
            }
#pragma unroll
            for (int nt = 0; nt < 8; nt++) {
                uint32_t bh0 = Kf[nt >> 1][nt & 1];
                uint32_t bh1 = Kf[nt >> 1][2 + (nt & 1)];
                mma16816(S[nt], Qf[ks], bh0, bh1);
                mma16816(S[nt], Ql4[ks], bh0, bh1);
                uint32_t bl0 = Kl4[nt >> 1][nt & 1];
                uint32_t bl1 = Kl4[nt >> 1][2 + (nt & 1)];
                mma16816(S[nt], Qf[ks], bl0, bl1);
            }
        }

        float mx0 = -1e30f, mx1 = -1e30f;
#pragma unroll
        for (int nt = 0; nt < 8; nt++) {
#pragma unroll
            for (int e = 0; e < 2; e++) {
                int kvc = kv0 + nt * 8 + (l & 3) * 2 + e;
                bool inb = kvc < TT;
                if (!(inb && kvc < COND + qg0)) S[nt][e] = -1e30f;
                if (!(inb && kvc < COND + qg1)) S[nt][2 + e] = -1e30f;
                mx0 = fmaxf(mx0, S[nt][e]);
                mx1 = fmaxf(mx1, S[nt][2 + e]);
            }
        }
        mx0 = fmaxf(mx0, __shfl_xor_sync(0xffffffffu, mx0, 1));
        mx0 = fmaxf(mx0, __shfl_xor_sync(0xffffffffu, mx0, 2));
        mx1 = fmaxf(mx1, __shfl_xor_sync(0xffffffffu, mx1, 1));
        mx1 = fmaxf(mx1, __shfl_xor_sync(0xffffffffu, mx1, 2));

        float mn0 = fmaxf(m0, mx0), mn1 = fmaxf(m1, mx1);
        float al0 = __expf(m0 - mn0), al1 = __expf(m1 - mn1);
        m0 = mn0; m1 = mn1;

        float s0 = 0.f, s1 = 0.f;
#pragma unroll
        for (int nt = 0; nt < 8; nt++) {
#pragma unroll
            for (int e = 0; e < 2; e++) {
                S[nt][e] = __expf(S[nt][e] - mn0);         s0 += S[nt][e];
                S[nt][2 + e] = __expf(S[nt][2 + e] - mn1); s1 += S[nt][2 + e];
            }
        }
        s0 += __shfl_xor_sync(0xffffffffu, s0, 1);
        s0 += __shfl_xor_sync(0xffffffffu, s0, 2);
        s1 += __shfl_xor_sync(0xffffffffu, s1, 1);
        s1 += __shfl_xor_sync(0xffffffffu, s1, 2);
        l0 = l0 * al0 + s0;
        l1 = l1 * al1 + s1;

#pragma unroll
        for (int nt = 0; nt < 8; nt++) {
            Oacc[nt][0] *= al0; Oacc[nt][1] *= al0;
            Oacc[nt][2] *= al1; Oacc[nt][3] *= al1;
        }

#pragma unroll
        for (int ks = 0; ks < 4; ks++) {
            uint32_t Ph[4], Pl[4];
            pack_split(S[2 * ks][0],     S[2 * ks][1],     Ph[0], Pl[0]);
            pack_split(S[2 * ks][2],     S[2 * ks][3],     Ph[1], Pl[1]);
            pack_split(S[2 * ks + 1][0], S[2 * ks + 1][1], Ph[2], Pl[2]);
            pack_split(S[2 * ks + 1][2], S[2 * ks + 1][3], Ph[3], Pl[3]);

            uint32_t Vf[4][4], Vl4[4][4];
#pragma unroll
            for (int np = 0; np < 4; np++) {
                ldm_x4_t(Vf[np],  swa(smb + AVH(buf), (uint32_t)(ks * 16), (uint32_t)(np * 2)));
                ldm_x4_t(Vl4[np], swa(smb + AVL(buf), (uint32_t)(ks * 16), (uint32_t)(np * 2)));
            }
#pragma unroll
            for (int nt = 0; nt < 8; nt++) {
                uint32_t bh0 = Vf[nt >> 1][(nt & 1) * 2];
                uint32_t bh1 = Vf[nt >> 1][(nt & 1) * 2 + 1];
                mma16816(Oacc[nt], Ph, bh0, bh1);
                mma16816(Oacc[nt], Pl, bh0, bh1);
                uint32_t bl0 = Vl4[nt >> 1][(nt & 1) * 2];
                uint32_t bl1 = Vl4[nt >> 1][(nt & 1) * 2 + 1];
                mma16816(Oacc[nt], Ph, bl0, bl1);
            }
        }
    }

    float inv0 = 1.f / l0, inv1 = 1.f / l1;
#pragma unroll
    for (int nt = 0; nt < 8; nt++) {
        int c = nt * 8 + (l & 3) * 2;
        uint32_t hi, lo;
        if (qg0 < TT) {
            pack_split(Oacc[nt][0] * inv0, Oacc[nt][1] * inv0, hi, lo);
            size_t off = rb + (size_t)qg0 * CC + c;
            *reinterpret_cast<uint32_t*>(oh + off) = hi;
            *reinterpret_cast<uint32_t*>(ol + off) = lo;
        }
        if (qg1 < TT) {
            pack_split(Oacc[nt][2] * inv1, Oacc[nt][3] * inv1, hi, lo);
            size_t off = rb + (size_t)qg1 * CC + c;
            *reinterpret_cast<uint32_t*>(oh + off) = hi;
            *reinterpret_cast<uint32_t*>(ol + off) = lo;
        }
    }
}

// ---------------------------------------------------------------------------
// Launch
// ---------------------------------------------------------------------------
extern "C" void kernel_launch(void* const* d_in, const int* in_sizes, int n_in,
                              void* d_out, int out_size)
{
    const float* x_q  = (const float*)d_in[0];
    const float* x_kv = (const float*)d_in[1];
    const float* rope = (const float*)d_in[2];
    const float* Wq   = (const float*)d_in[3];
    const float* bq   = (const float*)d_in[4];
    const float* Wk   = (const float*)d_in[5];
    const float* bk   = (const float*)d_in[6];
    const float* Wv   = (const float*)d_in[7];
    const float* bv   = (const float*)d_in[8];
    const float* Wp   = (const float*)d_in[9];
    const float* bp   = (const float*)d_in[10];
    float* out = (float*)d_out;

    __half *xqh, *xql, *xkh, *xkl, *Wh;
    __half *qh, *ql, *kh, *kl, *vh, *vl, *ah, *al;
    cudaGetSymbolAddress((void**)&xqh, g_xqh);
    cudaGetSymbolAddress((void**)&xql, g_xql);
    cudaGetSymbolAddress((void**)&xkh, g_xkh);
    cudaGetSymbolAddress((void**)&xkl, g_xkl);
    cudaGetSymbolAddress((void**)&Wh,  g_Wh);
    cudaGetSymbolAddress((void**)&qh,  g_qh);
    cudaGetSymbolAddress((void**)&ql,  g_ql);
    cudaGetSymbolAddress((void**)&kh,  g_kh);
    cudaGetSymbolAddress((void**)&kl,  g_kl);
    cudaGetSymbolAddress((void**)&vh,  g_vh);
    cudaGetSymbolAddress((void**)&vl,  g_vl);
    cudaGetSymbolAddress((void**)&ah,  g_ah);
    cudaGetSymbolAddress((void**)&al,  g_al);

    cudaFuncSetAttribute(gemm_tc_kernel,
        cudaFuncAttributeMaxDynamicSharedMemorySize, 2 * GBUF);
    cudaFuncSetAttribute(attn_tc_kernel,
        cudaFuncAttributeMaxDynamicSharedMemorySize, SMEM_ATTN);

    // 1) one-time splits: X hi/lo, W hi-only
    const int NX4 = MROWS * CC / 4;
    const int NW4 = CC * CC / 4;
    dim3 split_grid((NX4 + 255) / 256, 6);
    split6_kernel<<<split_grid, 256>>>(
        x_q,  xqh, xql, NX4,
        x_kv, xkh, xkl, NX4,
        Wq, Wh,              nullptr, NW4,
        Wk, Wh + CC * CC,     nullptr, NW4,
        Wv, Wh + 2 * CC * CC, nullptr, NW4,
        Wp, Wh + 3 * CC * CC, nullptr, NW4);

    // 2) fused Q/K/V projections with rotary/scale/split epilogues
    dim3 g_qkv(CC / 128, (MROWS + 127) / 128, 3);   // (8, 49, 3)
    gemm_tc_kernel<<<g_qkv, 256, 2 * GBUF>>>(
        xqh, xql, Wh,              bq, qh, ql, nullptr,
        xkh, xkl, Wh + CC * CC,     bk, kh, kl,
        xkh, xkl, Wh + 2 * CC * CC, bv, vh, vl,
        rope, 1, MROWS);

    // 3) tensor-core attention (64-q tiles, 3 CTAs/SM) -> split output
    dim3 attn_grid((TT + 63) / 64, HH, BB);         // (13, 16, 8)
    attn_tc_kernel<<<attn_grid, 128, SMEM_ATTN>>>(qh, ql, kh, kl, vh, vl, ah, al);

    // 4) output projection, f32 epilogue
    dim3 g_out(CC / 128, (MROWS + 127) / 128, 1);
    gemm_tc_kernel<<<g_out, 256, 2 * GBUF>>>(
        ah, al, Wh + 3 * CC * CC, bp, nullptr, nullptr, out,
        ah, al, Wh + 3 * CC * CC, bp, nullptr, nullptr,
        ah, al, Wh + 3 * CC * CC, bp, nullptr, nullptr,
        rope, 0, MROWS);
}

// round 12
// speedup vs baseline: 1.3655x; 1.0561x over previous
#include <cuda_runtime.h>
#include <cuda_fp16.h>
#include <math.h>
#include <stdint.h>

#define BB 8
#define TT 769
#define CC 1024
#define HH 16
#define HD 64
#define LL 32
#define COND 256
#define MROWS (BB*TT)   // 6152

// ---------------------------------------------------------------------------
// Device scratch (allocation-free requirement -> globals)  [fp16]
// ---------------------------------------------------------------------------
__device__ __half g_xqh[(size_t)MROWS * CC], g_xql[(size_t)MROWS * CC];
__device__ __half g_xkh[(size_t)MROWS * CC], g_xkl[(size_t)MROWS * CC];
__device__ __half g_Wh[(size_t)4 * CC * CC];          // W: hi only
__device__ __half g_qh[(size_t)MROWS * CC], g_ql[(size_t)MROWS * CC];
__device__ __half g_kh[(size_t)MROWS * CC];           // K: hi only
__device__ __half g_vh[(size_t)MROWS * CC];           // V: hi only
__device__ __half g_ah[(size_t)MROWS * CC], g_al[(size_t)MROWS * CC];

// ---------------------------------------------------------------------------
// Helpers
// ---------------------------------------------------------------------------
__device__ __forceinline__ uint32_t smem_to_u32(const void* p) {
    uint32_t a;
    asm("{ .reg .u64 t; cvta.to.shared.u64 t, %1; cvt.u32.u64 %0, t; }"
        : "=r"(a) : "l"(p));
    return a;
}
__device__ __forceinline__ void ldm_x4(uint32_t* r, uint32_t addr) {
    asm volatile("ldmatrix.sync.aligned.m8n8.x4.shared.b16 {%0,%1,%2,%3}, [%4];"
        : "=r"(r[0]), "=r"(r[1]), "=r"(r[2]), "=r"(r[3]) : "r"(addr));
}
__device__ __forceinline__ void ldm_x4_t(uint32_t* r, uint32_t addr) {
    asm volatile("ldmatrix.sync.aligned.m8n8.x4.trans.shared.b16 {%0,%1,%2,%3}, [%4];"
        : "=r"(r[0]), "=r"(r[1]), "=r"(r[2]), "=r"(r[3]) : "r"(addr));
}
__device__ __forceinline__ void mma16816(float* d, const uint32_t* a,
                                         uint32_t b0, uint32_t b1) {
    asm("mma.sync.aligned.m16n8k16.row.col.f32.f16.f16.f32 "
        "{%0,%1,%2,%3}, {%4,%5,%6,%7}, {%8,%9}, {%0,%1,%2,%3};"
        : "+f"(d[0]), "+f"(d[1]), "+f"(d[2]), "+f"(d[3])
        : "r"(a[0]), "r"(a[1]), "r"(a[2]), "r"(a[3]), "r"(b0), "r"(b1));
}
__device__ __forceinline__ void cp16(uint32_t dst, const void* src, bool pred) {
    int n = pred ? 16 : 0;
    asm volatile("cp.async.cg.shared.global [%0], [%1], 16, %2;"
        :: "r"(dst), "l"(src), "r"(n) : "memory");
}
#define CP_COMMIT() asm volatile("cp.async.commit_group;" ::: "memory")
#define CP_WAIT0()  asm volatile("cp.async.wait_group 0;" ::: "memory")

// pack 2 floats -> half2 hi + half2 residual-lo
__device__ __forceinline__ void pack_split(float x, float y,
                                           uint32_t& hi, uint32_t& lo) {
    __half2 h = __floats2half2_rn(x, y);
    float hx = __low2float(h), hy = __high2float(h);
    __half2 l2 = __floats2half2_rn(x - hx, y - hy);
    hi = *reinterpret_cast<uint32_t*>(&h);
    lo = *reinterpret_cast<uint32_t*>(&l2);
}
__device__ __forceinline__ uint32_t pack_hi(float x, float y) {
    __half2 h = __floats2half2_rn(x, y);
    return *reinterpret_cast<uint32_t*>(&h);
}

// ---------------------------------------------------------------------------
// One launch for all 6 one-time splits. lo==nullptr -> hi-only (weights).
// ---------------------------------------------------------------------------
__global__ void split6_kernel(
    const float* __restrict__ s0, __half* __restrict__ h0, __half* __restrict__ l0, int n0,
    const float* __restrict__ s1, __half* __restrict__ h1, __half* __restrict__ l1, int n1,
    const float* __restrict__ s2, __half* __restrict__ h2, __half* __restrict__ l2, int n2,
    const float* __restrict__ s3, __half* __restrict__ h3, __half* __restrict__ l3, int n3,
    const float* __restrict__ s4, __half* __restrict__ h4, __half* __restrict__ l4, int n4,
    const float* __restrict__ s5, __half* __restrict__ h5, __half* __restrict__ l5, int n5)
{
    const float* src; __half *hi, *lo; int n;
    switch (blockIdx.y) {
        case 0: src = s0; hi = h0; lo = l0; n = n0; break;
        case 1: src = s1; hi = h1; lo = l1; n = n1; break;
        case 2: src = s2; hi = h2; lo = l2; n = n2; break;
        case 3: src = s3; hi = h3; lo = l3; n = n3; break;
        case 4: src = s4; hi = h4; lo = l4; n = n4; break;
        default: src = s5; hi = h5; lo = l5; n = n5; break;
    }
    int idx = blockIdx.x * blockDim.x + threadIdx.x;
    if (idx >= n) return;
    float4 v = reinterpret_cast<const float4*>(src)[idx];
    if (lo) {
        uint2 h, l;
        pack_split(v.x, v.y, h.x, l.x);
        pack_split(v.z, v.w, h.y, l.y);
        reinterpret_cast<uint2*>(hi)[idx] = h;
        reinterpret_cast<uint2*>(lo)[idx] = l;
    } else {
        uint2 h;
        h.x = pack_hi(v.x, v.y);
        h.y = pack_hi(v.z, v.w);
        reinterpret_cast<uint2*>(hi)[idx] = h;
    }
}

// ===========================================================================
// GEMM (fp16 2-term): Y = (Ah+Al) x Bh^T + bias. 128x128 tile, k-chunk 32,
// 2 CTAs/SM, cp.async double-buffered, one sync per chunk. Fused epilogues:
// mode 0 q (rotary+scale+split), 1 k (rotary, hi-only), 2 v (hi-only),
// 3 f32. Ol==nullptr skips the lo store.
// ===========================================================================
#define RSB 80
#define GARR 10240
#define GBUF (3 * GARR)     // Ah | Al | Bh

__global__ void __launch_bounds__(256, 2) gemm_tc_kernel(
    const __half* __restrict__ A0h, const __half* __restrict__ A0l,
    const __half* __restrict__ B0, const float* __restrict__ b0,
    __half* __restrict__ O0h, __half* __restrict__ O0l, float* __restrict__ F0,
    const __half* __restrict__ A1h, const __half* __restrict__ A1l,
    const __half* __restrict__ B1, const float* __restrict__ b1,
    __half* __restrict__ O1h, __half* __restrict__ O1l,
    const __half* __restrict__ A2h, const __half* __restrict__ A2l,
    const __half* __restrict__ B2, const float* __restrict__ b2,
    __half* __restrict__ O2h, __half* __restrict__ O2l,
    const float* __restrict__ rope, int fused, int M)
{
    extern __shared__ char sm[];
    const uint32_t smb = smem_to_u32(sm);
    const int tid = threadIdx.x;
    const int lid = tid & 31;
    const int wid = tid >> 5;
    const int wm = wid >> 2, wn = wid & 3;

    const __half *Ah, *Al, *Bh;
    const float* Bi;
    __half *Oh, *Ol;
    if (blockIdx.z == 0)      { Ah=A0h; Al=A0l; Bh=B0; Bi=b0; Oh=O0h; Ol=O0l; }
    else if (blockIdx.z == 1) { Ah=A1h; Al=A1l; Bh=B1; Bi=b1; Oh=O1h; Ol=O1l; }
    else                      { Ah=A2h; Al=A2l; Bh=B2; Bi=b2; Oh=O2h; Ol=O2l; }
    const int mode = fused ? (int)blockIdx.z : 3;

    const int bm = blockIdx.y * 128, bn = blockIdx.x * 128;
    const uint32_t lmoff = (uint32_t)((lid & 15) * RSB + ((lid >> 4) << 4));

    const int r0 = tid >> 2, s0 = (tid & 3);
    const int r1 = (tid + 256) >> 2, s1 = ((tid + 256) & 3);

    float acc[4][4][4];
#pragma unroll
    for (int a = 0; a < 4; a++)
#pragma unroll
        for (int b = 0; b < 4; b++)
#pragma unroll
            for (int c = 0; c < 4; c++) acc[a][b][c] = 0.f;

    auto issue = [&](int ch, int buf) {
        uint32_t base = smb + buf * GBUF;
#pragma unroll
        for (int j = 0; j < 2; j++) {
            int row = j ? r1 : r0;
            int seg = j ? s1 : s0;
            uint32_t doff = (uint32_t)(row * RSB + seg * 16);
            bool ap = (bm + row) < M;
            size_t abyte = ((size_t)(bm + row) * CC + ch * 32) * 2 + seg * 16;
            size_t bbyte = ((size_t)(bn + row) * CC + ch * 32) * 2 + seg * 16;
            cp16(base + doff,            (const char*)Ah + abyte, ap);
            cp16(base + GARR + doff,     (const char*)Al + abyte, ap);
            cp16(base + 2 * GARR + doff, (const char*)Bh + bbyte, true);
        }
    };

    issue(0, 0);
    CP_COMMIT();

    for (int ch = 0; ch < 32; ch++) {
        CP_WAIT0();
        __syncthreads();
        if (ch < 31) { issue(ch + 1, (ch + 1) & 1); CP_COMMIT(); }

        const uint32_t base = smb + (ch & 1) * GBUF;
#pragma unroll
        for (int ks = 0; ks < 2; ks++) {
            const uint32_t kofs = (uint32_t)(ks * 32);
            uint32_t Af[4][4], Al4[4][4], Bf[2][4];
#pragma unroll
            for (int mt = 0; mt < 4; mt++) {
                uint32_t rb = (uint32_t)((wm * 64 + mt * 16) * RSB) + kofs + lmoff;
                ldm_x4(Af[mt],  base + rb);
                ldm_x4(Al4[mt], base + GARR + rb);
            }
#pragma unroll
            for (int np = 0; np < 2; np++) {
                uint32_t rb = (uint32_t)((wn * 32 + np * 16) * RSB) + kofs + lmoff;
                ldm_x4(Bf[np], base + 2 * GARR + rb);
            }
#pragma unroll
            for (int mt = 0; mt < 4; mt++)
#pragma unroll
                for (int nt = 0; nt < 4; nt++) {
                    uint32_t bb0 = Bf[nt >> 1][nt & 1];
                    uint32_t bb1 = Bf[nt >> 1][2 + (nt & 1)];
                    mma16816(acc[mt][nt], Af[mt], bb0, bb1);
                }
#pragma unroll
            for (int mt = 0; mt < 4; mt++)
#pragma unroll
                for (int nt = 0; nt < 4; nt++) {
                    uint32_t bb0 = Bf[nt >> 1][nt & 1];
                    uint32_t bb1 = Bf[nt >> 1][2 + (nt & 1)];
                    mma16816(acc[mt][nt], Al4[mt], bb0, bb1);
                }
        }
    }

    const int rbase = bm + wm * 64 + (lid >> 2);
    const int cbase = bn + wn * 32 + (lid & 3) * 2;
#pragma unroll
    for (int mt = 0; mt < 4; mt++) {
#pragma unroll
        for (int nt = 0; nt < 4; nt++) {
            int c = cbase + nt * 8;
            float2 bv = *(const float2*)(Bi + c);
#pragma unroll
            for (int half = 0; half < 2; half++) {
                int rr = rbase + mt * 16 + half * 8;
                if (rr >= M) continue;
                float v0 = acc[mt][nt][half * 2 + 0] + bv.x;
                float v1 = acc[mt][nt][half * 2 + 1] + bv.y;
                if (mode == 3) {
                    *(float2*)(F0 + (size_t)rr * CC + c) = make_float2(v0, v1);
                    continue;
                }
                if (mode <= 1) {
                    int d = c & 63;
                    if (d < LL) {
                        int t = rr % TT;
                        float f0 = rope[t * LL + d], f1 = rope[t * LL + d + 1];
                        float c0 = cosf(f0), s0f = sinf(f0);
                        float c1 = cosf(f1), s1f = sinf(f1);
                        float a = v0, bq2 = v1;
                        v0 = a * c0 - bq2 * s0f;
                        v1 = bq2 * c1 + a * s1f;
                    }
                    if (mode == 0) { v0 *= 0.125f; v1 *= 0.125f; }
                }
                size_t off = (size_t)rr * CC + c;
                if (Ol) {
                    uint32_t h, l;
                    pack_split(v0, v1, h, l);
                    *reinterpret_cast<uint32_t*>(Oh + off) = h;
                    *reinterpret_cast<uint32_t*>(Ol + off) = l;
                } else {
                    *reinterpret_cast<uint32_t*>(Oh + off) = pack_hi(v0, v1);
                }
            }
        }
    }
}

// ===========================================================================
// Tensor-core flash attention (fp16, 2-term): S=(Qh+Ql)·Kh, O=(Ph+Pl)·Vh.
// CTA = (64 q, h, b); 4 warps, XOR-swizzled smem 32 KB -> 4 CTAs/SM.
// Q staged in buf1 and overwritten by kv tile 1.
// ===========================================================================
#define ABUF(b)  ((b) * 16384)
#define AKH(b)   (ABUF(b) + 0)
#define AVH(b)   (ABUF(b) + 8192)
#define AQH      (ABUF(1) + 0)
#define AQL      (ABUF(1) + 8192)
#define SMEM_ATTN 32768

#define SWOFF(row, seg) ((uint32_t)((row) * 128 + ((((seg) ^ ((row) & 7))) << 4)))

__global__ void __launch_bounds__(128, 4) attn_tc_kernel(
    const __half* __restrict__ qh, const __half* __restrict__ ql,
    const __half* __restrict__ kh, const __half* __restrict__ vh,
    __half* __restrict__ oh, __half* __restrict__ ol)
{
    extern __shared__ char sm[];
    const uint32_t smb = smem_to_u32(sm);
    const int tid = threadIdx.x;
    const int l = tid & 31, w = tid >> 5;
    const int q0 = blockIdx.x * 64;
    const int h = blockIdx.y, b = blockIdx.z;
    const size_t rb = (size_t)b * TT * CC + (size_t)h * HD;

    const uint32_t lrow = (uint32_t)(l & 15) * 128;
    const uint32_t lhb = (uint32_t)(l >> 4);
    const uint32_t lx7 = (uint32_t)(l & 7);
    auto swa = [&](uint32_t base, uint32_t R, uint32_t cseg) {
        return base + R * 128 + lrow + ((((cseg | lhb)) ^ lx7) << 4);
    };

    // ---- stage Q (hi+lo) in buf1, read frags, then release ----
#pragma unroll
    for (int j = 0; j < 4; j++) {
        int slot = tid + j * 128;          // 512 slots = 64 rows x 8 segs
        int row = slot >> 3, seg = slot & 7;
        bool p = (q0 + row) < TT;
        size_t byte = (rb + (size_t)(q0 + row) * CC) * 2 + seg * 16;
        uint32_t doff = SWOFF(row, seg);
        cp16(smb + AQH + doff, (const char*)qh + byte, p);
        cp16(smb + AQL + doff, (const char*)ql + byte, p);
    }
    CP_COMMIT();
    CP_WAIT0();
    __syncthreads();

    uint32_t Qf[4][4], Ql4[4][4];
#pragma unroll
    for (int ks = 0; ks < 4; ks++) {
        ldm_x4(Qf[ks],  swa(smb + AQH, (uint32_t)(w * 16), (uint32_t)(ks * 2)));
        ldm_x4(Ql4[ks], swa(smb + AQL, (uint32_t)(w * 16), (uint32_t)(ks * 2)));
    }
    __syncthreads();

    auto issue_kv = [&](int t, int buf) {
        int kv0 = t * 64;
#pragma unroll
        for (int j = 0; j < 4; j++) {
            int slot = tid + j * 128;
            int row = slot >> 3, seg = slot & 7;
            bool p = (kv0 + row) < TT;
            size_t byte = (rb + (size_t)(kv0 + row) * CC) * 2 + seg * 16;
            uint32_t doff = SWOFF(row, seg);
            cp16(smb + AKH(buf) + doff, (const char*)kh + byte, p);
            cp16(smb + AVH(buf) + doff, (const char*)vh + byte, p);
        }
    };

    issue_kv(0, 0);
    CP_COMMIT();

    int kv_end = q0 + COND + 63;
    if (kv_end > TT) kv_end = TT;
    const int nkv = (kv_end + 63) >> 6;    // >= 4 always

    const int qg0 = q0 + w * 16 + (l >> 2);
    const int qg1 = qg0 + 8;

    float Oacc[8][4];
#pragma unroll
    for (int i = 0; i < 8; i++)
#pragma unroll
        for (int j = 0; j < 4; j++) Oacc[i][j] = 0.f;
    float m0 = -1e30f, m1 = -1e30f, l0 = 0.f, l1 = 0.f;

    for (int t = 0; t < nkv; t++) {
        const int buf = t & 1;
        CP_WAIT0();
        __syncthreads();
        if (t + 1 < nkv) { issue_kv(t + 1, buf ^ 1); CP_COMMIT(); }

        const int kv0 = t * 64;
        float S[8][4];
#pragma unroll
        for (int i = 0; i < 8; i++)
#pragma unroll
            for (int j = 0; j < 4; j++) S[i][j] = 0.f;

#pragma unroll
        for (int ks = 0; ks < 4; ks++) {
            uint32_t Kf[4][4];
#pragma unroll
            for (int np = 0; np < 4; np++)
                ldm_x4(Kf[np], swa(smb + AKH(buf), (uint32_t)(np * 16), (uint32_t)(ks * 2)));
#pragma unroll
            for (int nt = 0; nt < 8; nt++) {
                uint32_t bh0 = Kf[nt >> 1][nt & 1];
                uint32_t bh1 = Kf[nt >> 1][2 + (nt & 1)];
                mma16816(S[nt], Qf[ks], bh0, bh1);
            }
#pragma unroll
            for (int nt = 0; nt < 8; nt++) {
                uint32_t bh0 = Kf[nt >> 1][nt & 1];
                uint32_t bh1 = Kf[nt >> 1][2 + (nt & 1)];
                mma16816(S[nt], Ql4[ks], bh0, bh1);
            }
        }

        float mx0 = -1e30f, mx1 = -1e30f;
#pragma unroll
        for (int nt = 0; nt < 8; nt++) {
#pragma unroll
            for (int e = 0; e < 2; e++) {
                int kvc = kv0 + nt * 8 + (l & 3) * 2 + e;
                bool inb = kvc < TT;
                if (!(inb && kvc < COND + qg0)) S[nt][e] = -1e30f;
                if (!(inb && kvc < COND + qg1)) S[nt][2 + e] = -1e30f;
                mx0 = fmaxf(mx0, S[nt][e]);
                mx1 = fmaxf(mx1, S[nt][2 + e]);
            }
        }
        mx0 = fmaxf(mx0, __shfl_xor_sync(0xffffffffu, mx0, 1));
        mx0 = fmaxf(mx0, __shfl_xor_sync(0xffffffffu, mx0, 2));
        mx1 = fmaxf(mx1, __shfl_xor_sync(0xffffffffu, mx1, 1));
        mx1 = fmaxf(mx1, __shfl_xor_sync(0xffffffffu, mx1, 2));

        float mn0 = fmaxf(m0, mx0), mn1 = fmaxf(m1, mx1);
        float al0 = __expf(m0 - mn0), al1 = __expf(m1 - mn1);
        m0 = mn0; m1 = mn1;

        float s0 = 0.f, s1 = 0.f;
#pragma unroll
        for (int nt = 0; nt < 8; nt++) {
#pragma unroll
            for (int e = 0; e < 2; e++) {
                S[nt][e] = __expf(S[nt][e] - mn0);         s0 += S[nt][e];
                S[nt][2 + e] = __expf(S[nt][2 + e] - mn1); s1 += S[nt][2 + e];
            }
        }
        s0 += __shfl_xor_sync(0xffffffffu, s0, 1);
        s0 += __shfl_xor_sync(0xffffffffu, s0, 2);
        s1 += __shfl_xor_sync(0xffffffffu, s1, 1);
        s1 += __shfl_xor_sync(0xffffffffu, s1, 2);
        l0 = l0 * al0 + s0;
        l1 = l1 * al1 + s1;

#pragma unroll
        for (int nt = 0; nt < 8; nt++) {
            Oacc[nt][0] *= al0; Oacc[nt][1] *= al0;
            Oacc[nt][2] *= al1; Oacc[nt][3] *= al1;
        }

#pragma unroll
        for (int ks = 0; ks < 4; ks++) {
            uint32_t Ph[4], Pl[4];
            pack_split(S[2 * ks][0],     S[2 * ks][1],     Ph[0], Pl[0]);
            pack_split(S[2 * ks][2],     S[2 * ks][3],     Ph[1], Pl[1]);
            pack_split(S[2 * ks + 1][0], S[2 * ks + 1][1], Ph[2], Pl[2]);
            pack_split(S[2 * ks + 1][2], S[2 * ks + 1][3], Ph[3], Pl[3]);

            uint32_t Vf[4][4];
#pragma unroll
            for (int np = 0; np < 4; np++)
                ldm_x4_t(Vf[np], swa(smb + AVH(buf), (uint32_t)(ks * 16), (uint32_t)(np * 2)));
#pragma unroll
            for (int nt = 0; nt < 8; nt++) {
                uint32_t bh0 = Vf[nt >> 1][(nt & 1) * 2];
                uint32_t bh1 = Vf[nt >> 1][(nt & 1) * 2 + 1];
                mma16816(Oacc[nt], Ph, bh0, bh1);
            }
#pragma unroll
            for (int nt = 0; nt < 8; nt++) {
                uint32_t bh0 = Vf[nt >> 1][(nt & 1) * 2];
                uint32_t bh1 = Vf[nt >> 1][(nt & 1) * 2 + 1];
                mma16816(Oacc[nt], Pl, bh0, bh1);
            }
        }
    }

    float inv0 = 1.f / l0, inv1 = 1.f / l1;
#pragma unroll
    for (int nt = 0; nt < 8; nt++) {
        int c = nt * 8 + (l & 3) * 2;
        uint32_t hi, lo;
        if (qg0 < TT) {
            pack_split(Oacc[nt][0] * inv0, Oacc[nt][1] * inv0, hi, lo);
            size_t off = rb + (size_t)qg0 * CC + c;
            *reinterpret_cast<uint32_t*>(oh + off) = hi;
            *reinterpret_cast<uint32_t*>(ol + off) = lo;
        }
        if (qg1 < TT) {
            pack_split(Oacc[nt][2] * inv1, Oacc[nt][3] * inv1, hi, lo);
            size_t off = rb + (size_t)qg1 * CC + c;
            *reinterpret_cast<uint32_t*>(oh + off) = hi;
            *reinterpret_cast<uint32_t*>(ol + off) = lo;
        }
    }
}

// ---------------------------------------------------------------------------
// Launch
// ---------------------------------------------------------------------------
extern "C" void kernel_launch(void* const* d_in, const int* in_sizes, int n_in,
                              void* d_out, int out_size)
{
    const float* x_q  = (const float*)d_in[0];
    const float* x_kv = (const float*)d_in[1];
    const float* rope = (const float*)d_in[2];
    const float* Wq   = (const float*)d_in[3];
    const float* bq   = (const float*)d_in[4];
    const float* Wk   = (const float*)d_in[5];
    const float* bk   = (const float*)d_in[6];
    const float* Wv   = (const float*)d_in[7];
    const float* bv   = (const float*)d_in[8];
    const float* Wp   = (const float*)d_in[9];
    const float* bp   = (const float*)d_in[10];
    float* out = (float*)d_out;

    __half *xqh, *xql, *xkh, *xkl, *Wh;
    __half *qh, *ql, *kh, *vh, *ah, *al;
    cudaGetSymbolAddress((void**)&xqh, g_xqh);
    cudaGetSymbolAddress((void**)&xql, g_xql);
    cudaGetSymbolAddress((void**)&xkh, g_xkh);
    cudaGetSymbolAddress((void**)&xkl, g_xkl);
    cudaGetSymbolAddress((void**)&Wh,  g_Wh);
    cudaGetSymbolAddress((void**)&qh,  g_qh);
    cudaGetSymbolAddress((void**)&ql,  g_ql);
    cudaGetSymbolAddress((void**)&kh,  g_kh);
    cudaGetSymbolAddress((void**)&vh,  g_vh);
    cudaGetSymbolAddress((void**)&ah,  g_ah);
    cudaGetSymbolAddress((void**)&al,  g_al);

    cudaFuncSetAttribute(gemm_tc_kernel,
        cudaFuncAttributeMaxDynamicSharedMemorySize, 2 * GBUF);
    cudaFuncSetAttribute(attn_tc_kernel,
        cudaFuncAttributeMaxDynamicSharedMemorySize, SMEM_ATTN);

    // 1) one-time splits: X hi/lo, W hi-only
    const int NX4 = MROWS * CC / 4;
    const int NW4 = CC * CC / 4;
    dim3 split_grid((NX4 + 255) / 256, 6);
    split6_kernel<<<split_grid, 256>>>(
        x_q,  xqh, xql, NX4,
        x_kv, xkh, xkl, NX4,
        Wq, Wh,              nullptr, NW4,
        Wk, Wh + CC * CC,     nullptr, NW4,
        Wv, Wh + 2 * CC * CC, nullptr, NW4,
        Wp, Wh + 3 * CC * CC, nullptr, NW4);

    // 2) fused Q/K/V projections; q split, k/v hi-only
    dim3 g_qkv(CC / 128, (MROWS + 127) / 128, 3);   // (8, 49, 3)
    gemm_tc_kernel<<<g_qkv, 256, 2 * GBUF>>>(
        xqh, xql, Wh,              bq, qh, ql, nullptr,
        xkh, xkl, Wh + CC * CC,     bk, kh, nullptr,
        xkh, xkl, Wh + 2 * CC * CC, bv, vh, nullptr,
        rope, 1, MROWS);

    // 3) tensor-core attention (2-term, 4 CTAs/SM) -> split output
    dim3 attn_grid((TT + 63) / 64, HH, BB);         // (13, 16, 8)
    attn_tc_kernel<<<attn_grid, 128, SMEM_ATTN>>>(qh, ql, kh, vh, ah, al);

    // 4) output projection, f32 epilogue
    dim3 g_out(CC / 128, (MROWS + 127) / 128, 1);
    gemm_tc_kernel<<<g_out, 256, 2 * GBUF>>>(
        ah, al, Wh + 3 * CC * CC, bp, nullptr, nullptr, out,
        ah, al, Wh + 3 * CC * CC, bp, nullptr, nullptr,
        ah, al, Wh + 3 * CC * CC, bp, nullptr, nullptr,
        rope, 0, MROWS);
}

// round 13
// speedup vs baseline: 1.5789x; 1.1563x over previous
#include <cuda_runtime.h>
#include <cuda_fp16.h>
#include <math.h>
#include <stdint.h>

#define BB 8
#define TT 769
#define CC 1024
#define HH 16
#define HD 64
#define LL 32
#define COND 256
#define MROWS (BB*TT)   // 6152

// ---------------------------------------------------------------------------
// Device scratch (allocation-free requirement -> globals)  [fp16]
// ---------------------------------------------------------------------------
__device__ __half g_xqh[(size_t)MROWS * CC], g_xql[(size_t)MROWS * CC];
__device__ __half g_xkh[(size_t)MROWS * CC];          // x_kv: hi only now
__device__ __half g_Wh[(size_t)4 * CC * CC];          // W: hi only
__device__ __half g_qh[(size_t)MROWS * CC], g_ql[(size_t)MROWS * CC];
__device__ __half g_kh[(size_t)MROWS * CC];           // K: hi only
__device__ __half g_vh[(size_t)MROWS * CC];           // V: hi only
__device__ __half g_ah[(size_t)MROWS * CC];           // attn out: hi only

// ---------------------------------------------------------------------------
// Helpers
// ---------------------------------------------------------------------------
__device__ __forceinline__ uint32_t smem_to_u32(const void* p) {
    uint32_t a;
    asm("{ .reg .u64 t; cvta.to.shared.u64 t, %1; cvt.u32.u64 %0, t; }"
        : "=r"(a) : "l"(p));
    return a;
}
__device__ __forceinline__ void ldm_x4(uint32_t* r, uint32_t addr) {
    asm volatile("ldmatrix.sync.aligned.m8n8.x4.shared.b16 {%0,%1,%2,%3}, [%4];"
        : "=r"(r[0]), "=r"(r[1]), "=r"(r[2]), "=r"(r[3]) : "r"(addr));
}
__device__ __forceinline__ void ldm_x4_t(uint32_t* r, uint32_t addr) {
    asm volatile("ldmatrix.sync.aligned.m8n8.x4.trans.shared.b16 {%0,%1,%2,%3}, [%4];"
        : "=r"(r[0]), "=r"(r[1]), "=r"(r[2]), "=r"(r[3]) : "r"(addr));
}
__device__ __forceinline__ void mma16816(float* d, const uint32_t* a,
                                         uint32_t b0, uint32_t b1) {
    asm("mma.sync.aligned.m16n8k16.row.col.f32.f16.f16.f32 "
        "{%0,%1,%2,%3}, {%4,%5,%6,%7}, {%8,%9}, {%0,%1,%2,%3};"
        : "+f"(d[0]), "+f"(d[1]), "+f"(d[2]), "+f"(d[3])
        : "r"(a[0]), "r"(a[1]), "r"(a[2]), "r"(a[3]), "r"(b0), "r"(b1));
}
__device__ __forceinline__ void cp16(uint32_t dst, const void* src, bool pred) {
    int n = pred ? 16 : 0;
    asm volatile("cp.async.cg.shared.global [%0], [%1], 16, %2;"
        :: "r"(dst), "l"(src), "r"(n) : "memory");
}
#define CP_COMMIT() asm volatile("cp.async.commit_group;" ::: "memory")
#define CP_WAIT0()  asm volatile("cp.async.wait_group 0;" ::: "memory")

// pack 2 floats -> half2 hi + half2 residual-lo
__device__ __forceinline__ void pack_split(float x, float y,
                                           uint32_t& hi, uint32_t& lo) {
    __half2 h = __floats2half2_rn(x, y);
    float hx = __low2float(h), hy = __high2float(h);
    __half2 l2 = __floats2half2_rn(x - hx, y - hy);
    hi = *reinterpret_cast<uint32_t*>(&h);
    lo = *reinterpret_cast<uint32_t*>(&l2);
}
__device__ __forceinline__ uint32_t pack_hi(float x, float y) {
    __half2 h = __floats2half2_rn(x, y);
    return *reinterpret_cast<uint32_t*>(&h);
}

// ---------------------------------------------------------------------------
// One launch for all 6 one-time splits. lo==nullptr -> hi-only.
// ---------------------------------------------------------------------------
__global__ void split6_kernel(
    const float* __restrict__ s0, __half* __restrict__ h0, __half* __restrict__ l0, int n0,
    const float* __restrict__ s1, __half* __restrict__ h1, __half* __restrict__ l1, int n1,
    const float* __restrict__ s2, __half* __restrict__ h2, __half* __restrict__ l2, int n2,
    const float* __restrict__ s3, __half* __restrict__ h3, __half* __restrict__ l3, int n3,
    const float* __restrict__ s4, __half* __restrict__ h4, __half* __restrict__ l4, int n4,
    const float* __restrict__ s5, __half* __restrict__ h5, __half* __restrict__ l5, int n5)
{
    const float* src; __half *hi, *lo; int n;
    switch (blockIdx.y) {
        case 0: src = s0; hi = h0; lo = l0; n = n0; break;
        case 1: src = s1; hi = h1; lo = l1; n = n1; break;
        case 2: src = s2; hi = h2; lo = l2; n = n2; break;
        case 3: src = s3; hi = h3; lo = l3; n = n3; break;
        case 4: src = s4; hi = h4; lo = l4; n = n4; break;
        default: src = s5; hi = h5; lo = l5; n = n5; break;
    }
    int idx = blockIdx.x * blockDim.x + threadIdx.x;
    if (idx >= n) return;
    float4 v = reinterpret_cast<const float4*>(src)[idx];
    if (lo) {
        uint2 h, l;
        pack_split(v.x, v.y, h.x, l.x);
        pack_split(v.z, v.w, h.y, l.y);
        reinterpret_cast<uint2*>(hi)[idx] = h;
        reinterpret_cast<uint2*>(lo)[idx] = l;
    } else {
        uint2 h;
        h.x = pack_hi(v.x, v.y);
        h.y = pack_hi(v.z, v.w);
        reinterpret_cast<uint2*>(hi)[idx] = h;
    }
}

// ===========================================================================
// GEMM (fp16): Y = (Ah [+ Al]) x Bh^T + bias. Al pass only when twoTerm
// (q projection). 128x128 tile, k-chunk 32, 2 CTAs/SM, cp.async
// double-buffered, one sync per chunk. Fused epilogues:
// mode 0 q (rotary+scale+split), 1 k (rotary, hi), 2 v (hi), 3 f32.
// ===========================================================================
#define RSB 80
#define GARR 10240
#define GBUF (3 * GARR)     // Ah | Al | Bh

__global__ void __launch_bounds__(256, 2) gemm_tc_kernel(
    const __half* __restrict__ A0h, const __half* __restrict__ A0l,
    const __half* __restrict__ B0, const float* __restrict__ b0,
    __half* __restrict__ O0h, __half* __restrict__ O0l, float* __restrict__ F0,
    const __half* __restrict__ A1h,
    const __half* __restrict__ B1, const float* __restrict__ b1,
    __half* __restrict__ O1h,
    const __half* __restrict__ A2h,
    const __half* __restrict__ B2, const float* __restrict__ b2,
    __half* __restrict__ O2h,
    const float* __restrict__ rope, int fused, int M)
{
    extern __shared__ char sm[];
    const uint32_t smb = smem_to_u32(sm);
    const int tid = threadIdx.x;
    const int lid = tid & 31;
    const int wid = tid >> 5;
    const int wm = wid >> 2, wn = wid & 3;

    const __half *Ah, *Al, *Bh;
    const float* Bi;
    __half *Oh, *Ol;
    if (blockIdx.z == 0)      { Ah=A0h; Al=A0l;  Bh=B0; Bi=b0; Oh=O0h; Ol=O0l; }
    else if (blockIdx.z == 1) { Ah=A1h; Al=A1h;  Bh=B1; Bi=b1; Oh=O1h; Ol=nullptr; }
    else                      { Ah=A2h; Al=A2h;  Bh=B2; Bi=b2; Oh=O2h; Ol=nullptr; }
    const int mode = fused ? (int)blockIdx.z : 3;
    const bool twoTerm = fused && (blockIdx.z == 0);   // only q projection

    const int bm = blockIdx.y * 128, bn = blockIdx.x * 128;
    const uint32_t lmoff = (uint32_t)((lid & 15) * RSB + ((lid >> 4) << 4));

    const int r0 = tid >> 2, s0 = (tid & 3);
    const int r1 = (tid + 256) >> 2, s1 = ((tid + 256) & 3);

    float acc[4][4][4];
#pragma unroll
    for (int a = 0; a < 4; a++)
#pragma unroll
        for (int b = 0; b < 4; b++)
#pragma unroll
            for (int c = 0; c < 4; c++) acc[a][b][c] = 0.f;

    auto issue = [&](int ch, int buf) {
        uint32_t base = smb + buf * GBUF;
#pragma unroll
        for (int j = 0; j < 2; j++) {
            int row = j ? r1 : r0;
            int seg = j ? s1 : s0;
            uint32_t doff = (uint32_t)(row * RSB + seg * 16);
            bool ap = (bm + row) < M;
            size_t abyte = ((size_t)(bm + row) * CC + ch * 32) * 2 + seg * 16;
            size_t bbyte = ((size_t)(bn + row) * CC + ch * 32) * 2 + seg * 16;
            cp16(base + doff,            (const char*)Ah + abyte, ap);
            if (twoTerm)
                cp16(base + GARR + doff, (const char*)Al + abyte, ap);
            cp16(base + 2 * GARR + doff, (const char*)Bh + bbyte, true);
        }
    };

    issue(0, 0);
    CP_COMMIT();

    for (int ch = 0; ch < 32; ch++) {
        CP_WAIT0();
        __syncthreads();
        if (ch < 31) { issue(ch + 1, (ch + 1) & 1); CP_COMMIT(); }

        const uint32_t base = smb + (ch & 1) * GBUF;
#pragma unroll
        for (int ks = 0; ks < 2; ks++) {
            const uint32_t kofs = (uint32_t)(ks * 32);
            uint32_t Af[4][4], Al4[4][4], Bf[2][4];
#pragma unroll
            for (int mt = 0; mt < 4; mt++) {
                uint32_t rb = (uint32_t)((wm * 64 + mt * 16) * RSB) + kofs + lmoff;
                ldm_x4(Af[mt], base + rb);
                if (twoTerm) ldm_x4(Al4[mt], base + GARR + rb);
            }
#pragma unroll
            for (int np = 0; np < 2; np++) {
                uint32_t rb = (uint32_t)((wn * 32 + np * 16) * RSB) + kofs + lmoff;
                ldm_x4(Bf[np], base + 2 * GARR + rb);
            }
#pragma unroll
            for (int mt = 0; mt < 4; mt++)
#pragma unroll
                for (int nt = 0; nt < 4; nt++) {
                    uint32_t bb0 = Bf[nt >> 1][nt & 1];
                    uint32_t bb1 = Bf[nt >> 1][2 + (nt & 1)];
                    mma16816(acc[mt][nt], Af[mt], bb0, bb1);
                }
            if (twoTerm) {
#pragma unroll
                for (int mt = 0; mt < 4; mt++)
#pragma unroll
                    for (int nt = 0; nt < 4; nt++) {
                        uint32_t bb0 = Bf[nt >> 1][nt & 1];
                        uint32_t bb1 = Bf[nt >> 1][2 + (nt & 1)];
                        mma16816(acc[mt][nt], Al4[mt], bb0, bb1);
                    }
            }
        }
    }

    const int rbase = bm + wm * 64 + (lid >> 2);
    const int cbase = bn + wn * 32 + (lid & 3) * 2;
#pragma unroll
    for (int mt = 0; mt < 4; mt++) {
#pragma unroll
        for (int nt = 0; nt < 4; nt++) {
            int c = cbase + nt * 8;
            float2 bv = *(const float2*)(Bi + c);
#pragma unroll
            for (int half = 0; half < 2; half++) {
                int rr = rbase + mt * 16 + half * 8;
                if (rr >= M) continue;
                float v0 = acc[mt][nt][half * 2 + 0] + bv.x;
                float v1 = acc[mt][nt][half * 2 + 1] + bv.y;
                if (mode == 3) {
                    *(float2*)(F0 + (size_t)rr * CC + c) = make_float2(v0, v1);
                    continue;
                }
                if (mode <= 1) {
                    int d = c & 63;
                    if (d < LL) {
                        int t = rr % TT;
                        float f0 = rope[t * LL + d], f1 = rope[t * LL + d + 1];
                        float c0 = cosf(f0), s0f = sinf(f0);
                        float c1 = cosf(f1), s1f = sinf(f1);
                        float a = v0, bq2 = v1;
                        v0 = a * c0 - bq2 * s0f;
                        v1 = bq2 * c1 + a * s1f;
                    }
                    if (mode == 0) { v0 *= 0.125f; v1 *= 0.125f; }
                }
                size_t off = (size_t)rr * CC + c;
                if (Ol) {
                    uint32_t h, l;
                    pack_split(v0, v1, h, l);
                    *reinterpret_cast<uint32_t*>(Oh + off) = h;
                    *reinterpret_cast<uint32_t*>(Ol + off) = l;
                } else {
                    *reinterpret_cast<uint32_t*>(Oh + off) = pack_hi(v0, v1);
                }
            }
        }
    }
}

// ===========================================================================
// Tensor-core flash attention (fp16, 2-term): S=(Qh+Ql)·Kh, O=(Ph+Pl)·Vh.
// CTA = (64 q, h, b); 4 warps, XOR-swizzled smem 32 KB -> 4 CTAs/SM.
// Q staged in buf1 and overwritten by kv tile 1. Output hi-only.
// ===========================================================================
#define ABUF(b)  ((b) * 16384)
#define AKH(b)   (ABUF(b) + 0)
#define AVH(b)   (ABUF(b) + 8192)
#define AQH      (ABUF(1) + 0)
#define AQL      (ABUF(1) + 8192)
#define SMEM_ATTN 32768

#define SWOFF(row, seg) ((uint32_t)((row) * 128 + ((((seg) ^ ((row) & 7))) << 4)))

__global__ void __launch_bounds__(128, 4) attn_tc_kernel(
    const __half* __restrict__ qh, const __half* __restrict__ ql,
    const __half* __restrict__ kh, const __half* __restrict__ vh,
    __half* __restrict__ oh)
{
    extern __shared__ char sm[];
    const uint32_t smb = smem_to_u32(sm);
    const int tid = threadIdx.x;
    const int l = tid & 31, w = tid >> 5;
    const int q0 = blockIdx.x * 64;
    const int h = blockIdx.y, b = blockIdx.z;
    const size_t rb = (size_t)b * TT * CC + (size_t)h * HD;

    const uint32_t lrow = (uint32_t)(l & 15) * 128;
    const uint32_t lhb = (uint32_t)(l >> 4);
    const uint32_t lx7 = (uint32_t)(l & 7);
    auto swa = [&](uint32_t base, uint32_t R, uint32_t cseg) {
        return base + R * 128 + lrow + ((((cseg | lhb)) ^ lx7) << 4);
    };

#pragma unroll
    for (int j = 0; j < 4; j++) {
        int slot = tid + j * 128;
        int row = slot >> 3, seg = slot & 7;
        bool p = (q0 + row) < TT;
        size_t byte = (rb + (size_t)(q0 + row) * CC) * 2 + seg * 16;
        uint32_t doff = SWOFF(row, seg);
        cp16(smb + AQH + doff, (const char*)qh + byte, p);
        cp16(smb + AQL + doff, (const char*)ql + byte, p);
    }
    CP_COMMIT();
    CP_WAIT0();
    __syncthreads();

    uint32_t Qf[4][4], Ql4[4][4];
#pragma unroll
    for (int ks = 0; ks < 4; ks++) {
        ldm_x4(Qf[ks],  swa(smb + AQH, (uint32_t)(w * 16), (uint32_t)(ks * 2)));
        ldm_x4(Ql4[ks], swa(smb + AQL, (uint32_t)(w * 16), (uint32_t)(ks * 2)));
    }
    __syncthreads();

    auto issue_kv = [&](int t, int buf) {
        int kv0 = t * 64;
#pragma unroll
        for (int j = 0; j < 4; j++) {
            int slot = tid + j * 128;
            int row = slot >> 3, seg = slot & 7;
            bool p = (kv0 + row) < TT;
            size_t byte = (rb + (size_t)(kv0 + row) * CC) * 2 + seg * 16;
            uint32_t doff = SWOFF(row, seg);
            cp16(smb + AKH(buf) + doff, (const char*)kh + byte, p);
            cp16(smb + AVH(buf) + doff, (const char*)vh + byte, p);
        }
    };

    issue_kv(0, 0);
    CP_COMMIT();

    int kv_end = q0 + COND + 63;
    if (kv_end > TT) kv_end = TT;
    const int nkv = (kv_end + 63) >> 6;

    const int qg0 = q0 + w * 16 + (l >> 2);
    const int qg1 = qg0 + 8;

    float Oacc[8][4];
#pragma unroll
    for (int i = 0; i < 8; i++)
#pragma unroll
        for (int j = 0; j < 4; j++) Oacc[i][j] = 0.f;
    float m0 = -1e30f, m1 = -1e30f, l0 = 0.f, l1 = 0.f;

    for (int t = 0; t < nkv; t++) {
        const int buf = t & 1;
        CP_WAIT0();
        __syncthreads();
        if (t + 1 < nkv) { issue_kv(t + 1, buf ^ 1); CP_COMMIT(); }

        const int kv0 = t * 64;
        float S[8][4];
#pragma unroll
        for (int i = 0; i < 8; i++)
#pragma unroll
            for (int j = 0; j < 4; j++) S[i][j] = 0.f;

#pragma unroll
        for (int ks = 0; ks < 4; ks++) {
            uint32_t Kf[4][4];
#pragma unroll
            for (int np = 0; np < 4; np++)
                ldm_x4(Kf[np], swa(smb + AKH(buf), (uint32_t)(np * 16), (uint32_t)(ks * 2)));
#pragma unroll
            for (int nt = 0; nt < 8; nt++) {
                uint32_t bh0 = Kf[nt >> 1][nt & 1];
                uint32_t bh1 = Kf[nt >> 1][2 + (nt & 1)];
                mma16816(S[nt], Qf[ks], bh0, bh1);
            }
#pragma unroll
            for (int nt = 0; nt < 8; nt++) {
                uint32_t bh0 = Kf[nt >> 1][nt & 1];
                uint32_t bh1 = Kf[nt >> 1][2 + (nt & 1)];
                mma16816(S[nt], Ql4[ks], bh0, bh1);
            }
        }

        float mx0 = -1e30f, mx1 = -1e30f;
#pragma unroll
        for (int nt = 0; nt < 8; nt++) {
#pragma unroll
            for (int e = 0; e < 2; e++) {
                int kvc = kv0 + nt * 8 + (l & 3) * 2 + e;
                bool inb = kvc < TT;
                if (!(inb && kvc < COND + qg0)) S[nt][e] = -1e30f;
                if (!(inb && kvc < COND + qg1)) S[nt][2 + e] = -1e30f;
                mx0 = fmaxf(mx0, S[nt][e]);
                mx1 = fmaxf(mx1, S[nt][2 + e]);
            }
        }
        mx0 = fmaxf(mx0, __shfl_xor_sync(0xffffffffu, mx0, 1));
        mx0 = fmaxf(mx0, __shfl_xor_sync(0xffffffffu, mx0, 2));
        mx1 = fmaxf(mx1, __shfl_xor_sync(0xffffffffu, mx1, 1));
        mx1 = fmaxf(mx1, __shfl_xor_sync(0xffffffffu, mx1, 2));

        float mn0 = fmaxf(m0, mx0), mn1 = fmaxf(m1, mx1);
        float al0 = __expf(m0 - mn0), al1 = __expf(m1 - mn1);
        m0 = mn0; m1 = mn1;

        float s0 = 0.f, s1 = 0.f;
#pragma unroll
        for (int nt = 0; nt < 8; nt++) {
#pragma unroll
            for (int e = 0; e < 2; e++) {
                S[nt][e] = __expf(S[nt][e] - mn0);         s0 += S[nt][e];
                S[nt][2 + e] = __expf(S[nt][2 + e] - mn1); s1 += S[nt][2 + e];
            }
        }
        s0 += __shfl_xor_sync(0xffffffffu, s0, 1);
        s0 += __shfl_xor_sync(0xffffffffu, s0, 2);
        s1 += __shfl_xor_sync(0xffffffffu, s1, 1);
        s1 += __shfl_xor_sync(0xffffffffu, s1, 2);
        l0 = l0 * al0 + s0;
        l1 = l1 * al1 + s1;

#pragma unroll
        for (int nt = 0; nt < 8; nt++) {
            Oacc[nt][0] *= al0; Oacc[nt][1] *= al0;
            Oacc[nt][2] *= al1; Oacc[nt][3] *= al1;
        }

#pragma unroll
        for (int ks = 0; ks < 4; ks++) {
            uint32_t Ph[4], Pl[4];
            pack_split(S[2 * ks][0],     S[2 * ks][1],     Ph[0], Pl[0]);
            pack_split(S[2 * ks][2],     S[2 * ks][3],     Ph[1], Pl[1]);
            pack_split(S[2 * ks + 1][0], S[2 * ks + 1][1], Ph[2], Pl[2]);
            pack_split(S[2 * ks + 1][2], S[2 * ks + 1][3], Ph[3], Pl[3]);

            uint32_t Vf[4][4];
#pragma unroll
            for (int np = 0; np < 4; np++)
                ldm_x4_t(Vf[np], swa(smb + AVH(buf), (uint32_t)(ks * 16), (uint32_t)(np * 2)));
#pragma unroll
            for (int nt = 0; nt < 8; nt++) {
                uint32_t bh0 = Vf[nt >> 1][(nt & 1) * 2];
                uint32_t bh1 = Vf[nt >> 1][(nt & 1) * 2 + 1];
                mma16816(Oacc[nt], Ph, bh0, bh1);
            }
#pragma unroll
            for (int nt = 0; nt < 8; nt++) {
                uint32_t bh0 = Vf[nt >> 1][(nt & 1) * 2];
                uint32_t bh1 = Vf[nt >> 1][(nt & 1) * 2 + 1];
                mma16816(Oacc[nt], Pl, bh0, bh1);
            }
        }
    }

    float inv0 = 1.f / l0, inv1 = 1.f / l1;
#pragma unroll
    for (int nt = 0; nt < 8; nt++) {
        int c = nt * 8 + (l & 3) * 2;
        if (qg0 < TT) {
            size_t off = rb + (size_t)qg0 * CC + c;
            *reinterpret_cast<uint32_t*>(oh + off) =
                pack_hi(Oacc[nt][0] * inv0, Oacc[nt][1] * inv0);
        }
        if (qg1 < TT) {
            size_t off = rb + (size_t)qg1 * CC + c;
            *reinterpret_cast<uint32_t*>(oh + off) =
                pack_hi(Oacc[nt][2] * inv1, Oacc[nt][3] * inv1);
        }
    }
}

// ---------------------------------------------------------------------------
// Launch
// ---------------------------------------------------------------------------
extern "C" void kernel_launch(void* const* d_in, const int* in_sizes, int n_in,
                              void* d_out, int out_size)
{
    const float* x_q  = (const float*)d_in[0];
    const float* x_kv = (const float*)d_in[1];
    const float* rope = (const float*)d_in[2];
    const float* Wq   = (const float*)d_in[3];
    const float* bq   = (const float*)d_in[4];
    const float* Wk   = (const float*)d_in[5];
    const float* bk   = (const float*)d_in[6];
    const float* Wv   = (const float*)d_in[7];
    const float* bv   = (const float*)d_in[8];
    const float* Wp   = (const float*)d_in[9];
    const float* bp   = (const float*)d_in[10];
    float* out = (float*)d_out;

    __half *xqh, *xql, *xkh, *Wh;
    __half *qh, *ql, *kh, *vh, *ah;
    cudaGetSymbolAddress((void**)&xqh, g_xqh);
    cudaGetSymbolAddress((void**)&xql, g_xql);
    cudaGetSymbolAddress((void**)&xkh, g_xkh);
    cudaGetSymbolAddress((void**)&Wh,  g_Wh);
    cudaGetSymbolAddress((void**)&qh,  g_qh);
    cudaGetSymbolAddress((void**)&ql,  g_ql);
    cudaGetSymbolAddress((void**)&kh,  g_kh);
    cudaGetSymbolAddress((void**)&vh,  g_vh);
    cudaGetSymbolAddress((void**)&ah,  g_ah);

    cudaFuncSetAttribute(gemm_tc_kernel,
        cudaFuncAttributeMaxDynamicSharedMemorySize, 2 * GBUF);
    cudaFuncSetAttribute(attn_tc_kernel,
        cudaFuncAttributeMaxDynamicSharedMemorySize, SMEM_ATTN);

    // 1) one-time splits: x_q hi/lo, x_kv hi, W hi
    const int NX4 = MROWS * CC / 4;
    const int NW4 = CC * CC / 4;
    dim3 split_grid((NX4 + 255) / 256, 6);
    split6_kernel<<<split_grid, 256>>>(
        x_q,  xqh, xql, NX4,
        x_kv, xkh, nullptr, NX4,
        Wq, Wh,              nullptr, NW4,
        Wk, Wh + CC * CC,     nullptr, NW4,
        Wv, Wh + 2 * CC * CC, nullptr, NW4,
        Wp, Wh + 3 * CC * CC, nullptr, NW4);

    // 2) fused Q/K/V projections; q 2-term split-out, k/v 1-term hi-out
    dim3 g_qkv(CC / 128, (MROWS + 127) / 128, 3);   // (8, 49, 3)
    gemm_tc_kernel<<<g_qkv, 256, 2 * GBUF>>>(
        xqh, xql, Wh,              bq, qh, ql, nullptr,
        xkh,      Wh + CC * CC,     bk, kh,
        xkh,      Wh + 2 * CC * CC, bv, vh,
        rope, 1, MROWS);

    // 3) tensor-core attention (2-term, 4 CTAs/SM) -> hi-only output
    dim3 attn_grid((TT + 63) / 64, HH, BB);         // (13, 16, 8)
    attn_tc_kernel<<<attn_grid, 128, SMEM_ATTN>>>(qh, ql, kh, vh, ah);

    // 4) output projection, 1-term, f32 epilogue
    dim3 g_out(CC / 128, (MROWS + 127) / 128, 1);
    gemm_tc_kernel<<<g_out, 256, 2 * GBUF>>>(
        ah, ah, Wh + 3 * CC * CC, bp, nullptr, nullptr, out,
        ah,     Wh + 3 * CC * CC, bp, nullptr,
        ah,     Wh + 3 * CC * CC, bp, nullptr,
        rope, 0, MROWS);
}

// round 14
// speedup vs baseline: 1.6611x; 1.0520x over previous
#include <cuda_runtime.h>
#include <cuda_fp16.h>
#include <math.h>
#include <stdint.h>

#define BB 8
#define TT 769
#define CC 1024
#define HH 16
#define HD 64
#define LL 32
#define COND 256
#define MROWS (BB*TT)   // 6152

// ---------------------------------------------------------------------------
// Device scratch (allocation-free requirement -> globals)  [fp16]
// ---------------------------------------------------------------------------
__device__ __half g_xqh[(size_t)MROWS * CC], g_xql[(size_t)MROWS * CC];
__device__ __half g_xkh[(size_t)MROWS * CC];          // x_kv: hi only
__device__ __half g_Wh[(size_t)4 * CC * CC];          // W: hi only
__device__ __half g_qh[(size_t)MROWS * CC], g_ql[(size_t)MROWS * CC];
__device__ __half g_kh[(size_t)MROWS * CC];           // K: hi only
__device__ __half g_vh[(size_t)MROWS * CC];           // V: hi only
__device__ __half g_ah[(size_t)MROWS * CC];           // attn out: hi only

// ---------------------------------------------------------------------------
// Helpers
// ---------------------------------------------------------------------------
__device__ __forceinline__ uint32_t smem_to_u32(const void* p) {
    uint32_t a;
    asm("{ .reg .u64 t; cvta.to.shared.u64 t, %1; cvt.u32.u64 %0, t; }"
        : "=r"(a) : "l"(p));
    return a;
}
__device__ __forceinline__ void ldm_x4(uint32_t* r, uint32_t addr) {
    asm volatile("ldmatrix.sync.aligned.m8n8.x4.shared.b16 {%0,%1,%2,%3}, [%4];"
        : "=r"(r[0]), "=r"(r[1]), "=r"(r[2]), "=r"(r[3]) : "r"(addr));
}
__device__ __forceinline__ void ldm_x4_t(uint32_t* r, uint32_t addr) {
    asm volatile("ldmatrix.sync.aligned.m8n8.x4.trans.shared.b16 {%0,%1,%2,%3}, [%4];"
        : "=r"(r[0]), "=r"(r[1]), "=r"(r[2]), "=r"(r[3]) : "r"(addr));
}
__device__ __forceinline__ void mma16816(float* d, const uint32_t* a,
                                         uint32_t b0, uint32_t b1) {
    asm("mma.sync.aligned.m16n8k16.row.col.f32.f16.f16.f32 "
        "{%0,%1,%2,%3}, {%4,%5,%6,%7}, {%8,%9}, {%0,%1,%2,%3};"
        : "+f"(d[0]), "+f"(d[1]), "+f"(d[2]), "+f"(d[3])
        : "r"(a[0]), "r"(a[1]), "r"(a[2]), "r"(a[3]), "r"(b0), "r"(b1));
}
__device__ __forceinline__ void cp16(uint32_t dst, const void* src, bool pred) {
    int n = pred ? 16 : 0;
    asm volatile("cp.async.cg.shared.global [%0], [%1], 16, %2;"
        :: "r"(dst), "l"(src), "r"(n) : "memory");
}
#define CP_COMMIT() asm volatile("cp.async.commit_group;" ::: "memory")
#define CP_WAIT0()  asm volatile("cp.async.wait_group 0;" ::: "memory")

// pack 2 floats -> half2 hi + half2 residual-lo
__device__ __forceinline__ void pack_split(float x, float y,
                                           uint32_t& hi, uint32_t& lo) {
    __half2 h = __floats2half2_rn(x, y);
    float hx = __low2float(h), hy = __high2float(h);
    __half2 l2 = __floats2half2_rn(x - hx, y - hy);
    hi = *reinterpret_cast<uint32_t*>(&h);
    lo = *reinterpret_cast<uint32_t*>(&l2);
}
__device__ __forceinline__ uint32_t pack_hi(float x, float y) {
    __half2 h = __floats2half2_rn(x, y);
    return *reinterpret_cast<uint32_t*>(&h);
}

// ---------------------------------------------------------------------------
// One launch for all 6 one-time splits. lo==nullptr -> hi-only.
// ---------------------------------------------------------------------------
__global__ void split6_kernel(
    const float* __restrict__ s0, __half* __restrict__ h0, __half* __restrict__ l0, int n0,
    const float* __restrict__ s1, __half* __restrict__ h1, __half* __restrict__ l1, int n1,
    const float* __restrict__ s2, __half* __restrict__ h2, __half* __restrict__ l2, int n2,
    const float* __restrict__ s3, __half* __restrict__ h3, __half* __restrict__ l3, int n3,
    const float* __restrict__ s4, __half* __restrict__ h4, __half* __restrict__ l4, int n4,
    const float* __restrict__ s5, __half* __restrict__ h5, __half* __restrict__ l5, int n5)
{
    const float* src; __half *hi, *lo; int n;
    switch (blockIdx.y) {
        case 0: src = s0; hi = h0; lo = l0; n = n0; break;
        case 1: src = s1; hi = h1; lo = l1; n = n1; break;
        case 2: src = s2; hi = h2; lo = l2; n = n2; break;
        case 3: src = s3; hi = h3; lo = l3; n = n3; break;
        case 4: src = s4; hi = h4; lo = l4; n = n4; break;
        default: src = s5; hi = h5; lo = l5; n = n5; break;
    }
    int idx = blockIdx.x * blockDim.x + threadIdx.x;
    if (idx >= n) return;
    float4 v = reinterpret_cast<const float4*>(src)[idx];
    if (lo) {
        uint2 h, l;
        pack_split(v.x, v.y, h.x, l.x);
        pack_split(v.z, v.w, h.y, l.y);
        reinterpret_cast<uint2*>(hi)[idx] = h;
        reinterpret_cast<uint2*>(lo)[idx] = l;
    } else {
        uint2 h;
        h.x = pack_hi(v.x, v.y);
        h.y = pack_hi(v.z, v.w);
        reinterpret_cast<uint2*>(hi)[idx] = h;
    }
}

// ===========================================================================
// GEMM (fp16): Y = (Ah [+ Al]) x Bh^T + bias. Al pass only for q projection.
// 128x128 tile, k-chunk 32, 2 CTAs/SM, cp.async double-buffered,
// one sync per chunk. Fused epilogues.
// ===========================================================================
#define RSB 80
#define GARR 10240
#define GBUF (3 * GARR)     // Ah | Al | Bh

__global__ void __launch_bounds__(256, 2) gemm_tc_kernel(
    const __half* __restrict__ A0h, const __half* __restrict__ A0l,
    const __half* __restrict__ B0, const float* __restrict__ b0,
    __half* __restrict__ O0h, __half* __restrict__ O0l, float* __restrict__ F0,
    const __half* __restrict__ A1h,
    const __half* __restrict__ B1, const float* __restrict__ b1,
    __half* __restrict__ O1h,
    const __half* __restrict__ A2h,
    const __half* __restrict__ B2, const float* __restrict__ b2,
    __half* __restrict__ O2h,
    const float* __restrict__ rope, int fused, int M)
{
    extern __shared__ char sm[];
    const uint32_t smb = smem_to_u32(sm);
    const int tid = threadIdx.x;
    const int lid = tid & 31;
    const int wid = tid >> 5;
    const int wm = wid >> 2, wn = wid & 3;

    const __half *Ah, *Al, *Bh;
    const float* Bi;
    __half *Oh, *Ol;
    if (blockIdx.z == 0)      { Ah=A0h; Al=A0l;  Bh=B0; Bi=b0; Oh=O0h; Ol=O0l; }
    else if (blockIdx.z == 1) { Ah=A1h; Al=A1h;  Bh=B1; Bi=b1; Oh=O1h; Ol=nullptr; }
    else                      { Ah=A2h; Al=A2h;  Bh=B2; Bi=b2; Oh=O2h; Ol=nullptr; }
    const int mode = fused ? (int)blockIdx.z : 3;
    const bool twoTerm = fused && (blockIdx.z == 0);

    const int bm = blockIdx.y * 128, bn = blockIdx.x * 128;
    const uint32_t lmoff = (uint32_t)((lid & 15) * RSB + ((lid >> 4) << 4));

    const int r0 = tid >> 2, s0 = (tid & 3);
    const int r1 = (tid + 256) >> 2, s1 = ((tid + 256) & 3);

    float acc[4][4][4];
#pragma unroll
    for (int a = 0; a < 4; a++)
#pragma unroll
        for (int b = 0; b < 4; b++)
#pragma unroll
            for (int c = 0; c < 4; c++) acc[a][b][c] = 0.f;

    auto issue = [&](int ch, int buf) {
        uint32_t base = smb + buf * GBUF;
#pragma unroll
        for (int j = 0; j < 2; j++) {
            int row = j ? r1 : r0;
            int seg = j ? s1 : s0;
            uint32_t doff = (uint32_t)(row * RSB + seg * 16);
            bool ap = (bm + row) < M;
            size_t abyte = ((size_t)(bm + row) * CC + ch * 32) * 2 + seg * 16;
            size_t bbyte = ((size_t)(bn + row) * CC + ch * 32) * 2 + seg * 16;
            cp16(base + doff,            (const char*)Ah + abyte, ap);
            if (twoTerm)
                cp16(base + GARR + doff, (const char*)Al + abyte, ap);
            cp16(base + 2 * GARR + doff, (const char*)Bh + bbyte, true);
        }
    };

    issue(0, 0);
    CP_COMMIT();

    for (int ch = 0; ch < 32; ch++) {
        CP_WAIT0();
        __syncthreads();
        if (ch < 31) { issue(ch + 1, (ch + 1) & 1); CP_COMMIT(); }

        const uint32_t base = smb + (ch & 1) * GBUF;
#pragma unroll
        for (int ks = 0; ks < 2; ks++) {
            const uint32_t kofs = (uint32_t)(ks * 32);
            uint32_t Af[4][4], Al4[4][4], Bf[2][4];
#pragma unroll
            for (int mt = 0; mt < 4; mt++) {
                uint32_t rb = (uint32_t)((wm * 64 + mt * 16) * RSB) + kofs + lmoff;
                ldm_x4(Af[mt], base + rb);
                if (twoTerm) ldm_x4(Al4[mt], base + GARR + rb);
            }
#pragma unroll
            for (int np = 0; np < 2; np++) {
                uint32_t rb = (uint32_t)((wn * 32 + np * 16) * RSB) + kofs + lmoff;
                ldm_x4(Bf[np], base + 2 * GARR + rb);
            }
#pragma unroll
            for (int mt = 0; mt < 4; mt++)
#pragma unroll
                for (int nt = 0; nt < 4; nt++) {
                    uint32_t bb0 = Bf[nt >> 1][nt & 1];
                    uint32_t bb1 = Bf[nt >> 1][2 + (nt & 1)];
                    mma16816(acc[mt][nt], Af[mt], bb0, bb1);
                }
            if (twoTerm) {
#pragma unroll
                for (int mt = 0; mt < 4; mt++)
#pragma unroll
                    for (int nt = 0; nt < 4; nt++) {
                        uint32_t bb0 = Bf[nt >> 1][nt & 1];
                        uint32_t bb1 = Bf[nt >> 1][2 + (nt & 1)];
                        mma16816(acc[mt][nt], Al4[mt], bb0, bb1);
                    }
            }
        }
    }

    const int rbase = bm + wm * 64 + (lid >> 2);
    const int cbase = bn + wn * 32 + (lid & 3) * 2;
#pragma unroll
    for (int mt = 0; mt < 4; mt++) {
#pragma unroll
        for (int nt = 0; nt < 4; nt++) {
            int c = cbase + nt * 8;
            float2 bv = *(const float2*)(Bi + c);
#pragma unroll
            for (int half = 0; half < 2; half++) {
                int rr = rbase + mt * 16 + half * 8;
                if (rr >= M) continue;
                float v0 = acc[mt][nt][half * 2 + 0] + bv.x;
                float v1 = acc[mt][nt][half * 2 + 1] + bv.y;
                if (mode == 3) {
                    *(float2*)(F0 + (size_t)rr * CC + c) = make_float2(v0, v1);
                    continue;
                }
                if (mode <= 1) {
                    int d = c & 63;
                    if (d < LL) {
                        int t = rr % TT;
                        float f0 = rope[t * LL + d], f1 = rope[t * LL + d + 1];
                        float c0 = cosf(f0), s0f = sinf(f0);
                        float c1 = cosf(f1), s1f = sinf(f1);
                        float a = v0, bq2 = v1;
                        v0 = a * c0 - bq2 * s0f;
                        v1 = bq2 * c1 + a * s1f;
                    }
                    if (mode == 0) { v0 *= 0.125f; v1 *= 0.125f; }
                }
                size_t off = (size_t)rr * CC + c;
                if (Ol) {
                    uint32_t h, l;
                    pack_split(v0, v1, h, l);
                    *reinterpret_cast<uint32_t*>(Oh + off) = h;
                    *reinterpret_cast<uint32_t*>(Ol + off) = l;
                } else {
                    *reinterpret_cast<uint32_t*>(Oh + off) = pack_hi(v0, v1);
                }
            }
        }
    }
}

// ===========================================================================
// Tensor-core flash attention: S=(Qh+Ql)·Kh (2-term), O=Ph·Vh (1-term).
// CTA = (64 q, h, b); 4 warps, XOR-swizzled smem 32 KB -> 4 CTAs/SM.
// Interior kv tiles skip the masking pass entirely.
// ===========================================================================
#define ABUF(b)  ((b) * 16384)
#define AKH(b)   (ABUF(b) + 0)
#define AVH(b)   (ABUF(b) + 8192)
#define AQH      (ABUF(1) + 0)
#define AQL      (ABUF(1) + 8192)
#define SMEM_ATTN 32768

#define SWOFF(row, seg) ((uint32_t)((row) * 128 + ((((seg) ^ ((row) & 7))) << 4)))

__global__ void __launch_bounds__(128, 4) attn_tc_kernel(
    const __half* __restrict__ qh, const __half* __restrict__ ql,
    const __half* __restrict__ kh, const __half* __restrict__ vh,
    __half* __restrict__ oh)
{
    extern __shared__ char sm[];
    const uint32_t smb = smem_to_u32(sm);
    const int tid = threadIdx.x;
    const int l = tid & 31, w = tid >> 5;
    const int q0 = blockIdx.x * 64;
    const int h = blockIdx.y, b = blockIdx.z;
    const size_t rb = (size_t)b * TT * CC + (size_t)h * HD;

    const uint32_t lrow = (uint32_t)(l & 15) * 128;
    const uint32_t lhb = (uint32_t)(l >> 4);
    const uint32_t lx7 = (uint32_t)(l & 7);
    auto swa = [&](uint32_t base, uint32_t R, uint32_t cseg) {
        return base + R * 128 + lrow + ((((cseg | lhb)) ^ lx7) << 4);
    };

#pragma unroll
    for (int j = 0; j < 4; j++) {
        int slot = tid + j * 128;
        int row = slot >> 3, seg = slot & 7;
        bool p = (q0 + row) < TT;
        size_t byte = (rb + (size_t)(q0 + row) * CC) * 2 + seg * 16;
        uint32_t doff = SWOFF(row, seg);
        cp16(smb + AQH + doff, (const char*)qh + byte, p);
        cp16(smb + AQL + doff, (const char*)ql + byte, p);
    }
    CP_COMMIT();
    CP_WAIT0();
    __syncthreads();

    uint32_t Qf[4][4], Ql4[4][4];
#pragma unroll
    for (int ks = 0; ks < 4; ks++) {
        ldm_x4(Qf[ks],  swa(smb + AQH, (uint32_t)(w * 16), (uint32_t)(ks * 2)));
        ldm_x4(Ql4[ks], swa(smb + AQL, (uint32_t)(w * 16), (uint32_t)(ks * 2)));
    }
    __syncthreads();

    auto issue_kv = [&](int t, int buf) {
        int kv0 = t * 64;
#pragma unroll
        for (int j = 0; j < 4; j++) {
            int slot = tid + j * 128;
            int row = slot >> 3, seg = slot & 7;
            bool p = (kv0 + row) < TT;
            size_t byte = (rb + (size_t)(kv0 + row) * CC) * 2 + seg * 16;
            uint32_t doff = SWOFF(row, seg);
            cp16(smb + AKH(buf) + doff, (const char*)kh + byte, p);
            cp16(smb + AVH(buf) + doff, (const char*)vh + byte, p);
        }
    };

    issue_kv(0, 0);
    CP_COMMIT();

    int kv_end = q0 + COND + 63;
    if (kv_end > TT) kv_end = TT;
    const int nkv = (kv_end + 63) >> 6;

    const int qg0 = q0 + w * 16 + (l >> 2);
    const int qg1 = qg0 + 8;
    const int warp_qmin = q0 + w * 16;

    float Oacc[8][4];
#pragma unroll
    for (int i = 0; i < 8; i++)
#pragma unroll
        for (int j = 0; j < 4; j++) Oacc[i][j] = 0.f;
    float m0 = -1e30f, m1 = -1e30f, l0 = 0.f, l1 = 0.f;

    for (int t = 0; t < nkv; t++) {
        const int buf = t & 1;
        CP_WAIT0();
        __syncthreads();
        if (t + 1 < nkv) { issue_kv(t + 1, buf ^ 1); CP_COMMIT(); }

        const int kv0 = t * 64;
        float S[8][4];
#pragma unroll
        for (int i = 0; i < 8; i++)
#pragma unroll
            for (int j = 0; j < 4; j++) S[i][j] = 0.f;

#pragma unroll
        for (int ks = 0; ks < 4; ks++) {
            uint32_t Kf[4][4];
#pragma unroll
            for (int np = 0; np < 4; np++)
                ldm_x4(Kf[np], swa(smb + AKH(buf), (uint32_t)(np * 16), (uint32_t)(ks * 2)));
#pragma unroll
            for (int nt = 0; nt < 8; nt++) {
                uint32_t bh0 = Kf[nt >> 1][nt & 1];
                uint32_t bh1 = Kf[nt >> 1][2 + (nt & 1)];
                mma16816(S[nt], Qf[ks], bh0, bh1);
            }
#pragma unroll
            for (int nt = 0; nt < 8; nt++) {
                uint32_t bh0 = Kf[nt >> 1][nt & 1];
                uint32_t bh1 = Kf[nt >> 1][2 + (nt & 1)];
                mma16816(S[nt], Ql4[ks], bh0, bh1);
            }
        }

        // masking only needed on boundary tiles (per warp)
        if ((kv0 + 63 >= COND + warp_qmin) || (kv0 + 63 >= TT)) {
#pragma unroll
            for (int nt = 0; nt < 8; nt++) {
#pragma unroll
                for (int e = 0; e < 2; e++) {
                    int kvc = kv0 + nt * 8 + (l & 3) * 2 + e;
                    bool inb = kvc < TT;
                    if (!(inb && kvc < COND + qg0)) S[nt][e] = -1e30f;
                    if (!(inb && kvc < COND + qg1)) S[nt][2 + e] = -1e30f;
                }
            }
        }

        float mx0 = -1e30f, mx1 = -1e30f;
#pragma unroll
        for (int nt = 0; nt < 8; nt++) {
            mx0 = fmaxf(mx0, fmaxf(S[nt][0], S[nt][1]));
            mx1 = fmaxf(mx1, fmaxf(S[nt][2], S[nt][3]));
        }
        mx0 = fmaxf(mx0, __shfl_xor_sync(0xffffffffu, mx0, 1));
        mx0 = fmaxf(mx0, __shfl_xor_sync(0xffffffffu, mx0, 2));
        mx1 = fmaxf(mx1, __shfl_xor_sync(0xffffffffu, mx1, 1));
        mx1 = fmaxf(mx1, __shfl_xor_sync(0xffffffffu, mx1, 2));

        float mn0 = fmaxf(m0, mx0), mn1 = fmaxf(m1, mx1);
        float al0 = __expf(m0 - mn0), al1 = __expf(m1 - mn1);
        m0 = mn0; m1 = mn1;

        float s0 = 0.f, s1 = 0.f;
#pragma unroll
        for (int nt = 0; nt < 8; nt++) {
#pragma unroll
            for (int e = 0; e < 2; e++) {
                S[nt][e] = __expf(S[nt][e] - mn0);         s0 += S[nt][e];
                S[nt][2 + e] = __expf(S[nt][2 + e] - mn1); s1 += S[nt][2 + e];
            }
        }
        s0 += __shfl_xor_sync(0xffffffffu, s0, 1);
        s0 += __shfl_xor_sync(0xffffffffu, s0, 2);
        s1 += __shfl_xor_sync(0xffffffffu, s1, 1);
        s1 += __shfl_xor_sync(0xffffffffu, s1, 2);
        l0 = l0 * al0 + s0;
        l1 = l1 * al1 + s1;

#pragma unroll
        for (int nt = 0; nt < 8; nt++) {
            Oacc[nt][0] *= al0; Oacc[nt][1] *= al0;
            Oacc[nt][2] *= al1; Oacc[nt][3] *= al1;
        }

        // O += P x V, P hi-only (single term)
#pragma unroll
        for (int ks = 0; ks < 4; ks++) {
            uint32_t Ph[4];
            Ph[0] = pack_hi(S[2 * ks][0],     S[2 * ks][1]);
            Ph[1] = pack_hi(S[2 * ks][2],     S[2 * ks][3]);
            Ph[2] = pack_hi(S[2 * ks + 1][0], S[2 * ks + 1][1]);
            Ph[3] = pack_hi(S[2 * ks + 1][2], S[2 * ks + 1][3]);

            uint32_t Vf[4][4];
#pragma unroll
            for (int np = 0; np < 4; np++)
                ldm_x4_t(Vf[np], swa(smb + AVH(buf), (uint32_t)(ks * 16), (uint32_t)(np * 2)));
#pragma unroll
            for (int nt = 0; nt < 8; nt++) {
                uint32_t bh0 = Vf[nt >> 1][(nt & 1) * 2];
                uint32_t bh1 = Vf[nt >> 1][(nt & 1) * 2 + 1];
                mma16816(Oacc[nt], Ph, bh0, bh1);
            }
        }
    }

    float inv0 = 1.f / l0, inv1 = 1.f / l1;
#pragma unroll
    for (int nt = 0; nt < 8; nt++) {
        int c = nt * 8 + (l & 3) * 2;
        if (qg0 < TT) {
            size_t off = rb + (size_t)qg0 * CC + c;
            *reinterpret_cast<uint32_t*>(oh + off) =
                pack_hi(Oacc[nt][0] * inv0, Oacc[nt][1] * inv0);
        }
        if (qg1 < TT) {
            size_t off = rb + (size_t)qg1 * CC + c;
            *reinterpret_cast<uint32_t*>(oh + off) =
                pack_hi(Oacc[nt][2] * inv1, Oacc[nt][3] * inv1);
        }
    }
}

// ---------------------------------------------------------------------------
// Launch
// ---------------------------------------------------------------------------
extern "C" void kernel_launch(void* const* d_in, const int* in_sizes, int n_in,
                              void* d_out, int out_size)
{
    const float* x_q  = (const float*)d_in[0];
    const float* x_kv = (const float*)d_in[1];
    const float* rope = (const float*)d_in[2];
    const float* Wq   = (const float*)d_in[3];
    const float* bq   = (const float*)d_in[4];
    const float* Wk   = (const float*)d_in[5];
    const float* bk   = (const float*)d_in[6];
    const float* Wv   = (const float*)d_in[7];
    const float* bv   = (const float*)d_in[8];
    const float* Wp   = (const float*)d_in[9];
    const float* bp   = (const float*)d_in[10];
    float* out = (float*)d_out;

    __half *xqh, *xql, *xkh, *Wh;
    __half *qh, *ql, *kh, *vh, *ah;
    cudaGetSymbolAddress((void**)&xqh, g_xqh);
    cudaGetSymbolAddress((void**)&xql, g_xql);
    cudaGetSymbolAddress((void**)&xkh, g_xkh);
    cudaGetSymbolAddress((void**)&Wh,  g_Wh);
    cudaGetSymbolAddress((void**)&qh,  g_qh);
    cudaGetSymbolAddress((void**)&ql,  g_ql);
    cudaGetSymbolAddress((void**)&kh,  g_kh);
    cudaGetSymbolAddress((void**)&vh,  g_vh);
    cudaGetSymbolAddress((void**)&ah,  g_ah);

    cudaFuncSetAttribute(gemm_tc_kernel,
        cudaFuncAttributeMaxDynamicSharedMemorySize, 2 * GBUF);
    cudaFuncSetAttribute(attn_tc_kernel,
        cudaFuncAttributeMaxDynamicSharedMemorySize, SMEM_ATTN);

    // 1) one-time splits: x_q hi/lo, x_kv hi, W hi
    const int NX4 = MROWS * CC / 4;
    const int NW4 = CC * CC / 4;
    dim3 split_grid((NX4 + 255) / 256, 6);
    split6_kernel<<<split_grid, 256>>>(
        x_q,  xqh, xql, NX4,
        x_kv, xkh, nullptr, NX4,
        Wq, Wh,              nullptr, NW4,
        Wk, Wh + CC * CC,     nullptr, NW4,
        Wv, Wh + 2 * CC * CC, nullptr, NW4,
        Wp, Wh + 3 * CC * CC, nullptr, NW4);

    // 2) fused Q/K/V projections; q 2-term split-out, k/v 1-term hi-out
    dim3 g_qkv(CC / 128, (MROWS + 127) / 128, 3);   // (8, 49, 3)
    gemm_tc_kernel<<<g_qkv, 256, 2 * GBUF>>>(
        xqh, xql, Wh,              bq, qh, ql, nullptr,
        xkh,      Wh + CC * CC,     bk, kh,
        xkh,      Wh + 2 * CC * CC, bv, vh,
        rope, 1, MROWS);

    // 3) tensor-core attention -> hi-only output
    dim3 attn_grid((TT + 63) / 64, HH, BB);         // (13, 16, 8)
    attn_tc_kernel<<<attn_grid, 128, SMEM_ATTN>>>(qh, ql, kh, vh, ah);

    // 4) output projection, 1-term, f32 epilogue
    dim3 g_out(CC / 128, (MROWS + 127) / 128, 1);
    gemm_tc_kernel<<<g_out, 256, 2 * GBUF>>>(
        ah, ah, Wh + 3 * CC * CC, bp, nullptr, nullptr, out,
        ah,     Wh + 3 * CC * CC, bp, nullptr,
        ah,     Wh + 3 * CC * CC, bp, nullptr,
        rope, 0, MROWS);
}

// round 15
// speedup vs baseline: 1.8110x; 1.0903x over previous
#include <cuda_runtime.h>
#include <cuda_fp16.h>
#include <math.h>
#include <stdint.h>

#define BB 8
#define TT 769
#define CC 1024
#define HH 16
#define HD 64
#define LL 32
#define COND 256
#define MROWS (BB*TT)   // 6152

// ---------------------------------------------------------------------------
// Device scratch (allocation-free requirement -> globals)  [fp16]
// ---------------------------------------------------------------------------
__device__ __half g_xqh[(size_t)MROWS * CC], g_xql[(size_t)MROWS * CC];
__device__ __half g_xkh[(size_t)MROWS * CC];          // x_kv: hi only
__device__ __half g_Wh[(size_t)4 * CC * CC];          // W: hi only
__device__ __half g_qh[(size_t)MROWS * CC], g_ql[(size_t)MROWS * CC];
__device__ __half g_kh[(size_t)MROWS * CC];           // K: hi only
__device__ __half g_vh[(size_t)MROWS * CC];           // V: hi only
__device__ __half g_ah[(size_t)MROWS * CC];           // attn out: hi only

// ---------------------------------------------------------------------------
// Helpers
// ---------------------------------------------------------------------------
__device__ __forceinline__ uint32_t smem_to_u32(const void* p) {
    uint32_t a;
    asm("{ .reg .u64 t; cvta.to.shared.u64 t, %1; cvt.u32.u64 %0, t; }"
        : "=r"(a) : "l"(p));
    return a;
}
__device__ __forceinline__ void ldm_x4(uint32_t* r, uint32_t addr) {
    asm volatile("ldmatrix.sync.aligned.m8n8.x4.shared.b16 {%0,%1,%2,%3}, [%4];"
        : "=r"(r[0]), "=r"(r[1]), "=r"(r[2]), "=r"(r[3]) : "r"(addr));
}
__device__ __forceinline__ void ldm_x4_t(uint32_t* r, uint32_t addr) {
    asm volatile("ldmatrix.sync.aligned.m8n8.x4.trans.shared.b16 {%0,%1,%2,%3}, [%4];"
        : "=r"(r[0]), "=r"(r[1]), "=r"(r[2]), "=r"(r[3]) : "r"(addr));
}
__device__ __forceinline__ void mma16816(float* d, const uint32_t* a,
                                         uint32_t b0, uint32_t b1) {
    asm("mma.sync.aligned.m16n8k16.row.col.f32.f16.f16.f32 "
        "{%0,%1,%2,%3}, {%4,%5,%6,%7}, {%8,%9}, {%0,%1,%2,%3};"
        : "+f"(d[0]), "+f"(d[1]), "+f"(d[2]), "+f"(d[3])
        : "r"(a[0]), "r"(a[1]), "r"(a[2]), "r"(a[3]), "r"(b0), "r"(b1));
}
__device__ __forceinline__ void cp16(uint32_t dst, const void* src, bool pred) {
    int n = pred ? 16 : 0;
    asm volatile("cp.async.cg.shared.global [%0], [%1], 16, %2;"
        :: "r"(dst), "l"(src), "r"(n) : "memory");
}
#define CP_COMMIT() asm volatile("cp.async.commit_group;" ::: "memory")
#define CP_WAIT0()  asm volatile("cp.async.wait_group 0;" ::: "memory")

// pack 2 floats -> half2 hi + half2 residual-lo
__device__ __forceinline__ void pack_split(float x, float y,
                                           uint32_t& hi, uint32_t& lo) {
    __half2 h = __floats2half2_rn(x, y);
    float hx = __low2float(h), hy = __high2float(h);
    __half2 l2 = __floats2half2_rn(x - hx, y - hy);
    hi = *reinterpret_cast<uint32_t*>(&h);
    lo = *reinterpret_cast<uint32_t*>(&l2);
}
__device__ __forceinline__ uint32_t pack_hi(float x, float y) {
    __half2 h = __floats2half2_rn(x, y);
    return *reinterpret_cast<uint32_t*>(&h);
}

// XOR-swizzled byte offset within a 128-rows x 128-bytes tile
#define SWOFF(row, seg) ((uint32_t)((row) * 128 + ((((seg) ^ ((row) & 7))) << 4)))

// ---------------------------------------------------------------------------
// One launch for all 6 one-time splits. lo==nullptr -> hi-only.
// ---------------------------------------------------------------------------
__global__ void split6_kernel(
    const float* __restrict__ s0, __half* __restrict__ h0, __half* __restrict__ l0, int n0,
    const float* __restrict__ s1, __half* __restrict__ h1, __half* __restrict__ l1, int n1,
    const float* __restrict__ s2, __half* __restrict__ h2, __half* __restrict__ l2, int n2,
    const float* __restrict__ s3, __half* __restrict__ h3, __half* __restrict__ l3, int n3,
    const float* __restrict__ s4, __half* __restrict__ h4, __half* __restrict__ l4, int n4,
    const float* __restrict__ s5, __half* __restrict__ h5, __half* __restrict__ l5, int n5)
{
    const float* src; __half *hi, *lo; int n;
    switch (blockIdx.y) {
        case 0: src = s0; hi = h0; lo = l0; n = n0; break;
        case 1: src = s1; hi = h1; lo = l1; n = n1; break;
        case 2: src = s2; hi = h2; lo = l2; n = n2; break;
        case 3: src = s3; hi = h3; lo = l3; n = n3; break;
        case 4: src = s4; hi = h4; lo = l4; n = n4; break;
        default: src = s5; hi = h5; lo = l5; n = n5; break;
    }
    int idx = blockIdx.x * blockDim.x + threadIdx.x;
    if (idx >= n) return;
    float4 v = reinterpret_cast<const float4*>(src)[idx];
    if (lo) {
        uint2 h, l;
        pack_split(v.x, v.y, h.x, l.x);
        pack_split(v.z, v.w, h.y, l.y);
        reinterpret_cast<uint2*>(hi)[idx] = h;
        reinterpret_cast<uint2*>(lo)[idx] = l;
    } else {
        uint2 h;
        h.x = pack_hi(v.x, v.y);
        h.y = pack_hi(v.z, v.w);
        reinterpret_cast<uint2*>(hi)[idx] = h;
    }
}

// ===========================================================================
// GEMM v3 (fp16): Y = (Ah [+ Al]) x Bh^T + bias. k-chunk 64, XOR-swizzled
// smem (no padding): per-buffer Ah|Bh(|Al) 16KB arrays. 1-term: 64KB total,
// 2-term: 96KB; both keep 2 CTAs/SM. One sync per chunk (16 chunks).
// Fused epilogues: mode 0 q (rotary+scale+split), 1 k, 2 v (hi), 3 f32.
// ===========================================================================
#define GARR2 16384

__global__ void __launch_bounds__(256, 2) gemm_tc_kernel(
    const __half* __restrict__ A0h, const __half* __restrict__ A0l,
    const __half* __restrict__ B0, const float* __restrict__ b0,
    __half* __restrict__ O0h, __half* __restrict__ O0l, float* __restrict__ F0,
    const __half* __restrict__ A1h,
    const __half* __restrict__ B1, const float* __restrict__ b1,
    __half* __restrict__ O1h,
    const __half* __restrict__ A2h,
    const __half* __restrict__ B2, const float* __restrict__ b2,
    __half* __restrict__ O2h,
    const float* __restrict__ rope, int fused, int M)
{
    extern __shared__ char sm[];
    const uint32_t smb = smem_to_u32(sm);
    const int tid = threadIdx.x;
    const int lid = tid & 31;
    const int wid = tid >> 5;
    const int wm = wid >> 2, wn = wid & 3;

    const __half *Ah, *Al, *Bh;
    const float* Bi;
    __half *Oh, *Ol;
    if (blockIdx.z == 0)      { Ah=A0h; Al=A0l;  Bh=B0; Bi=b0; Oh=O0h; Ol=O0l; }
    else if (blockIdx.z == 1) { Ah=A1h; Al=A1h;  Bh=B1; Bi=b1; Oh=O1h; Ol=nullptr; }
    else                      { Ah=A2h; Al=A2h;  Bh=B2; Bi=b2; Oh=O2h; Ol=nullptr; }
    const int mode = fused ? (int)blockIdx.z : 3;
    const bool twoTerm = fused && (blockIdx.z == 0);
    const uint32_t bstride = twoTerm ? (3 * GARR2) : (2 * GARR2);

    const int bm = blockIdx.y * 128, bn = blockIdx.x * 128;

    // per-lane swizzled ldmatrix address
    const uint32_t lrow = (uint32_t)(lid & 15) * 128;
    const uint32_t lhb = (uint32_t)(lid >> 4);
    const uint32_t lx7 = (uint32_t)(lid & 7);
    auto swa = [&](uint32_t base, uint32_t R, uint32_t cseg) {
        return base + R * 128 + lrow + ((((cseg | lhb)) ^ lx7) << 4);
    };

    float acc[4][4][4];
#pragma unroll
    for (int a = 0; a < 4; a++)
#pragma unroll
        for (int b = 0; b < 4; b++)
#pragma unroll
            for (int c = 0; c < 4; c++) acc[a][b][c] = 0.f;

    auto issue = [&](int ch, int buf) {
        uint32_t base = smb + buf * bstride;
#pragma unroll
        for (int j = 0; j < 4; j++) {
            int slot = tid + j * 256;          // 1024 = 128 rows x 8 segs
            int row = slot >> 3, seg = slot & 7;
            uint32_t doff = SWOFF(row, seg);
            bool ap = (bm + row) < M;
            size_t abyte = ((size_t)(bm + row) * CC + ch * 64) * 2 + seg * 16;
            size_t bbyte = ((size_t)(bn + row) * CC + ch * 64) * 2 + seg * 16;
            cp16(base + doff,             (const char*)Ah + abyte, ap);
            cp16(base + GARR2 + doff,     (const char*)Bh + bbyte, true);
            if (twoTerm)
                cp16(base + 2 * GARR2 + doff, (const char*)Al + abyte, ap);
        }
    };

    issue(0, 0);
    CP_COMMIT();

    for (int ch = 0; ch < 16; ch++) {
        CP_WAIT0();
        __syncthreads();
        if (ch < 15) { issue(ch + 1, (ch + 1) & 1); CP_COMMIT(); }

        const uint32_t base = smb + (ch & 1) * bstride;
#pragma unroll
        for (int ks = 0; ks < 4; ks++) {
            uint32_t Af[4][4], Al4[4][4], Bf[2][4];
#pragma unroll
            for (int mt = 0; mt < 4; mt++) {
                Af[mt][0] = 0;  // silence maybe-uninit; overwritten below
                ldm_x4(Af[mt], swa(base, (uint32_t)(wm * 64 + mt * 16), (uint32_t)(ks * 2)));
                if (twoTerm)
                    ldm_x4(Al4[mt], swa(base + 2 * GARR2, (uint32_t)(wm * 64 + mt * 16), (uint32_t)(ks * 2)));
            }
#pragma unroll
            for (int np = 0; np < 2; np++)
                ldm_x4(Bf[np], swa(base + GARR2, (uint32_t)(wn * 32 + np * 16), (uint32_t)(ks * 2)));
#pragma unroll
            for (int mt = 0; mt < 4; mt++)
#pragma unroll
                for (int nt = 0; nt < 4; nt++) {
                    uint32_t bb0 = Bf[nt >> 1][nt & 1];
                    uint32_t bb1 = Bf[nt >> 1][2 + (nt & 1)];
                    mma16816(acc[mt][nt], Af[mt], bb0, bb1);
                }
            if (twoTerm) {
#pragma unroll
                for (int mt = 0; mt < 4; mt++)
#pragma unroll
                    for (int nt = 0; nt < 4; nt++) {
                        uint32_t bb0 = Bf[nt >> 1][nt & 1];
                        uint32_t bb1 = Bf[nt >> 1][2 + (nt & 1)];
                        mma16816(acc[mt][nt], Al4[mt], bb0, bb1);
                    }
            }
        }
    }

    const int rbase = bm + wm * 64 + (lid >> 2);
    const int cbase = bn + wn * 32 + (lid & 3) * 2;
#pragma unroll
    for (int mt = 0; mt < 4; mt++) {
#pragma unroll
        for (int nt = 0; nt < 4; nt++) {
            int c = cbase + nt * 8;
            float2 bv = *(const float2*)(Bi + c);
#pragma unroll
            for (int half = 0; half < 2; half++) {
                int rr = rbase + mt * 16 + half * 8;
                if (rr >= M) continue;
                float v0 = acc[mt][nt][half * 2 + 0] + bv.x;
                float v1 = acc[mt][nt][half * 2 + 1] + bv.y;
                if (mode == 3) {
                    *(float2*)(F0 + (size_t)rr * CC + c) = make_float2(v0, v1);
                    continue;
                }
                if (mode <= 1) {
                    int d = c & 63;
                    if (d < LL) {
                        int t = rr % TT;
                        float f0 = rope[t * LL + d], f1 = rope[t * LL + d + 1];
                        float c0 = cosf(f0), s0f = sinf(f0);
                        float c1 = cosf(f1), s1f = sinf(f1);
                        float a = v0, bq2 = v1;
                        v0 = a * c0 - bq2 * s0f;
                        v1 = bq2 * c1 + a * s1f;
                    }
                    if (mode == 0) { v0 *= 0.125f; v1 *= 0.125f; }
                }
                size_t off = (size_t)rr * CC + c;
                if (Ol) {
                    uint32_t h, l;
                    pack_split(v0, v1, h, l);
                    *reinterpret_cast<uint32_t*>(Oh + off) = h;
                    *reinterpret_cast<uint32_t*>(Ol + off) = l;
                } else {
                    *reinterpret_cast<uint32_t*>(Oh + off) = pack_hi(v0, v1);
                }
            }
        }
    }
}

// ===========================================================================
// Tensor-core flash attention (unchanged from R14 best): S=(Qh+Ql)·Kh,
// O=Ph·Vh. 4 warps, XOR-swizzled 32 KB smem, 4 CTAs/SM, boundary-only mask.
// ===========================================================================
#define ABUF(b)  ((b) * 16384)
#define AKH(b)   (ABUF(b) + 0)
#define AVH(b)   (ABUF(b) + 8192)
#define AQH      (ABUF(1) + 0)
#define AQL      (ABUF(1) + 8192)
#define SMEM_ATTN 32768

__global__ void __launch_bounds__(128, 4) attn_tc_kernel(
    const __half* __restrict__ qh, const __half* __restrict__ ql,
    const __half* __restrict__ kh, const __half* __restrict__ vh,
    __half* __restrict__ oh)
{
    extern __shared__ char sm[];
    const uint32_t smb = smem_to_u32(sm);
    const int tid = threadIdx.x;
    const int l = tid & 31, w = tid >> 5;
    const int q0 = blockIdx.x * 64;
    const int h = blockIdx.y, b = blockIdx.z;
    const size_t rb = (size_t)b * TT * CC + (size_t)h * HD;

    const uint32_t lrow = (uint32_t)(l & 15) * 128;
    const uint32_t lhb = (uint32_t)(l >> 4);
    const uint32_t lx7 = (uint32_t)(l & 7);
    auto swa = [&](uint32_t base, uint32_t R, uint32_t cseg) {
        return base + R * 128 + lrow + ((((cseg | lhb)) ^ lx7) << 4);
    };

#pragma unroll
    for (int j = 0; j < 4; j++) {
        int slot = tid + j * 128;
        int row = slot >> 3, seg = slot & 7;
        bool p = (q0 + row) < TT;
        size_t byte = (rb + (size_t)(q0 + row) * CC) * 2 + seg * 16;
        uint32_t doff = SWOFF(row, seg);
        cp16(smb + AQH + doff, (const char*)qh + byte, p);
        cp16(smb + AQL + doff, (const char*)ql + byte, p);
    }
    CP_COMMIT();
    CP_WAIT0();
    __syncthreads();

    uint32_t Qf[4][4], Ql4[4][4];
#pragma unroll
    for (int ks = 0; ks < 4; ks++) {
        ldm_x4(Qf[ks],  swa(smb + AQH, (uint32_t)(w * 16), (uint32_t)(ks * 2)));
        ldm_x4(Ql4[ks], swa(smb + AQL, (uint32_t)(w * 16), (uint32_t)(ks * 2)));
    }
    __syncthreads();

    auto issue_kv = [&](int t, int buf) {
        int kv0 = t * 64;
#pragma unroll
        for (int j = 0; j < 4; j++) {
            int slot = tid + j * 128;
            int row = slot >> 3, seg = slot & 7;
            bool p = (kv0 + row) < TT;
            size_t byte = (rb + (size_t)(kv0 + row) * CC) * 2 + seg * 16;
            uint32_t doff = SWOFF(row, seg);
            cp16(smb + AKH(buf) + doff, (const char*)kh + byte, p);
            cp16(smb + AVH(buf) + doff, (const char*)vh + byte, p);
        }
    };

    issue_kv(0, 0);
    CP_COMMIT();

    int kv_end = q0 + COND + 63;
    if (kv_end > TT) kv_end = TT;
    const int nkv = (kv_end + 63) >> 6;

    const int qg0 = q0 + w * 16 + (l >> 2);
    const int qg1 = qg0 + 8;
    const int warp_qmin = q0 + w * 16;

    float Oacc[8][4];
#pragma unroll
    for (int i = 0; i < 8; i++)
#pragma unroll
        for (int j = 0; j < 4; j++) Oacc[i][j] = 0.f;
    float m0 = -1e30f, m1 = -1e30f, l0 = 0.f, l1 = 0.f;

    for (int t = 0; t < nkv; t++) {
        const int buf = t & 1;
        CP_WAIT0();
        __syncthreads();
        if (t + 1 < nkv) { issue_kv(t + 1, buf ^ 1); CP_COMMIT(); }

        const int kv0 = t * 64;
        float S[8][4];
#pragma unroll
        for (int i = 0; i < 8; i++)
#pragma unroll
            for (int j = 0; j < 4; j++) S[i][j] = 0.f;

#pragma unroll
        for (int ks = 0; ks < 4; ks++) {
            uint32_t Kf[4][4];
#pragma unroll
            for (int np = 0; np < 4; np++)
                ldm_x4(Kf[np], swa(smb + AKH(buf), (uint32_t)(np * 16), (uint32_t)(ks * 2)));
#pragma unroll
            for (int nt = 0; nt < 8; nt++) {
                uint32_t bh0 = Kf[nt >> 1][nt & 1];
                uint32_t bh1 = Kf[nt >> 1][2 + (nt & 1)];
                mma16816(S[nt], Qf[ks], bh0, bh1);
            }
#pragma unroll
            for (int nt = 0; nt < 8; nt++) {
                uint32_t bh0 = Kf[nt >> 1][nt & 1];
                uint32_t bh1 = Kf[nt >> 1][2 + (nt & 1)];
                mma16816(S[nt], Ql4[ks], bh0, bh1);
            }
        }

        if ((kv0 + 63 >= COND + warp_qmin) || (kv0 + 63 >= TT)) {
#pragma unroll
            for (int nt = 0; nt < 8; nt++) {
#pragma unroll
                for (int e = 0; e < 2; e++) {
                    int kvc = kv0 + nt * 8 + (l & 3) * 2 + e;
                    bool inb = kvc < TT;
                    if (!(inb && kvc < COND + qg0)) S[nt][e] = -1e30f;
                    if (!(inb && kvc < COND + qg1)) S[nt][2 + e] = -1e30f;
                }
            }
        }

        float mx0 = -1e30f, mx1 = -1e30f;
#pragma unroll
        for (int nt = 0; nt < 8; nt++) {
            mx0 = fmaxf(mx0, fmaxf(S[nt][0], S[nt][1]));
            mx1 = fmaxf(mx1, fmaxf(S[nt][2], S[nt][3]));
        }
        mx0 = fmaxf(mx0, __shfl_xor_sync(0xffffffffu, mx0, 1));
        mx0 = fmaxf(mx0, __shfl_xor_sync(0xffffffffu, mx0, 2));
        mx1 = fmaxf(mx1, __shfl_xor_sync(0xffffffffu, mx1, 1));
        mx1 = fmaxf(mx1, __shfl_xor_sync(0xffffffffu, mx1, 2));

        float mn0 = fmaxf(m0, mx0), mn1 = fmaxf(m1, mx1);
        float al0 = __expf(m0 - mn0), al1 = __expf(m1 - mn1);
        m0 = mn0; m1 = mn1;

        float s0 = 0.f, s1 = 0.f;
#pragma unroll
        for (int nt = 0; nt < 8; nt++) {
#pragma unroll
            for (int e = 0; e < 2; e++) {
                S[nt][e] = __expf(S[nt][e] - mn0);         s0 += S[nt][e];
                S[nt][2 + e] = __expf(S[nt][2 + e] - mn1); s1 += S[nt][2 + e];
            }
        }
        s0 += __shfl_xor_sync(0xffffffffu, s0, 1);
        s0 += __shfl_xor_sync(0xffffffffu, s0, 2);
        s1 += __shfl_xor_sync(0xffffffffu, s1, 1);
        s1 += __shfl_xor_sync(0xffffffffu, s1, 2);
        l0 = l0 * al0 + s0;
        l1 = l1 * al1 + s1;

#pragma unroll
        for (int nt = 0; nt < 8; nt++) {
            Oacc[nt][0] *= al0; Oacc[nt][1] *= al0;
            Oacc[nt][2] *= al1; Oacc[nt][3] *= al1;
        }

#pragma unroll
        for (int ks = 0; ks < 4; ks++) {
            uint32_t Ph[4];
            Ph[0] = pack_hi(S[2 * ks][0],     S[2 * ks][1]);
            Ph[1] = pack_hi(S[2 * ks][2],     S[2 * ks][3]);
            Ph[2] = pack_hi(S[2 * ks + 1][0], S[2 * ks + 1][1]);
            Ph[3] = pack_hi(S[2 * ks + 1][2], S[2 * ks + 1][3]);

            uint32_t Vf[4][4];
#pragma unroll
            for (int np = 0; np < 4; np++)
                ldm_x4_t(Vf[np], swa(smb + AVH(buf), (uint32_t)(ks * 16), (uint32_t)(np * 2)));
#pragma unroll
            for (int nt = 0; nt < 8; nt++) {
                uint32_t bh0 = Vf[nt >> 1][(nt & 1) * 2];
                uint32_t bh1 = Vf[nt >> 1][(nt & 1) * 2 + 1];
                mma16816(Oacc[nt], Ph, bh0, bh1);
            }
        }
    }

    float inv0 = 1.f / l0, inv1 = 1.f / l1;
#pragma unroll
    for (int nt = 0; nt < 8; nt++) {
        int c = nt * 8 + (l & 3) * 2;
        if (qg0 < TT) {
            size_t off = rb + (size_t)qg0 * CC + c;
            *reinterpret_cast<uint32_t*>(oh + off) =
                pack_hi(Oacc[nt][0] * inv0, Oacc[nt][1] * inv0);
        }
        if (qg1 < TT) {
            size_t off = rb + (size_t)qg1 * CC + c;
            *reinterpret_cast<uint32_t*>(oh + off) =
                pack_hi(Oacc[nt][2] * inv1, Oacc[nt][3] * inv1);
        }
    }
}

// ---------------------------------------------------------------------------
// Launch
// ---------------------------------------------------------------------------
extern "C" void kernel_launch(void* const* d_in, const int* in_sizes, int n_in,
                              void* d_out, int out_size)
{
    const float* x_q  = (const float*)d_in[0];
    const float* x_kv = (const float*)d_in[1];
    const float* rope = (const float*)d_in[2];
    const float* Wq   = (const float*)d_in[3];
    const float* bq   = (const float*)d_in[4];
    const float* Wk   = (const float*)d_in[5];
    const float* bk   = (const float*)d_in[6];
    const float* Wv   = (const float*)d_in[7];
    const float* bv   = (const float*)d_in[8];
    const float* Wp   = (const float*)d_in[9];
    const float* bp   = (const float*)d_in[10];
    float* out = (float*)d_out;

    __half *xqh, *xql, *xkh, *Wh;
    __half *qh, *ql, *kh, *vh, *ah;
    cudaGetSymbolAddress((void**)&xqh, g_xqh);
    cudaGetSymbolAddress((void**)&xql, g_xql);
    cudaGetSymbolAddress((void**)&xkh, g_xkh);
    cudaGetSymbolAddress((void**)&Wh,  g_Wh);
    cudaGetSymbolAddress((void**)&qh,  g_qh);
    cudaGetSymbolAddress((void**)&ql,  g_ql);
    cudaGetSymbolAddress((void**)&kh,  g_kh);
    cudaGetSymbolAddress((void**)&vh,  g_vh);
    cudaGetSymbolAddress((void**)&ah,  g_ah);

    cudaFuncSetAttribute(gemm_tc_kernel,
        cudaFuncAttributeMaxDynamicSharedMemorySize, 2 * 3 * GARR2);  // 98304
    cudaFuncSetAttribute(attn_tc_kernel,
        cudaFuncAttributeMaxDynamicSharedMemorySize, SMEM_ATTN);

    // 1) one-time splits: x_q hi/lo, x_kv hi, W hi
    const int NX4 = MROWS * CC / 4;
    const int NW4 = CC * CC / 4;
    dim3 split_grid((NX4 + 255) / 256, 6);
    split6_kernel<<<split_grid, 256>>>(
        x_q,  xqh, xql, NX4,
        x_kv, xkh, nullptr, NX4,
        Wq, Wh,              nullptr, NW4,
        Wk, Wh + CC * CC,     nullptr, NW4,
        Wv, Wh + 2 * CC * CC, nullptr, NW4,
        Wp, Wh + 3 * CC * CC, nullptr, NW4);

    // 2) fused Q/K/V projections; q 2-term split-out, k/v 1-term hi-out
    dim3 g_qkv(CC / 128, (MROWS + 127) / 128, 3);   // (8, 49, 3)
    gemm_tc_kernel<<<g_qkv, 256, 2 * 3 * GARR2>>>(
        xqh, xql, Wh,              bq, qh, ql, nullptr,
        xkh,      Wh + CC * CC,     bk, kh,
        xkh,      Wh + 2 * CC * CC, bv, vh,
        rope, 1, MROWS);

    // 3) tensor-core attention -> hi-only output
    dim3 attn_grid((TT + 63) / 64, HH, BB);         // (13, 16, 8)
    attn_tc_kernel<<<attn_grid, 128, SMEM_ATTN>>>(qh, ql, kh, vh, ah);

    // 4) output projection, 1-term, f32 epilogue (64KB smem)
    dim3 g_out(CC / 128, (MROWS + 127) / 128, 1);
    gemm_tc_kernel<<<g_out, 256, 2 * 2 * GARR2>>>(
        ah, ah, Wh + 3 * CC * CC, bp, nullptr, nullptr, out,
        ah,     Wh + 3 * CC * CC, bp, nullptr,
        ah,     Wh + 3 * CC * CC, bp, nullptr,
        rope, 0, MROWS);
}

// round 16
// speedup vs baseline: 1.8811x; 1.0387x over previous
#include <cuda_runtime.h>
#include <cuda_fp16.h>
#include <math.h>
#include <stdint.h>

#define BB 8
#define TT 769
#define CC 1024
#define HH 16
#define HD 64
#define LL 32
#define COND 256
#define MROWS (BB*TT)   // 6152

// ---------------------------------------------------------------------------
// Device scratch (allocation-free requirement -> globals)  [fp16]
// ---------------------------------------------------------------------------
__device__ __half g_xqh[(size_t)MROWS * CC], g_xql[(size_t)MROWS * CC];
__device__ __half g_xkh[(size_t)MROWS * CC];          // x_kv: hi only
__device__ __half g_Wh[(size_t)4 * CC * CC];          // W: hi only
__device__ __half g_qh[(size_t)MROWS * CC], g_ql[(size_t)MROWS * CC];
__device__ __half g_kh[(size_t)MROWS * CC];           // K: hi only
__device__ __half g_vh[(size_t)MROWS * CC];           // V: hi only
__device__ __half g_ah[(size_t)MROWS * CC];           // attn out: hi only

// ---------------------------------------------------------------------------
// Helpers
// ---------------------------------------------------------------------------
__device__ __forceinline__ uint32_t smem_to_u32(const void* p) {
    uint32_t a;
    asm("{ .reg .u64 t; cvta.to.shared.u64 t, %1; cvt.u32.u64 %0, t; }"
        : "=r"(a) : "l"(p));
    return a;
}
__device__ __forceinline__ void ldm_x4(uint32_t* r, uint32_t addr) {
    asm volatile("ldmatrix.sync.aligned.m8n8.x4.shared.b16 {%0,%1,%2,%3}, [%4];"
        : "=r"(r[0]), "=r"(r[1]), "=r"(r[2]), "=r"(r[3]) : "r"(addr));
}
__device__ __forceinline__ void ldm_x4_t(uint32_t* r, uint32_t addr) {
    asm volatile("ldmatrix.sync.aligned.m8n8.x4.trans.shared.b16 {%0,%1,%2,%3}, [%4];"
        : "=r"(r[0]), "=r"(r[1]), "=r"(r[2]), "=r"(r[3]) : "r"(addr));
}
__device__ __forceinline__ void mma16816(float* d, const uint32_t* a,
                                         uint32_t b0, uint32_t b1) {
    asm("mma.sync.aligned.m16n8k16.row.col.f32.f16.f16.f32 "
        "{%0,%1,%2,%3}, {%4,%5,%6,%7}, {%8,%9}, {%0,%1,%2,%3};"
        : "+f"(d[0]), "+f"(d[1]), "+f"(d[2]), "+f"(d[3])
        : "r"(a[0]), "r"(a[1]), "r"(a[2]), "r"(a[3]), "r"(b0), "r"(b1));
}
__device__ __forceinline__ void cp16(uint32_t dst, const void* src, bool pred) {
    int n = pred ? 16 : 0;
    asm volatile("cp.async.cg.shared.global [%0], [%1], 16, %2;"
        :: "r"(dst), "l"(src), "r"(n) : "memory");
}
#define CP_COMMIT() asm volatile("cp.async.commit_group;" ::: "memory")
#define CP_WAIT0()  asm volatile("cp.async.wait_group 0;" ::: "memory")

// pack 2 floats -> half2 hi + half2 residual-lo
__device__ __forceinline__ void pack_split(float x, float y,
                                           uint32_t& hi, uint32_t& lo) {
    __half2 h = __floats2half2_rn(x, y);
    float hx = __low2float(h), hy = __high2float(h);
    __half2 l2 = __floats2half2_rn(x - hx, y - hy);
    hi = *reinterpret_cast<uint32_t*>(&h);
    lo = *reinterpret_cast<uint32_t*>(&l2);
}
__device__ __forceinline__ uint32_t pack_hi(float x, float y) {
    __half2 h = __floats2half2_rn(x, y);
    return *reinterpret_cast<uint32_t*>(&h);
}

// XOR-swizzled byte offset within a (rows x 128B) tile
#define SWOFF(row, seg) ((uint32_t)((row) * 128 + ((((seg) ^ ((row) & 7))) << 4)))

// ---------------------------------------------------------------------------
// One launch for all 6 one-time splits. lo==nullptr -> hi-only.
// ---------------------------------------------------------------------------
__global__ void split6_kernel(
    const float* __restrict__ s0, __half* __restrict__ h0, __half* __restrict__ l0, int n0,
    const float* __restrict__ s1, __half* __restrict__ h1, __half* __restrict__ l1, int n1,
    const float* __restrict__ s2, __half* __restrict__ h2, __half* __restrict__ l2, int n2,
    const float* __restrict__ s3, __half* __restrict__ h3, __half* __restrict__ l3, int n3,
    const float* __restrict__ s4, __half* __restrict__ h4, __half* __restrict__ l4, int n4,
    const float* __restrict__ s5, __half* __restrict__ h5, __half* __restrict__ l5, int n5)
{
    const float* src; __half *hi, *lo; int n;
    switch (blockIdx.y) {
        case 0: src = s0; hi = h0; lo = l0; n = n0; break;
        case 1: src = s1; hi = h1; lo = l1; n = n1; break;
        case 2: src = s2; hi = h2; lo = l2; n = n2; break;
        case 3: src = s3; hi = h3; lo = l3; n = n3; break;
        case 4: src = s4; hi = h4; lo = l4; n = n4; break;
        default: src = s5; hi = h5; lo = l5; n = n5; break;
    }
    int idx = blockIdx.x * blockDim.x + threadIdx.x;
    if (idx >= n) return;
    float4 v = reinterpret_cast<const float4*>(src)[idx];
    if (lo) {
        uint2 h, l;
        pack_split(v.x, v.y, h.x, l.x);
        pack_split(v.z, v.w, h.y, l.y);
        reinterpret_cast<uint2*>(hi)[idx] = h;
        reinterpret_cast<uint2*>(lo)[idx] = l;
    } else {
        uint2 h;
        h.x = pack_hi(v.x, v.y);
        h.y = pack_hi(v.z, v.w);
        reinterpret_cast<uint2*>(hi)[idx] = h;
    }
}

// ===========================================================================
// QKV GEMM (unchanged from R15 best): 128x128 tile, k-chunk 64, XOR-swizzle,
// 2 CTAs/SM. q 2-term, k/v 1-term, fused rotary/scale/split epilogues.
// ===========================================================================
#define GARR2 16384

__global__ void __launch_bounds__(256, 2) gemm_tc_kernel(
    const __half* __restrict__ A0h, const __half* __restrict__ A0l,
    const __half* __restrict__ B0, const float* __restrict__ b0,
    __half* __restrict__ O0h, __half* __restrict__ O0l,
    const __half* __restrict__ A1h,
    const __half* __restrict__ B1, const float* __restrict__ b1,
    __half* __restrict__ O1h,
    const __half* __restrict__ A2h,
    const __half* __restrict__ B2, const float* __restrict__ b2,
    __half* __restrict__ O2h,
    const float* __restrict__ rope, int M)
{
    extern __shared__ char sm[];
    const uint32_t smb = smem_to_u32(sm);
    const int tid = threadIdx.x;
    const int lid = tid & 31;
    const int wid = tid >> 5;
    const int wm = wid >> 2, wn = wid & 3;

    const __half *Ah, *Al, *Bh;
    const float* Bi;
    __half *Oh, *Ol;
    if (blockIdx.z == 0)      { Ah=A0h; Al=A0l;  Bh=B0; Bi=b0; Oh=O0h; Ol=O0l; }
    else if (blockIdx.z == 1) { Ah=A1h; Al=A1h;  Bh=B1; Bi=b1; Oh=O1h; Ol=nullptr; }
    else                      { Ah=A2h; Al=A2h;  Bh=B2; Bi=b2; Oh=O2h; Ol=nullptr; }
    const int mode = (int)blockIdx.z;
    const bool twoTerm = (blockIdx.z == 0);
    const uint32_t bstride = twoTerm ? (3 * GARR2) : (2 * GARR2);

    const int bm = blockIdx.y * 128, bn = blockIdx.x * 128;

    const uint32_t lrow = (uint32_t)(lid & 15) * 128;
    const uint32_t lhb = (uint32_t)(lid >> 4);
    const uint32_t lx7 = (uint32_t)(lid & 7);
    auto swa = [&](uint32_t base, uint32_t R, uint32_t cseg) {
        return base + R * 128 + lrow + ((((cseg | lhb)) ^ lx7) << 4);
    };

    float acc[4][4][4];
#pragma unroll
    for (int a = 0; a < 4; a++)
#pragma unroll
        for (int b = 0; b < 4; b++)
#pragma unroll
            for (int c = 0; c < 4; c++) acc[a][b][c] = 0.f;

    auto issue = [&](int ch, int buf) {
        uint32_t base = smb + buf * bstride;
#pragma unroll
        for (int j = 0; j < 4; j++) {
            int slot = tid + j * 256;
            int row = slot >> 3, seg = slot & 7;
            uint32_t doff = SWOFF(row, seg);
            bool ap = (bm + row) < M;
            size_t abyte = ((size_t)(bm + row) * CC + ch * 64) * 2 + seg * 16;
            size_t bbyte = ((size_t)(bn + row) * CC + ch * 64) * 2 + seg * 16;
            cp16(base + doff,             (const char*)Ah + abyte, ap);
            cp16(base + GARR2 + doff,     (const char*)Bh + bbyte, true);
            if (twoTerm)
                cp16(base + 2 * GARR2 + doff, (const char*)Al + abyte, ap);
        }
    };

    issue(0, 0);
    CP_COMMIT();

    for (int ch = 0; ch < 16; ch++) {
        CP_WAIT0();
        __syncthreads();
        if (ch < 15) { issue(ch + 1, (ch + 1) & 1); CP_COMMIT(); }

        const uint32_t base = smb + (ch & 1) * bstride;
#pragma unroll
        for (int ks = 0; ks < 4; ks++) {
            uint32_t Af[4][4], Al4[4][4], Bf[2][4];
#pragma unroll
            for (int mt = 0; mt < 4; mt++) {
                ldm_x4(Af[mt], swa(base, (uint32_t)(wm * 64 + mt * 16), (uint32_t)(ks * 2)));
                if (twoTerm)
                    ldm_x4(Al4[mt], swa(base + 2 * GARR2, (uint32_t)(wm * 64 + mt * 16), (uint32_t)(ks * 2)));
            }
#pragma unroll
            for (int np = 0; np < 2; np++)
                ldm_x4(Bf[np], swa(base + GARR2, (uint32_t)(wn * 32 + np * 16), (uint32_t)(ks * 2)));
#pragma unroll
            for (int mt = 0; mt < 4; mt++)
#pragma unroll
                for (int nt = 0; nt < 4; nt++) {
                    uint32_t bb0 = Bf[nt >> 1][nt & 1];
                    uint32_t bb1 = Bf[nt >> 1][2 + (nt & 1)];
                    mma16816(acc[mt][nt], Af[mt], bb0, bb1);
                }
            if (twoTerm) {
#pragma unroll
                for (int mt = 0; mt < 4; mt++)
#pragma unroll
                    for (int nt = 0; nt < 4; nt++) {
                        uint32_t bb0 = Bf[nt >> 1][nt & 1];
                        uint32_t bb1 = Bf[nt >> 1][2 + (nt & 1)];
                        mma16816(acc[mt][nt], Al4[mt], bb0, bb1);
                    }
            }
        }
    }

    const int rbase = bm + wm * 64 + (lid >> 2);
    const int cbase = bn + wn * 32 + (lid & 3) * 2;
#pragma unroll
    for (int mt = 0; mt < 4; mt++) {
#pragma unroll
        for (int nt = 0; nt < 4; nt++) {
            int c = cbase + nt * 8;
            float2 bv = *(const float2*)(Bi + c);
#pragma unroll
            for (int half = 0; half < 2; half++) {
                int rr = rbase + mt * 16 + half * 8;
                if (rr >= M) continue;
                float v0 = acc[mt][nt][half * 2 + 0] + bv.x;
                float v1 = acc[mt][nt][half * 2 + 1] + bv.y;
                if (mode <= 1) {
                    int d = c & 63;
                    if (d < LL) {
                        int t = rr % TT;
                        float f0 = rope[t * LL + d], f1 = rope[t * LL + d + 1];
                        float c0 = cosf(f0), s0f = sinf(f0);
                        float c1 = cosf(f1), s1f = sinf(f1);
                        float a = v0, bq2 = v1;
                        v0 = a * c0 - bq2 * s0f;
                        v1 = bq2 * c1 + a * s1f;
                    }
                    if (mode == 0) { v0 *= 0.125f; v1 *= 0.125f; }
                }
                size_t off = (size_t)rr * CC + c;
                if (Ol) {
                    uint32_t h, l;
                    pack_split(v0, v1, h, l);
                    *reinterpret_cast<uint32_t*>(Oh + off) = h;
                    *reinterpret_cast<uint32_t*>(Ol + off) = l;
                } else {
                    *reinterpret_cast<uint32_t*>(Oh + off) = pack_hi(v0, v1);
                }
            }
        }
    }
}

// ===========================================================================
// Out-proj GEMM: 64x128 tile, 128 threads (4 warps x 64x32), k-chunk 64,
// 1-term fp16, f32 epilogue. smem: 2 bufs x (A 8KB + B 16KB) = 48KB ->
// up to 4 CTAs/SM. Finer tiles fix the 1.32-wave quantization of the
// 128-row version (392 CTAs / 296 slots -> 2 full waves).
// ===========================================================================
#define OA 8192          // A array bytes (64 x 128B)
#define OB 16384         // B array bytes (128 x 128B)
#define OBUF (OA + OB)   // 24576 per buffer

__global__ void __launch_bounds__(128, 4) gemm_out_kernel(
    const __half* __restrict__ A, const __half* __restrict__ B,
    const float* __restrict__ bias, float* __restrict__ Y, int M)
{
    extern __shared__ char sm[];
    const uint32_t smb = smem_to_u32(sm);
    const int tid = threadIdx.x;
    const int lid = tid & 31;
    const int wn = tid >> 5;           // 0..3

    const int bm = blockIdx.y * 64, bn = blockIdx.x * 128;

    const uint32_t lrow = (uint32_t)(lid & 15) * 128;
    const uint32_t lhb = (uint32_t)(lid >> 4);
    const uint32_t lx7 = (uint32_t)(lid & 7);
    auto swa = [&](uint32_t base, uint32_t R, uint32_t cseg) {
        return base + R * 128 + lrow + ((((cseg | lhb)) ^ lx7) << 4);
    };

    float acc[4][4][4];
#pragma unroll
    for (int a = 0; a < 4; a++)
#pragma unroll
        for (int b = 0; b < 4; b++)
#pragma unroll
            for (int c = 0; c < 4; c++) acc[a][b][c] = 0.f;

    auto issue = [&](int ch, int buf) {
        uint32_t base = smb + buf * OBUF;
        // A: 512 slots (64 rows x 8 segs), 4/thread
#pragma unroll
        for (int j = 0; j < 4; j++) {
            int slot = tid + j * 128;
            int row = slot >> 3, seg = slot & 7;
            bool ap = (bm + row) < M;
            size_t abyte = ((size_t)(bm + row) * CC + ch * 64) * 2 + seg * 16;
            cp16(base + SWOFF(row, seg), (const char*)A + abyte, ap);
        }
        // B: 1024 slots (128 rows x 8 segs), 8/thread
#pragma unroll
        for (int j = 0; j < 8; j++) {
            int slot = tid + j * 128;
            int row = slot >> 3, seg = slot & 7;
            size_t bbyte = ((size_t)(bn + row) * CC + ch * 64) * 2 + seg * 16;
            cp16(base + OA + SWOFF(row, seg), (const char*)B + bbyte, true);
        }
    };

    issue(0, 0);
    CP_COMMIT();

    for (int ch = 0; ch < 16; ch++) {
        CP_WAIT0();
        __syncthreads();
        if (ch < 15) { issue(ch + 1, (ch + 1) & 1); CP_COMMIT(); }

        const uint32_t base = smb + (ch & 1) * OBUF;
#pragma unroll
        for (int ks = 0; ks < 4; ks++) {
            uint32_t Af[4][4], Bf[2][4];
#pragma unroll
            for (int mt = 0; mt < 4; mt++)
                ldm_x4(Af[mt], swa(base, (uint32_t)(mt * 16), (uint32_t)(ks * 2)));
#pragma unroll
            for (int np = 0; np < 2; np++)
                ldm_x4(Bf[np], swa(base + OA, (uint32_t)(wn * 32 + np * 16), (uint32_t)(ks * 2)));
#pragma unroll
            for (int mt = 0; mt < 4; mt++)
#pragma unroll
                for (int nt = 0; nt < 4; nt++) {
                    uint32_t bb0 = Bf[nt >> 1][nt & 1];
                    uint32_t bb1 = Bf[nt >> 1][2 + (nt & 1)];
                    mma16816(acc[mt][nt], Af[mt], bb0, bb1);
                }
        }
    }

    const int rbase = bm + (lid >> 2);
    const int cbase = bn + wn * 32 + (lid & 3) * 2;
#pragma unroll
    for (int mt = 0; mt < 4; mt++) {
#pragma unroll
        for (int nt = 0; nt < 4; nt++) {
            int c = cbase + nt * 8;
            float2 bv = *(const float2*)(bias + c);
#pragma unroll
            for (int half = 0; half < 2; half++) {
                int rr = rbase + mt * 16 + half * 8;
                if (rr >= M) continue;
                *(float2*)(Y + (size_t)rr * CC + c) = make_float2(
                    acc[mt][nt][half * 2 + 0] + bv.x,
                    acc[mt][nt][half * 2 + 1] + bv.y);
            }
        }
    }
}

// ===========================================================================
// Tensor-core flash attention (unchanged from R14/R15 best).
// ===========================================================================
#define ABUF(b)  ((b) * 16384)
#define AKH(b)   (ABUF(b) + 0)
#define AVH(b)   (ABUF(b) + 8192)
#define AQH      (ABUF(1) + 0)
#define AQL      (ABUF(1) + 8192)
#define SMEM_ATTN 32768

__global__ void __launch_bounds__(128, 4) attn_tc_kernel(
    const __half* __restrict__ qh, const __half* __restrict__ ql,
    const __half* __restrict__ kh, const __half* __restrict__ vh,
    __half* __restrict__ oh)
{
    extern __shared__ char sm[];
    const uint32_t smb = smem_to_u32(sm);
    const int tid = threadIdx.x;
    const int l = tid & 31, w = tid >> 5;
    const int q0 = blockIdx.x * 64;
    const int h = blockIdx.y, b = blockIdx.z;
    const size_t rb = (size_t)b * TT * CC + (size_t)h * HD;

    const uint32_t lrow = (uint32_t)(l & 15) * 128;
    const uint32_t lhb = (uint32_t)(l >> 4);
    const uint32_t lx7 = (uint32_t)(l & 7);
    auto swa = [&](uint32_t base, uint32_t R, uint32_t cseg) {
        return base + R * 128 + lrow + ((((cseg | lhb)) ^ lx7) << 4);
    };

#pragma unroll
    for (int j = 0; j < 4; j++) {
        int slot = tid + j * 128;
        int row = slot >> 3, seg = slot & 7;
        bool p = (q0 + row) < TT;
        size_t byte = (rb + (size_t)(q0 + row) * CC) * 2 + seg * 16;
        uint32_t doff = SWOFF(row, seg);
        cp16(smb + AQH + doff, (const char*)qh + byte, p);
        cp16(smb + AQL + doff, (const char*)ql + byte, p);
    }
    CP_COMMIT();
    CP_WAIT0();
    __syncthreads();

    uint32_t Qf[4][4], Ql4[4][4];
#pragma unroll
    for (int ks = 0; ks < 4; ks++) {
        ldm_x4(Qf[ks],  swa(smb + AQH, (uint32_t)(w * 16), (uint32_t)(ks * 2)));
        ldm_x4(Ql4[ks], swa(smb + AQL, (uint32_t)(w * 16), (uint32_t)(ks * 2)));
    }
    __syncthreads();

    auto issue_kv = [&](int t, int buf) {
        int kv0 = t * 64;
#pragma unroll
        for (int j = 0; j < 4; j++) {
            int slot = tid + j * 128;
            int row = slot >> 3, seg = slot & 7;
            bool p = (kv0 + row) < TT;
            size_t byte = (rb + (size_t)(kv0 + row) * CC) * 2 + seg * 16;
            uint32_t doff = SWOFF(row, seg);
            cp16(smb + AKH(buf) + doff, (const char*)kh + byte, p);
            cp16(smb + AVH(buf) + doff, (const char*)vh + byte, p);
        }
    };

    issue_kv(0, 0);
    CP_COMMIT();

    int kv_end = q0 + COND + 63;
    if (kv_end > TT) kv_end = TT;
    const int nkv = (kv_end + 63) >> 6;

    const int qg0 = q0 + w * 16 + (l >> 2);
    const int qg1 = qg0 + 8;
    const int warp_qmin = q0 + w * 16;

    float Oacc[8][4];
#pragma unroll
    for (int i = 0; i < 8; i++)
#pragma unroll
        for (int j = 0; j < 4; j++) Oacc[i][j] = 0.f;
    float m0 = -1e30f, m1 = -1e30f, l0 = 0.f, l1 = 0.f;

    for (int t = 0; t < nkv; t++) {
        const int buf = t & 1;
        CP_WAIT0();
        __syncthreads();
        if (t + 1 < nkv) { issue_kv(t + 1, buf ^ 1); CP_COMMIT(); }

        const int kv0 = t * 64;
        float S[8][4];
#pragma unroll
        for (int i = 0; i < 8; i++)
#pragma unroll
            for (int j = 0; j < 4; j++) S[i][j] = 0.f;

#pragma unroll
        for (int ks = 0; ks < 4; ks++) {
            uint32_t Kf[4][4];
#pragma unroll
            for (int np = 0; np < 4; np++)
                ldm_x4(Kf[np], swa(smb + AKH(buf), (uint32_t)(np * 16), (uint32_t)(ks * 2)));
#pragma unroll
            for (int nt = 0; nt < 8; nt++) {
                uint32_t bh0 = Kf[nt >> 1][nt & 1];
                uint32_t bh1 = Kf[nt >> 1][2 + (nt & 1)];
                mma16816(S[nt], Qf[ks], bh0, bh1);
            }
#pragma unroll
            for (int nt = 0; nt < 8; nt++) {
                uint32_t bh0 = Kf[nt >> 1][nt & 1];
                uint32_t bh1 = Kf[nt >> 1][2 + (nt & 1)];
                mma16816(S[nt], Ql4[ks], bh0, bh1);
            }
        }

        if ((kv0 + 63 >= COND + warp_qmin) || (kv0 + 63 >= TT)) {
#pragma unroll
            for (int nt = 0; nt < 8; nt++) {
#pragma unroll
                for (int e = 0; e < 2; e++) {
                    int kvc = kv0 + nt * 8 + (l & 3) * 2 + e;
                    bool inb = kvc < TT;
                    if (!(inb && kvc < COND + qg0)) S[nt][e] = -1e30f;
                    if (!(inb && kvc < COND + qg1)) S[nt][2 + e] = -1e30f;
                }
            }
        }

        float mx0 = -1e30f, mx1 = -1e30f;
#pragma unroll
        for (int nt = 0; nt < 8; nt++) {
            mx0 = fmaxf(mx0, fmaxf(S[nt][0], S[nt][1]));
            mx1 = fmaxf(mx1, fmaxf(S[nt][2], S[nt][3]));
        }
        mx0 = fmaxf(mx0, __shfl_xor_sync(0xffffffffu, mx0, 1));
        mx0 = fmaxf(mx0, __shfl_xor_sync(0xffffffffu, mx0, 2));
        mx1 = fmaxf(mx1, __shfl_xor_sync(0xffffffffu, mx1, 1));
        mx1 = fmaxf(mx1, __shfl_xor_sync(0xffffffffu, mx1, 2));

        float mn0 = fmaxf(m0, mx0), mn1 = fmaxf(m1, mx1);
        float al0 = __expf(m0 - mn0), al1 = __expf(m1 - mn1);
        m0 = mn0; m1 = mn1;

        float s0 = 0.f, s1 = 0.f;
#pragma unroll
        for (int nt = 0; nt < 8; nt++) {
#pragma unroll
            for (int e = 0; e < 2; e++) {
                S[nt][e] = __expf(S[nt][e] - mn0);         s0 += S[nt][e];
                S[nt][2 + e] = __expf(S[nt][2 + e] - mn1); s1 += S[nt][2 + e];
            }
        }
        s0 += __shfl_xor_sync(0xffffffffu, s0, 1);
        s0 += __shfl_xor_sync(0xffffffffu, s0, 2);
        s1 += __shfl_xor_sync(0xffffffffu, s1, 1);
        s1 += __shfl_xor_sync(0xffffffffu, s1, 2);
        l0 = l0 * al0 + s0;
        l1 = l1 * al1 + s1;

#pragma unroll
        for (int nt = 0; nt < 8; nt++) {
            Oacc[nt][0] *= al0; Oacc[nt][1] *= al0;
            Oacc[nt][2] *= al1; Oacc[nt][3] *= al1;
        }

#pragma unroll
        for (int ks = 0; ks < 4; ks++) {
            uint32_t Ph[4];
            Ph[0] = pack_hi(S[2 * ks][0],     S[2 * ks][1]);
            Ph[1] = pack_hi(S[2 * ks][2],     S[2 * ks][3]);
            Ph[2] = pack_hi(S[2 * ks + 1][0], S[2 * ks + 1][1]);
            Ph[3] = pack_hi(S[2 * ks + 1][2], S[2 * ks + 1][3]);

            uint32_t Vf[4][4];
#pragma unroll
            for (int np = 0; np < 4; np++)
                ldm_x4_t(Vf[np], swa(smb + AVH(buf), (uint32_t)(ks * 16), (uint32_t)(np * 2)));
#pragma unroll
            for (int nt = 0; nt < 8; nt++) {
                uint32_t bh0 = Vf[nt >> 1][(nt & 1) * 2];
                uint32_t bh1 = Vf[nt >> 1][(nt & 1) * 2 + 1];
                mma16816(Oacc[nt], Ph, bh0, bh1);
            }
        }
    }

    float inv0 = 1.f / l0, inv1 = 1.f / l1;
#pragma unroll
    for (int nt = 0; nt < 8; nt++) {
        int c = nt * 8 + (l & 3) * 2;
        if (qg0 < TT) {
            size_t off = rb + (size_t)qg0 * CC + c;
            *reinterpret_cast<uint32_t*>(oh + off) =
                pack_hi(Oacc[nt][0] * inv0, Oacc[nt][1] * inv0);
        }
        if (qg1 < TT) {
            size_t off = rb + (size_t)qg1 * CC + c;
            *reinterpret_cast<uint32_t*>(oh + off) =
                pack_hi(Oacc[nt][2] * inv1, Oacc[nt][3] * inv1);
        }
    }
}

// ---------------------------------------------------------------------------
// Launch
// ---------------------------------------------------------------------------
extern "C" void kernel_launch(void* const* d_in, const int* in_sizes, int n_in,
                              void* d_out, int out_size)
{
    const float* x_q  = (const float*)d_in[0];
    const float* x_kv = (const float*)d_in[1];
    const float* rope = (const float*)d_in[2];
    const float* Wq   = (const float*)d_in[3];
    const float* bq   = (const float*)d_in[4];
    const float* Wk   = (const float*)d_in[5];
    const float* bk   = (const float*)d_in[6];
    const float* Wv   = (const float*)d_in[7];
    const float* bv   = (const float*)d_in[8];
    const float* Wp   = (const float*)d_in[9];
    const float* bp   = (const float*)d_in[10];
    float* out = (float*)d_out;

    __half *xqh, *xql, *xkh, *Wh;
    __half *qh, *ql, *kh, *vh, *ah;
    cudaGetSymbolAddress((void**)&xqh, g_xqh);
    cudaGetSymbolAddress((void**)&xql, g_xql);
    cudaGetSymbolAddress((void**)&xkh, g_xkh);
    cudaGetSymbolAddress((void**)&Wh,  g_Wh);
    cudaGetSymbolAddress((void**)&qh,  g_qh);
    cudaGetSymbolAddress((void**)&ql,  g_ql);
    cudaGetSymbolAddress((void**)&kh,  g_kh);
    cudaGetSymbolAddress((void**)&vh,  g_vh);
    cudaGetSymbolAddress((void**)&ah,  g_ah);

    cudaFuncSetAttribute(gemm_tc_kernel,
        cudaFuncAttributeMaxDynamicSharedMemorySize, 2 * 3 * GARR2);  // 98304
    cudaFuncSetAttribute(gemm_out_kernel,
        cudaFuncAttributeMaxDynamicSharedMemorySize, 2 * OBUF);       // 49152
    cudaFuncSetAttribute(attn_tc_kernel,
        cudaFuncAttributeMaxDynamicSharedMemorySize, SMEM_ATTN);

    // 1) one-time splits: x_q hi/lo, x_kv hi, W hi
    const int NX4 = MROWS * CC / 4;
    const int NW4 = CC * CC / 4;
    dim3 split_grid((NX4 + 255) / 256, 6);
    split6_kernel<<<split_grid, 256>>>(
        x_q,  xqh, xql, NX4,
        x_kv, xkh, nullptr, NX4,
        Wq, Wh,              nullptr, NW4,
        Wk, Wh + CC * CC,     nullptr, NW4,
        Wv, Wh + 2 * CC * CC, nullptr, NW4,
        Wp, Wh + 3 * CC * CC, nullptr, NW4);

    // 2) fused Q/K/V projections; q 2-term split-out, k/v 1-term hi-out
    dim3 g_qkv(CC / 128, (MROWS + 127) / 128, 3);   // (8, 49, 3)
    gemm_tc_kernel<<<g_qkv, 256, 2 * 3 * GARR2>>>(
        xqh, xql, Wh,              bq, qh, ql,
        xkh,      Wh + CC * CC,     bk, kh,
        xkh,      Wh + 2 * CC * CC, bv, vh,
        rope, MROWS);

    // 3) tensor-core attention -> hi-only output
    dim3 attn_grid((TT + 63) / 64, HH, BB);         // (13, 16, 8)
    attn_tc_kernel<<<attn_grid, 128, SMEM_ATTN>>>(qh, ql, kh, vh, ah);

    // 4) output projection: 64x128 tiles (wave-quantization fix)
    dim3 g_out(CC / 128, (MROWS + 63) / 64, 1);     // (8, 97)
    gemm_out_kernel<<<g_out, 128, 2 * OBUF>>>(
        ah, Wh + 3 * CC * CC, bp, out, MROWS);
}

// round 17
// speedup vs baseline: 2.3482x; 1.2483x over previous
#include <cuda_runtime.h>
#include <cuda_fp16.h>
#include <math.h>
#include <stdint.h>

#define BB 8
#define TT 769
#define CC 1024
#define HH 16
#define HD 64
#define LL 32
#define COND 256
#define MROWS (BB*TT)   // 6152
// q scale with log2(e) folded in: softmax uses ex2 directly
#define QSCALE 0.18033688011112042f

// ---------------------------------------------------------------------------
// Device scratch (allocation-free requirement -> globals)  [fp16, all hi-only]
// ---------------------------------------------------------------------------
__device__ __half g_xqh[(size_t)MROWS * CC];
__device__ __half g_xkh[(size_t)MROWS * CC];
__device__ __half g_Wh[(size_t)4 * CC * CC];
__device__ __half g_qh[(size_t)MROWS * CC];
__device__ __half g_kh[(size_t)MROWS * CC];
__device__ __half g_vh[(size_t)MROWS * CC];
__device__ __half g_ah[(size_t)MROWS * CC];

// ---------------------------------------------------------------------------
// Helpers
// ---------------------------------------------------------------------------
__device__ __forceinline__ uint32_t smem_to_u32(const void* p) {
    uint32_t a;
    asm("{ .reg .u64 t; cvta.to.shared.u64 t, %1; cvt.u32.u64 %0, t; }"
        : "=r"(a) : "l"(p));
    return a;
}
__device__ __forceinline__ void ldm_x4(uint32_t* r, uint32_t addr) {
    asm volatile("ldmatrix.sync.aligned.m8n8.x4.shared.b16 {%0,%1,%2,%3}, [%4];"
        : "=r"(r[0]), "=r"(r[1]), "=r"(r[2]), "=r"(r[3]) : "r"(addr));
}
__device__ __forceinline__ void ldm_x4_t(uint32_t* r, uint32_t addr) {
    asm volatile("ldmatrix.sync.aligned.m8n8.x4.trans.shared.b16 {%0,%1,%2,%3}, [%4];"
        : "=r"(r[0]), "=r"(r[1]), "=r"(r[2]), "=r"(r[3]) : "r"(addr));
}
__device__ __forceinline__ void mma16816(float* d, const uint32_t* a,
                                         uint32_t b0, uint32_t b1) {
    asm("mma.sync.aligned.m16n8k16.row.col.f32.f16.f16.f32 "
        "{%0,%1,%2,%3}, {%4,%5,%6,%7}, {%8,%9}, {%0,%1,%2,%3};"
        : "+f"(d[0]), "+f"(d[1]), "+f"(d[2]), "+f"(d[3])
        : "r"(a[0]), "r"(a[1]), "r"(a[2]), "r"(a[3]), "r"(b0), "r"(b1));
}
__device__ __forceinline__ void cp16(uint32_t dst, const void* src, bool pred) {
    int n = pred ? 16 : 0;
    asm volatile("cp.async.cg.shared.global [%0], [%1], 16, %2;"
        :: "r"(dst), "l"(src), "r"(n) : "memory");
}
#define CP_COMMIT() asm volatile("cp.async.commit_group;" ::: "memory")
#define CP_WAIT0()  asm volatile("cp.async.wait_group 0;" ::: "memory")

__device__ __forceinline__ uint32_t pack_hi(float x, float y) {
    __half2 h = __floats2half2_rn(x, y);
    return *reinterpret_cast<uint32_t*>(&h);
}
__device__ __forceinline__ float ex2(float x) {
    float r;
    asm("ex2.approx.f32 %0, %1;" : "=f"(r) : "f"(x));
    return r;
}

// XOR-swizzled byte offset within a (rows x 128B) tile
#define SWOFF(row, seg) ((uint32_t)((row) * 128 + ((((seg) ^ ((row) & 7))) << 4)))

// ---------------------------------------------------------------------------
// One launch for all 6 one-time hi-only f32->fp16 conversions.
// ---------------------------------------------------------------------------
__global__ void split6_kernel(
    const float* __restrict__ s0, __half* __restrict__ h0, int n0,
    const float* __restrict__ s1, __half* __restrict__ h1, int n1,
    const float* __restrict__ s2, __half* __restrict__ h2, int n2,
    const float* __restrict__ s3, __half* __restrict__ h3, int n3,
    const float* __restrict__ s4, __half* __restrict__ h4, int n4,
    const float* __restrict__ s5, __half* __restrict__ h5, int n5)
{
    const float* src; __half* hi; int n;
    switch (blockIdx.y) {
        case 0: src = s0; hi = h0; n = n0; break;
        case 1: src = s1; hi = h1; n = n1; break;
        case 2: src = s2; hi = h2; n = n2; break;
        case 3: src = s3; hi = h3; n = n3; break;
        case 4: src = s4; hi = h4; n = n4; break;
        default: src = s5; hi = h5; n = n5; break;
    }
    int idx = blockIdx.x * blockDim.x + threadIdx.x;
    if (idx >= n) return;
    float4 v = reinterpret_cast<const float4*>(src)[idx];
    uint2 h;
    h.x = pack_hi(v.x, v.y);
    h.y = pack_hi(v.z, v.w);
    reinterpret_cast<uint2*>(hi)[idx] = h;
}

// ===========================================================================
// QKV GEMM (all 1-term fp16): 128x128 tile, k-chunk 64, XOR-swizzle,
// 2 bufs x 32KB = 64KB smem, 2 CTAs/SM (reg-capped). Fused epilogues:
// mode 0 q (rotary + QSCALE), 1 k (rotary), 2 v. All hi-only fp16 out.
// ===========================================================================
#define GARR2 16384
#define GBUF2 (2 * GARR2)

__global__ void __launch_bounds__(256, 2) gemm_tc_kernel(
    const __half* __restrict__ A0, const __half* __restrict__ B0,
    const float* __restrict__ b0, __half* __restrict__ O0,
    const __half* __restrict__ A1, const __half* __restrict__ B1,
    const float* __restrict__ b1, __half* __restrict__ O1,
    const __half* __restrict__ A2, const __half* __restrict__ B2,
    const float* __restrict__ b2, __half* __restrict__ O2,
    const float* __restrict__ rope, int M)
{
    extern __shared__ char sm[];
    const uint32_t smb = smem_to_u32(sm);
    const int tid = threadIdx.x;
    const int lid = tid & 31;
    const int wid = tid >> 5;
    const int wm = wid >> 2, wn = wid & 3;

    const __half *Ah, *Bh;
    const float* Bi;
    __half* Oh;
    if (blockIdx.z == 0)      { Ah=A0; Bh=B0; Bi=b0; Oh=O0; }
    else if (blockIdx.z == 1) { Ah=A1; Bh=B1; Bi=b1; Oh=O1; }
    else                      { Ah=A2; Bh=B2; Bi=b2; Oh=O2; }
    const int mode = (int)blockIdx.z;

    const int bm = blockIdx.y * 128, bn = blockIdx.x * 128;

    const uint32_t lrow = (uint32_t)(lid & 15) * 128;
    const uint32_t lhb = (uint32_t)(lid >> 4);
    const uint32_t lx7 = (uint32_t)(lid & 7);
    auto swa = [&](uint32_t base, uint32_t R, uint32_t cseg) {
        return base + R * 128 + lrow + ((((cseg | lhb)) ^ lx7) << 4);
    };

    float acc[4][4][4];
#pragma unroll
    for (int a = 0; a < 4; a++)
#pragma unroll
        for (int b = 0; b < 4; b++)
#pragma unroll
            for (int c = 0; c < 4; c++) acc[a][b][c] = 0.f;

    auto issue = [&](int ch, int buf) {
        uint32_t base = smb + buf * GBUF2;
#pragma unroll
        for (int j = 0; j < 4; j++) {
            int slot = tid + j * 256;
            int row = slot >> 3, seg = slot & 7;
            uint32_t doff = SWOFF(row, seg);
            bool ap = (bm + row) < M;
            size_t abyte = ((size_t)(bm + row) * CC + ch * 64) * 2 + seg * 16;
            size_t bbyte = ((size_t)(bn + row) * CC + ch * 64) * 2 + seg * 16;
            cp16(base + doff,         (const char*)Ah + abyte, ap);
            cp16(base + GARR2 + doff, (const char*)Bh + bbyte, true);
        }
    };

    issue(0, 0);
    CP_COMMIT();

    for (int ch = 0; ch < 16; ch++) {
        CP_WAIT0();
        __syncthreads();
        if (ch < 15) { issue(ch + 1, (ch + 1) & 1); CP_COMMIT(); }

        const uint32_t base = smb + (ch & 1) * GBUF2;
#pragma unroll
        for (int ks = 0; ks < 4; ks++) {
            uint32_t Af[4][4], Bf[2][4];
#pragma unroll
            for (int mt = 0; mt < 4; mt++)
                ldm_x4(Af[mt], swa(base, (uint32_t)(wm * 64 + mt * 16), (uint32_t)(ks * 2)));
#pragma unroll
            for (int np = 0; np < 2; np++)
                ldm_x4(Bf[np], swa(base + GARR2, (uint32_t)(wn * 32 + np * 16), (uint32_t)(ks * 2)));
#pragma unroll
            for (int mt = 0; mt < 4; mt++)
#pragma unroll
                for (int nt = 0; nt < 4; nt++) {
                    uint32_t bb0 = Bf[nt >> 1][nt & 1];
                    uint32_t bb1 = Bf[nt >> 1][2 + (nt & 1)];
                    mma16816(acc[mt][nt], Af[mt], bb0, bb1);
                }
        }
    }

    const int rbase = bm + wm * 64 + (lid >> 2);
    const int cbase = bn + wn * 32 + (lid & 3) * 2;
#pragma unroll
    for (int mt = 0; mt < 4; mt++) {
#pragma unroll
        for (int nt = 0; nt < 4; nt++) {
            int c = cbase + nt * 8;
            float2 bv = *(const float2*)(Bi + c);
#pragma unroll
            for (int half = 0; half < 2; half++) {
                int rr = rbase + mt * 16 + half * 8;
                if (rr >= M) continue;
                float v0 = acc[mt][nt][half * 2 + 0] + bv.x;
                float v1 = acc[mt][nt][half * 2 + 1] + bv.y;
                if (mode <= 1) {
                    int d = c & 63;
                    if (d < LL) {
                        int t = rr % TT;
                        float f0 = rope[t * LL + d], f1 = rope[t * LL + d + 1];
                        float c0 = cosf(f0), s0f = sinf(f0);
                        float c1 = cosf(f1), s1f = sinf(f1);
                        float a = v0, bq2 = v1;
                        v0 = a * c0 - bq2 * s0f;
                        v1 = bq2 * c1 + a * s1f;
                    }
                    if (mode == 0) { v0 *= QSCALE; v1 *= QSCALE; }
                }
                size_t off = (size_t)rr * CC + c;
                *reinterpret_cast<uint32_t*>(Oh + off) = pack_hi(v0, v1);
            }
        }
    }
}

// ===========================================================================
// Out-proj GEMM (unchanged from R16): 64x128 tile, 128 threads, k-chunk 64.
// ===========================================================================
#define OA 8192
#define OB 16384
#define OBUF (OA + OB)

__global__ void __launch_bounds__(128, 4) gemm_out_kernel(
    const __half* __restrict__ A, const __half* __restrict__ B,
    const float* __restrict__ bias, float* __restrict__ Y, int M)
{
    extern __shared__ char sm[];
    const uint32_t smb = smem_to_u32(sm);
    const int tid = threadIdx.x;
    const int lid = tid & 31;
    const int wn = tid >> 5;

    const int bm = blockIdx.y * 64, bn = blockIdx.x * 128;

    const uint32_t lrow = (uint32_t)(lid & 15) * 128;
    const uint32_t lhb = (uint32_t)(lid >> 4);
    const uint32_t lx7 = (uint32_t)(lid & 7);
    auto swa = [&](uint32_t base, uint32_t R, uint32_t cseg) {
        return base + R * 128 + lrow + ((((cseg | lhb)) ^ lx7) << 4);
    };

    float acc[4][4][4];
#pragma unroll
    for (int a = 0; a < 4; a++)
#pragma unroll
        for (int b = 0; b < 4; b++)
#pragma unroll
            for (int c = 0; c < 4; c++) acc[a][b][c] = 0.f;

    auto issue = [&](int ch, int buf) {
        uint32_t base = smb + buf * OBUF;
#pragma unroll
        for (int j = 0; j < 4; j++) {
            int slot = tid + j * 128;
            int row = slot >> 3, seg = slot & 7;
            bool ap = (bm + row) < M;
            size_t abyte = ((size_t)(bm + row) * CC + ch * 64) * 2 + seg * 16;
            cp16(base + SWOFF(row, seg), (const char*)A + abyte, ap);
        }
#pragma unroll
        for (int j = 0; j < 8; j++) {
            int slot = tid + j * 128;
            int row = slot >> 3, seg = slot & 7;
            size_t bbyte = ((size_t)(bn + row) * CC + ch * 64) * 2 + seg * 16;
            cp16(base + OA + SWOFF(row, seg), (const char*)B + bbyte, true);
        }
    };

    issue(0, 0);
    CP_COMMIT();

    for (int ch = 0; ch < 16; ch++) {
        CP_WAIT0();
        __syncthreads();
        if (ch < 15) { issue(ch + 1, (ch + 1) & 1); CP_COMMIT(); }

        const uint32_t base = smb + (ch & 1) * OBUF;
#pragma unroll
        for (int ks = 0; ks < 4; ks++) {
            uint32_t Af[4][4], Bf[2][4];
#pragma unroll
            for (int mt = 0; mt < 4; mt++)
                ldm_x4(Af[mt], swa(base, (uint32_t)(mt * 16), (uint32_t)(ks * 2)));
#pragma unroll
            for (int np = 0; np < 2; np++)
                ldm_x4(Bf[np], swa(base + OA, (uint32_t)(wn * 32 + np * 16), (uint32_t)(ks * 2)));
#pragma unroll
            for (int mt = 0; mt < 4; mt++)
#pragma unroll
                for (int nt = 0; nt < 4; nt++) {
                    uint32_t bb0 = Bf[nt >> 1][nt & 1];
                    uint32_t bb1 = Bf[nt >> 1][2 + (nt & 1)];
                    mma16816(acc[mt][nt], Af[mt], bb0, bb1);
                }
        }
    }

    const int rbase = bm + (lid >> 2);
    const int cbase = bn + wn * 32 + (lid & 3) * 2;
#pragma unroll
    for (int mt = 0; mt < 4; mt++) {
#pragma unroll
        for (int nt = 0; nt < 4; nt++) {
            int c = cbase + nt * 8;
            float2 bv = *(const float2*)(bias + c);
#pragma unroll
            for (int half = 0; half < 2; half++) {
                int rr = rbase + mt * 16 + half * 8;
                if (rr >= M) continue;
                *(float2*)(Y + (size_t)rr * CC + c) = make_float2(
                    acc[mt][nt][half * 2 + 0] + bv.x,
                    acc[mt][nt][half * 2 + 1] + bv.y);
            }
        }
    }
}

// ===========================================================================
// Tensor-core flash attention (all 1-term fp16): S=Qh·Kh, O=Ph·Vh.
// Softmax in log2 domain (scale folded into q), raw ex2.approx.
// 4 warps, XOR-swizzled 32 KB smem, 4 CTAs/SM, boundary-only mask.
// ===========================================================================
#define ABUF(b)  ((b) * 16384)
#define AKH(b)   (ABUF(b) + 0)
#define AVH(b)   (ABUF(b) + 8192)
#define AQH      (ABUF(1) + 0)      // Q staged in buf1 Kh region
#define SMEM_ATTN 32768

__global__ void __launch_bounds__(128, 4) attn_tc_kernel(
    const __half* __restrict__ qh, const __half* __restrict__ kh,
    const __half* __restrict__ vh, __half* __restrict__ oh)
{
    extern __shared__ char sm[];
    const uint32_t smb = smem_to_u32(sm);
    const int tid = threadIdx.x;
    const int l = tid & 31, w = tid >> 5;
    const int q0 = blockIdx.x * 64;
    const int h = blockIdx.y, b = blockIdx.z;
    const size_t rb = (size_t)b * TT * CC + (size_t)h * HD;

    const uint32_t lrow = (uint32_t)(l & 15) * 128;
    const uint32_t lhb = (uint32_t)(l >> 4);
    const uint32_t lx7 = (uint32_t)(l & 7);
    auto swa = [&](uint32_t base, uint32_t R, uint32_t cseg) {
        return base + R * 128 + lrow + ((((cseg | lhb)) ^ lx7) << 4);
    };

    // stage Q (hi only) in buf1, read frags, release
#pragma unroll
    for (int j = 0; j < 4; j++) {
        int slot = tid + j * 128;
        int row = slot >> 3, seg = slot & 7;
        bool p = (q0 + row) < TT;
        size_t byte = (rb + (size_t)(q0 + row) * CC) * 2 + seg * 16;
        cp16(smb + AQH + SWOFF(row, seg), (const char*)qh + byte, p);
    }
    CP_COMMIT();
    CP_WAIT0();
    __syncthreads();

    uint32_t Qf[4][4];
#pragma unroll
    for (int ks = 0; ks < 4; ks++)
        ldm_x4(Qf[ks], swa(smb + AQH, (uint32_t)(w * 16), (uint32_t)(ks * 2)));
    __syncthreads();

    auto issue_kv = [&](int t, int buf) {
        int kv0 = t * 64;
#pragma unroll
        for (int j = 0; j < 4; j++) {
            int slot = tid + j * 128;
            int row = slot >> 3, seg = slot & 7;
            bool p = (kv0 + row) < TT;
            size_t byte = (rb + (size_t)(kv0 + row) * CC) * 2 + seg * 16;
            uint32_t doff = SWOFF(row, seg);
            cp16(smb + AKH(buf) + doff, (const char*)kh + byte, p);
            cp16(smb + AVH(buf) + doff, (const char*)vh + byte, p);
        }
    };

    issue_kv(0, 0);
    CP_COMMIT();

    int kv_end = q0 + COND + 63;
    if (kv_end > TT) kv_end = TT;
    const int nkv = (kv_end + 63) >> 6;

    const int qg0 = q0 + w * 16 + (l >> 2);
    const int qg1 = qg0 + 8;
    const int warp_qmin = q0 + w * 16;

    float Oacc[8][4];
#pragma unroll
    for (int i = 0; i < 8; i++)
#pragma unroll
        for (int j = 0; j < 4; j++) Oacc[i][j] = 0.f;
    float m0 = -1e30f, m1 = -1e30f, l0 = 0.f, l1 = 0.f;

    for (int t = 0; t < nkv; t++) {
        const int buf = t & 1;
        CP_WAIT0();
        __syncthreads();
        if (t + 1 < nkv) { issue_kv(t + 1, buf ^ 1); CP_COMMIT(); }

        const int kv0 = t * 64;
        float S[8][4];
#pragma unroll
        for (int i = 0; i < 8; i++)
#pragma unroll
            for (int j = 0; j < 4; j++) S[i][j] = 0.f;

#pragma unroll
        for (int ks = 0; ks < 4; ks++) {
            uint32_t Kf[4][4];
#pragma unroll
            for (int np = 0; np < 4; np++)
                ldm_x4(Kf[np], swa(smb + AKH(buf), (uint32_t)(np * 16), (uint32_t)(ks * 2)));
#pragma unroll
            for (int nt = 0; nt < 8; nt++) {
                uint32_t bh0 = Kf[nt >> 1][nt & 1];
                uint32_t bh1 = Kf[nt >> 1][2 + (nt & 1)];
                mma16816(S[nt], Qf[ks], bh0, bh1);
            }
        }

        if ((kv0 + 63 >= COND + warp_qmin) || (kv0 + 63 >= TT)) {
#pragma unroll
            for (int nt = 0; nt < 8; nt++) {
#pragma unroll
                for (int e = 0; e < 2; e++) {
                    int kvc = kv0 + nt * 8 + (l & 3) * 2 + e;
                    bool inb = kvc < TT;
                    if (!(inb && kvc < COND + qg0)) S[nt][e] = -1e30f;
                    if (!(inb && kvc < COND + qg1)) S[nt][2 + e] = -1e30f;
                }
            }
        }

        float mx0 = -1e30f, mx1 = -1e30f;
#pragma unroll
        for (int nt = 0; nt < 8; nt++) {
            mx0 = fmaxf(mx0, fmaxf(S[nt][0], S[nt][1]));
            mx1 = fmaxf(mx1, fmaxf(S[nt][2], S[nt][3]));
        }
        mx0 = fmaxf(mx0, __shfl_xor_sync(0xffffffffu, mx0, 1));
        mx0 = fmaxf(mx0, __shfl_xor_sync(0xffffffffu, mx0, 2));
        mx1 = fmaxf(mx1, __shfl_xor_sync(0xffffffffu, mx1, 1));
        mx1 = fmaxf(mx1, __shfl_xor_sync(0xffffffffu, mx1, 2));

        float mn0 = fmaxf(m0, mx0), mn1 = fmaxf(m1, mx1);
        float al0 = ex2(m0 - mn0), al1 = ex2(m1 - mn1);
        m0 = mn0; m1 = mn1;

        float s0 = 0.f, s1 = 0.f;
#pragma unroll
        for (int nt = 0; nt < 8; nt++) {
#pragma unroll
            for (int e = 0; e < 2; e++) {
                S[nt][e] = ex2(S[nt][e] - mn0);         s0 += S[nt][e];
                S[nt][2 + e] = ex2(S[nt][2 + e] - mn1); s1 += S[nt][2 + e];
            }
        }
        s0 += __shfl_xor_sync(0xffffffffu, s0, 1);
        s0 += __shfl_xor_sync(0xffffffffu, s0, 2);
        s1 += __shfl_xor_sync(0xffffffffu, s1, 1);
        s1 += __shfl_xor_sync(0xffffffffu, s1, 2);
        l0 = l0 * al0 + s0;
        l1 = l1 * al1 + s1;

#pragma unroll
        for (int nt = 0; nt < 8; nt++) {
            Oacc[nt][0] *= al0; Oacc[nt][1] *= al0;
            Oacc[nt][2] *= al1; Oacc[nt][3] *= al1;
        }

#pragma unroll
        for (int ks = 0; ks < 4; ks++) {
            uint32_t Ph[4];
            Ph[0] = pack_hi(S[2 * ks][0],     S[2 * ks][1]);
            Ph[1] = pack_hi(S[2 * ks][2],     S[2 * ks][3]);
            Ph[2] = pack_hi(S[2 * ks + 1][0], S[2 * ks + 1][1]);
            Ph[3] = pack_hi(S[2 * ks + 1][2], S[2 * ks + 1][3]);

            uint32_t Vf[4][4];
#pragma unroll
            for (int np = 0; np < 4; np++)
                ldm_x4_t(Vf[np], swa(smb + AVH(buf), (uint32_t)(ks * 16), (uint32_t)(np * 2)));
#pragma unroll
            for (int nt = 0; nt < 8; nt++) {
                uint32_t bh0 = Vf[nt >> 1][(nt & 1) * 2];
                uint32_t bh1 = Vf[nt >> 1][(nt & 1) * 2 + 1];
                mma16816(Oacc[nt], Ph, bh0, bh1);
            }
        }
    }

    float inv0 = 1.f / l0, inv1 = 1.f / l1;
#pragma unroll
    for (int nt = 0; nt < 8; nt++) {
        int c = nt * 8 + (l & 3) * 2;
        if (qg0 < TT) {
            size_t off = rb + (size_t)qg0 * CC + c;
            *reinterpret_cast<uint32_t*>(oh + off) =
                pack_hi(Oacc[nt][0] * inv0, Oacc[nt][1] * inv0);
        }
        if (qg1 < TT) {
            size_t off = rb + (size_t)qg1 * CC + c;
            *reinterpret_cast<uint32_t*>(oh + off) =
                pack_hi(Oacc[nt][2] * inv1, Oacc[nt][3] * inv1);
        }
    }
}

// ---------------------------------------------------------------------------
// Launch
// ---------------------------------------------------------------------------
extern "C" void kernel_launch(void* const* d_in, const int* in_sizes, int n_in,
                              void* d_out, int out_size)
{
    const float* x_q  = (const float*)d_in[0];
    const float* x_kv = (const float*)d_in[1];
    const float* rope = (const float*)d_in[2];
    const float* Wq   = (const float*)d_in[3];
    const float* bq   = (const float*)d_in[4];
    const float* Wk   = (const float*)d_in[5];
    const float* bk   = (const float*)d_in[6];
    const float* Wv   = (const float*)d_in[7];
    const float* bv   = (const float*)d_in[8];
    const float* Wp   = (const float*)d_in[9];
    const float* bp   = (const float*)d_in[10];
    float* out = (float*)d_out;

    __half *xqh, *xkh, *Wh, *qh, *kh, *vh, *ah;
    cudaGetSymbolAddress((void**)&xqh, g_xqh);
    cudaGetSymbolAddress((void**)&xkh, g_xkh);
    cudaGetSymbolAddress((void**)&Wh,  g_Wh);
    cudaGetSymbolAddress((void**)&qh,  g_qh);
    cudaGetSymbolAddress((void**)&kh,  g_kh);
    cudaGetSymbolAddress((void**)&vh,  g_vh);
    cudaGetSymbolAddress((void**)&ah,  g_ah);

    cudaFuncSetAttribute(gemm_tc_kernel,
        cudaFuncAttributeMaxDynamicSharedMemorySize, 2 * GBUF2);   // 65536
    cudaFuncSetAttribute(gemm_out_kernel,
        cudaFuncAttributeMaxDynamicSharedMemorySize, 2 * OBUF);    // 49152
    cudaFuncSetAttribute(attn_tc_kernel,
        cudaFuncAttributeMaxDynamicSharedMemorySize, SMEM_ATTN);

    // 1) one-time hi-only conversions
    const int NX4 = MROWS * CC / 4;
    const int NW4 = CC * CC / 4;
    dim3 split_grid((NX4 + 255) / 256, 6);
    split6_kernel<<<split_grid, 256>>>(
        x_q,  xqh, NX4,
        x_kv, xkh, NX4,
        Wq, Wh,              NW4,
        Wk, Wh + CC * CC,     NW4,
        Wv, Wh + 2 * CC * CC, NW4,
        Wp, Wh + 3 * CC * CC, NW4);

    // 2) fused Q/K/V projections (all 1-term)
    dim3 g_qkv(CC / 128, (MROWS + 127) / 128, 3);   // (8, 49, 3)
    gemm_tc_kernel<<<g_qkv, 256, 2 * GBUF2>>>(
        xqh, Wh,              bq, qh,
        xkh, Wh + CC * CC,     bk, kh,
        xkh, Wh + 2 * CC * CC, bv, vh,
        rope, MROWS);

    // 3) tensor-core attention (1-term QK + 1-term PV)
    dim3 attn_grid((TT + 63) / 64, HH, BB);         // (13, 16, 8)
    attn_tc_kernel<<<attn_grid, 128, SMEM_ATTN>>>(qh, kh, vh, ah);

    // 4) output projection: 64x128 tiles
    dim3 g_out(CC / 128, (MROWS + 63) / 64, 1);     // (8, 97)
    gemm_out_kernel<<<g_out, 128, 2 * OBUF>>>(
        ah, Wh + 3 * CC * CC, bp, out, MROWS);
}